// round 6
// baseline (speedup 1.0000x reference)
#include <cuda_runtime.h>
#include <cstdint>

#define BSZ 8
#define NP  4096
#define MP  1024
#define CCH 512
#define CE  64
#define CD  256
#define NCAT 384

// ---------------- scratch ----------------
__device__ float wcat_buf[NCAT * CCH];
__device__ float wot_buf [CCH * CD];
__device__ float gfh_buf [(size_t)BSZ * NP * NCAT];
__device__ float f_buf   [BSZ * MP * CE];            // [b][key][e]
__device__ float h_buf   [BSZ * MP * CD];            // [b][key][d]
__device__ float o_buf   [(size_t)BSZ * NP * CD];

__device__ __forceinline__ uint32_t f2tf32(float f) {
    uint32_t r;
    asm("cvt.rna.tf32.f32 %0, %1;" : "=r"(r) : "f"(f));
    return r;
}
__device__ __forceinline__ void mma_tf32(float c[4], const uint32_t a[4], const uint32_t b[2]) {
    asm volatile(
        "mma.sync.aligned.m16n8k8.row.col.f32.tf32.tf32.f32 "
        "{%0,%1,%2,%3}, {%4,%5,%6,%7}, {%8,%9}, {%0,%1,%2,%3};"
        : "+f"(c[0]), "+f"(c[1]), "+f"(c[2]), "+f"(c[3])
        : "r"(a[0]), "r"(a[1]), "r"(a[2]), "r"(a[3]), "r"(b[0]), "r"(b[1]));
}

// ---------------------------------------------------------------------------
// Warp-tiled tf32 mma GEMM (unchanged from R4): C = A[M,K] * B[N,K]^T
// ---------------------------------------------------------------------------
template <int EPI>
__global__ void __launch_bounds__(256) mma_gemm(
    const float* __restrict__ A, const float* __restrict__ B, float* __restrict__ C,
    int K, int lda, int ldb, int ldc,
    long long strA, long long strB, long long strC,
    const float* __restrict__ gamma, const float* __restrict__ resid)
{
    __shared__ uint32_t As[32][133];
    __shared__ uint32_t Bs[32][133];

    const int tid  = threadIdx.x;
    const int wid  = tid >> 5;
    const int lane = tid & 31;
    const int bz   = blockIdx.z;
    A += (size_t)bz * strA;
    B += (size_t)bz * strB;
    C += (size_t)bz * strC;
    const int rowBase = blockIdx.y * 128;
    const int colBase = blockIdx.x * 128;

    const int wm = (wid >> 1) * 32;
    const int wn = (wid & 1) * 64;
    const int grp  = lane >> 2;
    const int quad = lane & 3;

    float acc[2][8][4] = {};

    for (int k0 = 0; k0 < K; k0 += 32) {
        #pragma unroll
        for (int i = 0; i < 4; i++) {
            int idx = tid + 256 * i;
            int r = idx >> 3, c4 = (idx & 7) * 4;
            float4 v = *(const float4*)(A + (size_t)(rowBase + r) * lda + k0 + c4);
            As[c4 + 0][r] = f2tf32(v.x);
            As[c4 + 1][r] = f2tf32(v.y);
            As[c4 + 2][r] = f2tf32(v.z);
            As[c4 + 3][r] = f2tf32(v.w);
        }
        #pragma unroll
        for (int i = 0; i < 4; i++) {
            int idx = tid + 256 * i;
            int r = idx >> 3, c4 = (idx & 7) * 4;
            float4 v = *(const float4*)(B + (size_t)(colBase + r) * ldb + k0 + c4);
            Bs[c4 + 0][r] = f2tf32(v.x);
            Bs[c4 + 1][r] = f2tf32(v.y);
            Bs[c4 + 2][r] = f2tf32(v.z);
            Bs[c4 + 3][r] = f2tf32(v.w);
        }
        __syncthreads();

        #pragma unroll
        for (int s = 0; s < 4; s++) {
            const int kk = s * 8;
            uint32_t af[2][4];
            uint32_t bf[8][2];
            #pragma unroll
            for (int mi = 0; mi < 2; mi++) {
                af[mi][0] = As[kk + quad    ][wm + mi * 16 + grp];
                af[mi][1] = As[kk + quad    ][wm + mi * 16 + 8 + grp];
                af[mi][2] = As[kk + 4 + quad][wm + mi * 16 + grp];
                af[mi][3] = As[kk + 4 + quad][wm + mi * 16 + 8 + grp];
            }
            #pragma unroll
            for (int ni = 0; ni < 8; ni++) {
                bf[ni][0] = Bs[kk + quad    ][wn + ni * 8 + grp];
                bf[ni][1] = Bs[kk + 4 + quad][wn + ni * 8 + grp];
            }
            #pragma unroll
            for (int mi = 0; mi < 2; mi++)
                #pragma unroll
                for (int ni = 0; ni < 8; ni++)
                    mma_tf32(acc[mi][ni], af[mi], bf[ni]);
        }
        __syncthreads();
    }

    const float gval = EPI ? gamma[0] : 0.0f;
    #pragma unroll
    for (int mi = 0; mi < 2; mi++) {
        #pragma unroll
        for (int half = 0; half < 2; half++) {
            const int row = rowBase + wm + mi * 16 + half * 8 + grp;
            float* cp = C + (size_t)row * ldc + colBase + wn + quad * 2;
            #pragma unroll
            for (int ni = 0; ni < 8; ni++) {
                float v0 = acc[mi][ni][half * 2 + 0];
                float v1 = acc[mi][ni][half * 2 + 1];
                if (EPI) {
                    const float* rp = resid + (size_t)row * ldc + colBase + wn + quad * 2 + ni * 8;
                    float2 rv = *(const float2*)rp;
                    v0 = fmaf(gval, v0, rv.x);
                    v1 = fmaf(gval, v1, rv.y);
                }
                *(float2*)(cp + ni * 8) = make_float2(v0, v1);
            }
        }
    }
}

// ---------------------------------------------------------------------------
// Flash attention: S = G@F^T, online softmax, O = P@H. One CTA = 128 queries.
// 512 threads. Dynamic smem ~152 KB.
// ---------------------------------------------------------------------------
#define GS_LD 133
#define FS_LD 69
#define HS_LD 260
#define GS_OFF 0
#define FS_OFF (64 * GS_LD)
#define PS_OFF (FS_OFF + 64 * FS_LD)
#define HS_OFF (PS_OFF + 64 * GS_LD)
#define ST_OFF (HS_OFF + 64 * HS_LD)
#define FLASH_SMEM_U32 (ST_OFF + 896)
#define FLASH_SMEM_B   (FLASH_SMEM_U32 * 4)

__global__ void __launch_bounds__(512) flash_attn(
    const float* __restrict__ gfh, const float* __restrict__ f,
    const float* __restrict__ h, float* __restrict__ o)
{
    extern __shared__ __align__(16) uint32_t sm[];
    uint32_t* Gs = sm + GS_OFF;          // [e=64][m=128+pad]
    uint32_t* Fs = sm + FS_OFF;          // [e=64][key=64+pad]
    uint32_t* Ps = sm + PS_OFF;          // [key=64][m=128+pad]
    uint32_t* Hs = sm + HS_OFF;          // [key=64][d=256+pad]
    float* pmax = (float*)(sm + ST_OFF); // [2][128]
    float* psum = pmax + 256;            // [2][128]
    float* mrow = psum + 256;            // [128]
    float* arow = mrow + 128;            // [128]
    float* lrow = arow + 128;            // [128]

    const int tid  = threadIdx.x;
    const int wid  = tid >> 5;
    const int lane = tid & 31;
    const int grp  = lane >> 2;
    const int quad = lane & 3;
    const int b    = blockIdx.y;
    const int mblk = blockIdx.x * 128;

    const float* gq = gfh + ((size_t)b * NP + mblk) * NCAT;   // G cols [0,64)
    const float* fb = f + (size_t)b * MP * CE;
    const float* hb = h + (size_t)b * MP * CD;

    // Load G tile (128 x 64) -> Gs[e][m], tf32
    {
        int row = tid >> 2, eb = (tid & 3) * 16;
        const float* src = gq + (size_t)row * NCAT + eb;
        #pragma unroll
        for (int j = 0; j < 16; j += 4) {
            float4 v = *(const float4*)(src + j);
            Gs[(eb + j + 0) * GS_LD + row] = f2tf32(v.x);
            Gs[(eb + j + 1) * GS_LD + row] = f2tf32(v.y);
            Gs[(eb + j + 2) * GS_LD + row] = f2tf32(v.z);
            Gs[(eb + j + 3) * GS_LD + row] = f2tf32(v.w);
        }
    }
    if (tid < 128) { mrow[tid] = -1e30f; lrow[tid] = 0.0f; }

    // warp coords: S phase 8m x 2n, PV phase 4m x 4n
    const int swr = (wid >> 1) * 16;
    const int swc = (wid & 1) * 32;
    const int pwr = (wid >> 2) * 32;
    const int pwc = (wid & 3) * 64;

    float accO[2][8][4] = {};

    for (int kc = 0; kc < 16; kc++) {
        // Load F chunk (64 keys x 64 e) -> Fs[e][key]
        {
            int key = tid >> 3, eb = (tid & 7) * 8;
            const float* src = fb + (size_t)(kc * 64 + key) * CE + eb;
            float4 v0 = *(const float4*)src;
            float4 v1 = *(const float4*)(src + 4);
            Fs[(eb + 0) * FS_LD + key] = f2tf32(v0.x);
            Fs[(eb + 1) * FS_LD + key] = f2tf32(v0.y);
            Fs[(eb + 2) * FS_LD + key] = f2tf32(v0.z);
            Fs[(eb + 3) * FS_LD + key] = f2tf32(v0.w);
            Fs[(eb + 4) * FS_LD + key] = f2tf32(v1.x);
            Fs[(eb + 5) * FS_LD + key] = f2tf32(v1.y);
            Fs[(eb + 6) * FS_LD + key] = f2tf32(v1.z);
            Fs[(eb + 7) * FS_LD + key] = f2tf32(v1.w);
        }
        // Load H chunk (64 keys x 256 d) -> Hs[key][d]
        {
            int key = tid >> 3, db = (tid & 7) * 32;
            const float* src = hb + (size_t)(kc * 64 + key) * CD + db;
            #pragma unroll
            for (int j = 0; j < 32; j += 4) {
                float4 v = *(const float4*)(src + j);
                uint4 u;
                u.x = f2tf32(v.x); u.y = f2tf32(v.y);
                u.z = f2tf32(v.z); u.w = f2tf32(v.w);
                *(uint4*)&Hs[key * HS_LD + db + j] = u;
            }
        }
        __syncthreads();                               // S1

        // ---- S = G @ F^T (warp tile 16m x 32n) ----
        float accS[4][4] = {};
        #pragma unroll
        for (int kk = 0; kk < 64; kk += 8) {
            uint32_t af[4];
            af[0] = Gs[(kk + quad    ) * GS_LD + swr + grp];
            af[1] = Gs[(kk + quad    ) * GS_LD + swr + 8 + grp];
            af[2] = Gs[(kk + 4 + quad) * GS_LD + swr + grp];
            af[3] = Gs[(kk + 4 + quad) * GS_LD + swr + 8 + grp];
            #pragma unroll
            for (int ni = 0; ni < 4; ni++) {
                uint32_t bf[2];
                bf[0] = Fs[(kk + quad    ) * FS_LD + swc + ni * 8 + grp];
                bf[1] = Fs[(kk + 4 + quad) * FS_LD + swc + ni * 8 + grp];
                mma_tf32(accS[ni], af, bf);
            }
        }

        // ---- row max (over this chunk) ----
        float mA = -1e30f, mB = -1e30f;
        #pragma unroll
        for (int ni = 0; ni < 4; ni++) {
            mA = fmaxf(mA, fmaxf(accS[ni][0], accS[ni][1]));
            mB = fmaxf(mB, fmaxf(accS[ni][2], accS[ni][3]));
        }
        mA = fmaxf(mA, __shfl_xor_sync(0xffffffffu, mA, 1));
        mA = fmaxf(mA, __shfl_xor_sync(0xffffffffu, mA, 2));
        mB = fmaxf(mB, __shfl_xor_sync(0xffffffffu, mB, 1));
        mB = fmaxf(mB, __shfl_xor_sync(0xffffffffu, mB, 2));
        if (quad == 0) {
            pmax[(wid & 1) * 128 + swr + grp]     = mA;
            pmax[(wid & 1) * 128 + swr + 8 + grp] = mB;
        }
        __syncthreads();                               // S2
        if (tid < 128) {
            float cm = fmaxf(pmax[tid], pmax[128 + tid]);
            float mo = mrow[tid];
            float mn = fmaxf(mo, cm);
            mrow[tid] = mn;
            arow[tid] = __expf(mo - mn);
        }
        __syncthreads();                               // S3

        // ---- exp, P -> smem, partial sums ----
        {
            float mnA = mrow[swr + grp];
            float mnB = mrow[swr + 8 + grp];
            float sA = 0.0f, sB = 0.0f;
            #pragma unroll
            for (int ni = 0; ni < 4; ni++) {
                float p0 = __expf(accS[ni][0] - mnA);
                float p1 = __expf(accS[ni][1] - mnA);
                float p2 = __expf(accS[ni][2] - mnB);
                float p3 = __expf(accS[ni][3] - mnB);
                sA += p0 + p1;
                sB += p2 + p3;
                int col = swc + ni * 8 + quad * 2;
                Ps[(col    ) * GS_LD + swr + grp]     = f2tf32(p0);
                Ps[(col + 1) * GS_LD + swr + grp]     = f2tf32(p1);
                Ps[(col    ) * GS_LD + swr + 8 + grp] = f2tf32(p2);
                Ps[(col + 1) * GS_LD + swr + 8 + grp] = f2tf32(p3);
            }
            sA += __shfl_xor_sync(0xffffffffu, sA, 1);
            sA += __shfl_xor_sync(0xffffffffu, sA, 2);
            sB += __shfl_xor_sync(0xffffffffu, sB, 1);
            sB += __shfl_xor_sync(0xffffffffu, sB, 2);
            if (quad == 0) {
                psum[(wid & 1) * 128 + swr + grp]     = sA;
                psum[(wid & 1) * 128 + swr + 8 + grp] = sB;
            }
        }
        __syncthreads();                               // S4
        if (tid < 128)
            lrow[tid] = lrow[tid] * arow[tid] + psum[tid] + psum[128 + tid];

        // ---- rescale O by alpha ----
        {
            float a0 = arow[pwr + grp];
            float a1 = arow[pwr + 8 + grp];
            float a2 = arow[pwr + 16 + grp];
            float a3 = arow[pwr + 24 + grp];
            #pragma unroll
            for (int nt = 0; nt < 8; nt++) {
                accO[0][nt][0] *= a0; accO[0][nt][1] *= a0;
                accO[0][nt][2] *= a1; accO[0][nt][3] *= a1;
                accO[1][nt][0] *= a2; accO[1][nt][1] *= a2;
                accO[1][nt][2] *= a3; accO[1][nt][3] *= a3;
            }
        }

        // ---- O += P @ H (warp tile 32m x 64d) ----
        #pragma unroll
        for (int kk = 0; kk < 64; kk += 8) {
            uint32_t af[2][4];
            #pragma unroll
            for (int mt = 0; mt < 2; mt++) {
                af[mt][0] = Ps[(kk + quad    ) * GS_LD + pwr + mt * 16 + grp];
                af[mt][1] = Ps[(kk + quad    ) * GS_LD + pwr + mt * 16 + 8 + grp];
                af[mt][2] = Ps[(kk + 4 + quad) * GS_LD + pwr + mt * 16 + grp];
                af[mt][3] = Ps[(kk + 4 + quad) * GS_LD + pwr + mt * 16 + 8 + grp];
            }
            #pragma unroll
            for (int nt = 0; nt < 8; nt++) {
                uint32_t bf[2];
                bf[0] = Hs[(kk + quad    ) * HS_LD + pwc + nt * 8 + grp];
                bf[1] = Hs[(kk + 4 + quad) * HS_LD + pwc + nt * 8 + grp];
                mma_tf32(accO[0][nt], af[0], bf);
                mma_tf32(accO[1][nt], af[1], bf);
            }
        }
        __syncthreads();                               // S5
    }

    // ---- epilogue: O /= l, write ----
    float* ob = o + ((size_t)b * NP + mblk) * CD;
    #pragma unroll
    for (int mt = 0; mt < 2; mt++) {
        int r0 = pwr + mt * 16 + grp;
        int r1 = r0 + 8;
        float i0 = 1.0f / lrow[r0];
        float i1 = 1.0f / lrow[r1];
        #pragma unroll
        for (int nt = 0; nt < 8; nt++) {
            int col = pwc + nt * 8 + quad * 2;
            *(float2*)&ob[(size_t)r0 * CD + col] =
                make_float2(accO[mt][nt][0] * i0, accO[mt][nt][1] * i0);
            *(float2*)&ob[(size_t)r1 * CD + col] =
                make_float2(accO[mt][nt][2] * i1, accO[mt][nt][3] * i1);
        }
    }
}

// ---------------------------------------------------------------------------
// weight prep
// ---------------------------------------------------------------------------
__global__ void prep_weights(const float* __restrict__ Wf, const float* __restrict__ Wg,
                             const float* __restrict__ Wh, const float* __restrict__ Wo,
                             float* __restrict__ wcat, float* __restrict__ wot)
{
    int idx = blockIdx.x * 256 + threadIdx.x;
    if (idx < NCAT * CCH) {
        int n = idx / CCH, k = idx % CCH;
        float v;
        if (n < 64)       v = Wg[(size_t)k * 64 + n];
        else if (n < 128) v = Wf[(size_t)k * 64 + (n - 64)];
        else              v = Wh[(size_t)k * 256 + (n - 128)];
        wcat[idx] = v;
    }
    if (idx < CCH * CD) {
        int n = idx / CD, k = idx % CD;
        wot[idx] = Wo[(size_t)k * CCH + n];
    }
}

// ---------------------------------------------------------------------------
// pools (both coalesced now): f[b][m][e], h[b][m][d]
// ---------------------------------------------------------------------------
__global__ void pool_f(const float* __restrict__ gfh, float* __restrict__ f)
{
    int idx = blockIdx.x * 256 + threadIdx.x;
    if (idx >= BSZ * MP * CE) return;
    int e = idx & 63;
    int m = (idx >> 6) & 1023;
    int b = idx >> 16;
    int p = m >> 5, q = m & 31;
    const float* base = gfh + ((size_t)b * NP + 2 * p * 64 + 2 * q) * NCAT + 64 + e;
    f[idx] = fmaxf(fmaxf(base[0], base[NCAT]),
                   fmaxf(base[64 * NCAT], base[64 * NCAT + NCAT]));
}

__global__ void pool_h(const float* __restrict__ gfh, float* __restrict__ h)
{
    int idx = blockIdx.x * 256 + threadIdx.x;
    if (idx >= BSZ * MP * CD) return;
    int c = idx & 255;
    int m = (idx >> 8) & 1023;
    int b = idx >> 18;
    int p = m >> 5, q = m & 31;
    const float* base = gfh + ((size_t)b * NP + 2 * p * 64 + 2 * q) * NCAT + 128 + c;
    h[idx] = fmaxf(fmaxf(base[0], base[NCAT]),
                   fmaxf(base[64 * NCAT], base[64 * NCAT + NCAT]));
}

// ---------------------------------------------------------------------------
// launch
// ---------------------------------------------------------------------------
extern "C" void kernel_launch(void* const* d_in, const int* in_sizes, int n_in,
                              void* d_out, int out_size)
{
    const float* x     = (const float*)d_in[0];
    const float* Wf    = (const float*)d_in[1];
    const float* Wg    = (const float*)d_in[2];
    const float* Wh    = (const float*)d_in[3];
    const float* Wo    = (const float*)d_in[4];
    const float* gamma = (const float*)d_in[5];
    float* out = (float*)d_out;

    float *wcat_p, *wot_p, *gfh_p, *f_p, *h_p, *o_p;
    cudaGetSymbolAddress((void**)&wcat_p, wcat_buf);
    cudaGetSymbolAddress((void**)&wot_p,  wot_buf);
    cudaGetSymbolAddress((void**)&gfh_p,  gfh_buf);
    cudaGetSymbolAddress((void**)&f_p,    f_buf);
    cudaGetSymbolAddress((void**)&h_p,    h_buf);
    cudaGetSymbolAddress((void**)&o_p,    o_buf);

    cudaFuncSetAttribute(flash_attn, cudaFuncAttributeMaxDynamicSharedMemorySize,
                         FLASH_SMEM_B);

    prep_weights<<<(NCAT * CCH + 255) / 256, 256>>>(Wf, Wg, Wh, Wo, wcat_p, wot_p);

    // fused projections: gfh[32768,384] = X @ wcat^T
    mma_gemm<0><<<dim3(3, 256, 1), 256>>>(
        x, wcat_p, gfh_p, CCH, CCH, CCH, NCAT, 0, 0, 0, nullptr, nullptr);

    pool_f<<<(BSZ * MP * CE + 255) / 256, 256>>>(gfh_p, f_p);
    pool_h<<<(BSZ * MP * CD + 255) / 256, 256>>>(gfh_p, h_p);

    // fused S + softmax + PV
    flash_attn<<<dim3(32, 8), 512, FLASH_SMEM_B>>>(gfh_p, f_p, h_p, o_p);

    // out = gamma * (O @ Wo) + x
    mma_gemm<1><<<dim3(4, 256, 1), 256>>>(
        o_p, wot_p, out, CD, CD, CD, CCH, 0, 0, 0, gamma, x);
}

// round 7
// speedup vs baseline: 1.7106x; 1.7106x over previous
#include <cuda_runtime.h>
#include <cstdint>

#define BSZ 8
#define NP  4096
#define MP  1024
#define CCH 512
#define CE  64
#define CD  256
#define NCAT 384

// ---------------- scratch ----------------
__device__ float wcat_buf[NCAT * CCH];              // [384,512] = [Wg|Wf|Wh]^T
__device__ float wot_buf [CCH * CD];                // [512,256] = Wo^T
__device__ float gfh_buf [(size_t)BSZ * NP * NCAT]; // [B*4096, 384]
__device__ float f_buf   [BSZ * MP * CE];           // [b][key][e]
__device__ float h_buf   [BSZ * MP * CD];           // [b][key][d]
__device__ float s_buf   [(size_t)BSZ * NP * MP];   // [b][4096][1024]
__device__ float o_buf   [(size_t)BSZ * NP * CD];   // [b][4096][256]

// ---------------- helpers ----------------
__device__ __forceinline__ uint32_t smem_u32(const void* p) {
    uint32_t a;
    asm("{ .reg .u64 t; cvta.to.shared.u64 t, %1; cvt.u32.u64 %0, t; }" : "=r"(a) : "l"(p));
    return a;
}
__device__ __forceinline__ void cp_async16(uint32_t dst, const void* src) {
    asm volatile("cp.async.cg.shared.global [%0], [%1], 16;" :: "r"(dst), "l"(src));
}
__device__ __forceinline__ void cp_commit() {
    asm volatile("cp.async.commit_group;" ::: "memory");
}
template <int N>
__device__ __forceinline__ void cp_wait() {
    asm volatile("cp.async.wait_group %0;" :: "n"(N) : "memory");
}
// tf32 mma; operands are raw fp32 bits (HW truncates mantissa to tf32)
__device__ __forceinline__ void mma_tf32(float c[4], const uint32_t a[4], const uint32_t b[2]) {
    asm volatile(
        "mma.sync.aligned.m16n8k8.row.col.f32.tf32.tf32.f32 "
        "{%0,%1,%2,%3}, {%4,%5,%6,%7}, {%8,%9}, {%0,%1,%2,%3};"
        : "+f"(c[0]), "+f"(c[1]), "+f"(c[2]), "+f"(c[3])
        : "r"(a[0]), "r"(a[1]), "r"(a[2]), "r"(a[3]), "r"(b[0]), "r"(b[1]));
}

// ---------------------------------------------------------------------------
// Pipelined warp-tiled tf32 GEMM.
//   BNN=0: C[M,N] = A[M,K] * B[N,K]^T  (both K-major)
//   BNN=1: C[M,N] = A[M,K] * B[K,N]    (B row-major [k][n])
// CTA tile 128x128, K-chunk 32, 2-stage cp.async double buffer.
// A (and NT B) tiles: [row][k] 32-wide with float4 XOR swizzle (conflict-free).
// NN B tile: [k][n] rows padded to 136 floats (conflict-free: bank = 8*quad+grp).
// EPI=1: C = gamma[0]*acc + resid. Requires M%128==0, N%128==0, K%32==0, KB>=2.
// ---------------------------------------------------------------------------
template <int BNN, int EPI>
__global__ void __launch_bounds__(256) mma_gemm(
    const float* __restrict__ A, const float* __restrict__ B, float* __restrict__ C,
    int K, int lda, int ldb, int ldc,
    long long strA, long long strB, long long strC,
    const float* __restrict__ gamma, const float* __restrict__ resid)
{
    constexpr int ATILE  = 128 * 32;                  // floats
    constexpr int BTILE  = BNN ? 32 * 136 : 128 * 32; // floats
    constexpr int BUFSTR = ATILE + BTILE;             // floats per stage

    extern __shared__ float smemf[];
    const uint32_t sbase = smem_u32(smemf);

    const int tid  = threadIdx.x;
    const int wid  = tid >> 5;
    const int lane = tid & 31;
    const int grp  = lane >> 2;
    const int quad = lane & 3;
    const int bz   = blockIdx.z;
    A += (size_t)bz * strA;
    B += (size_t)bz * strB;
    C += (size_t)bz * strC;
    const int rowBase = blockIdx.y * 128;
    const int colBase = blockIdx.x * 128;
    const int wm = (wid >> 1) * 32;
    const int wn = (wid & 1) * 64;

    const int KB = K >> 5;

    auto prefetch = [&](int kb, int buf) {
        const uint32_t abase = sbase + buf * (BUFSTR * 4);
        const uint32_t bbase = abase + ATILE * 4;
        const float* Ag = A + (size_t)rowBase * lda + kb * 32;
        #pragma unroll
        for (int i = 0; i < 4; i++) {
            int idx = tid + 256 * i;
            int r = idx >> 3, c4 = idx & 7;
            uint32_t dst = abase + (uint32_t)(r * 32 + ((c4 ^ (r & 7)) << 2)) * 4u;
            cp_async16(dst, Ag + (size_t)r * lda + c4 * 4);
        }
        if (BNN) {
            const float* Bg = B + (size_t)(kb * 32) * ldb + colBase;
            #pragma unroll
            for (int i = 0; i < 4; i++) {
                int idx = tid + 256 * i;
                int r = idx >> 5, c4 = idx & 31;
                uint32_t dst = bbase + (uint32_t)(r * 136 + c4 * 4) * 4u;
                cp_async16(dst, Bg + (size_t)r * ldb + c4 * 4);
            }
        } else {
            const float* Bg = B + (size_t)colBase * ldb + kb * 32;
            #pragma unroll
            for (int i = 0; i < 4; i++) {
                int idx = tid + 256 * i;
                int r = idx >> 3, c4 = idx & 7;
                uint32_t dst = bbase + (uint32_t)(r * 32 + ((c4 ^ (r & 7)) << 2)) * 4u;
                cp_async16(dst, Bg + (size_t)r * ldb + c4 * 4);
            }
        }
        cp_commit();
    };

    float acc[2][8][4] = {};

    prefetch(0, 0);
    for (int kb = 0; kb < KB; kb++) {
        const int buf = kb & 1;
        if (kb + 1 < KB) {
            prefetch(kb + 1, buf ^ 1);
            cp_wait<1>();
        } else {
            cp_wait<0>();
        }
        __syncthreads();

        const uint32_t* Asb = (const uint32_t*)(smemf + buf * BUFSTR);
        const uint32_t* Bsb = Asb + ATILE;

        #pragma unroll
        for (int s = 0; s < 4; s++) {
            const int kk = s * 8;
            const int g0 = kk >> 2, g1 = g0 + 1;
            uint32_t af[2][4];
            #pragma unroll
            for (int mi = 0; mi < 2; mi++) {
                int m0 = wm + mi * 16 + grp, m1 = m0 + 8;
                af[mi][0] = Asb[m0 * 32 + ((g0 ^ (m0 & 7)) << 2) + quad];
                af[mi][1] = Asb[m1 * 32 + ((g0 ^ (m1 & 7)) << 2) + quad];
                af[mi][2] = Asb[m0 * 32 + ((g1 ^ (m0 & 7)) << 2) + quad];
                af[mi][3] = Asb[m1 * 32 + ((g1 ^ (m1 & 7)) << 2) + quad];
            }
            #pragma unroll
            for (int ni = 0; ni < 8; ni++) {
                uint32_t bf[2];
                const int n = wn + ni * 8 + grp;
                if (BNN) {
                    bf[0] = Bsb[(kk + quad) * 136 + n];
                    bf[1] = Bsb[(kk + 4 + quad) * 136 + n];
                } else {
                    bf[0] = Bsb[n * 32 + ((g0 ^ (n & 7)) << 2) + quad];
                    bf[1] = Bsb[n * 32 + ((g1 ^ (n & 7)) << 2) + quad];
                }
                mma_tf32(acc[0][ni], af[0], bf);
                mma_tf32(acc[1][ni], af[1], bf);
            }
        }
        __syncthreads();
    }

    // epilogue
    const float gval = EPI ? gamma[0] : 0.0f;
    #pragma unroll
    for (int mi = 0; mi < 2; mi++) {
        #pragma unroll
        for (int half = 0; half < 2; half++) {
            const int row = rowBase + wm + mi * 16 + half * 8 + grp;
            float* cp = C + (size_t)row * ldc + colBase + wn + quad * 2;
            #pragma unroll
            for (int ni = 0; ni < 8; ni++) {
                float v0 = acc[mi][ni][half * 2 + 0];
                float v1 = acc[mi][ni][half * 2 + 1];
                if (EPI) {
                    const float* rp = resid + (size_t)row * ldc + colBase + wn + quad * 2 + ni * 8;
                    float2 rv = *(const float2*)rp;
                    v0 = fmaf(gval, v0, rv.x);
                    v1 = fmaf(gval, v1, rv.y);
                }
                *(float2*)(cp + ni * 8) = make_float2(v0, v1);
            }
        }
    }
}

// ---------------------------------------------------------------------------
// weight prep: wcat[n][k] = [Wg|Wf|Wh](k,n'),  wot[n][k] = Wo[k][n]
// ---------------------------------------------------------------------------
__global__ void prep_weights(const float* __restrict__ Wf, const float* __restrict__ Wg,
                             const float* __restrict__ Wh, const float* __restrict__ Wo,
                             float* __restrict__ wcat, float* __restrict__ wot)
{
    int idx = blockIdx.x * 256 + threadIdx.x;
    if (idx < NCAT * CCH) {
        int n = idx / CCH, k = idx % CCH;
        float v;
        if (n < 64)       v = Wg[(size_t)k * 64 + n];
        else if (n < 128) v = Wf[(size_t)k * 64 + (n - 64)];
        else              v = Wh[(size_t)k * 256 + (n - 128)];
        wcat[idx] = v;
    }
    if (idx < CCH * CD) {
        int n = idx / CD, k = idx % CD;
        wot[idx] = Wo[(size_t)k * CCH + n];
    }
}

// ---------------------------------------------------------------------------
// pools (coalesced): f[b][m][e], h[b][m][d]
// ---------------------------------------------------------------------------
__global__ void pool_f(const float* __restrict__ gfh, float* __restrict__ f)
{
    int idx = blockIdx.x * 256 + threadIdx.x;
    if (idx >= BSZ * MP * CE) return;
    int e = idx & 63;
    int m = (idx >> 6) & 1023;
    int b = idx >> 16;
    int p = m >> 5, q = m & 31;
    const float* base = gfh + ((size_t)b * NP + 2 * p * 64 + 2 * q) * NCAT + 64 + e;
    f[idx] = fmaxf(fmaxf(base[0], base[NCAT]),
                   fmaxf(base[64 * NCAT], base[64 * NCAT + NCAT]));
}

__global__ void pool_h(const float* __restrict__ gfh, float* __restrict__ h)
{
    int idx = blockIdx.x * 256 + threadIdx.x;
    if (idx >= BSZ * MP * CD) return;
    int c = idx & 255;
    int m = (idx >> 8) & 1023;
    int b = idx >> 18;
    int p = m >> 5, q = m & 31;
    const float* base = gfh + ((size_t)b * NP + 2 * p * 64 + 2 * q) * NCAT + 128 + c;
    h[idx] = fmaxf(fmaxf(base[0], base[NCAT]),
                   fmaxf(base[64 * NCAT], base[64 * NCAT + NCAT]));
}

// ---------------------------------------------------------------------------
// row softmax over 1024 cols, in-place; one 256-thread block per row
// ---------------------------------------------------------------------------
__global__ void softmax_kernel(float* __restrict__ S)
{
    __shared__ float redmax[8];
    __shared__ float redsum[8];
    float* r = S + (size_t)blockIdx.x * MP;
    int t = threadIdx.x;

    float4 v = ((float4*)r)[t];
    float m = fmaxf(fmaxf(v.x, v.y), fmaxf(v.z, v.w));
    #pragma unroll
    for (int o = 16; o > 0; o >>= 1) m = fmaxf(m, __shfl_xor_sync(0xffffffffu, m, o));
    if ((t & 31) == 0) redmax[t >> 5] = m;
    __syncthreads();
    m = redmax[0];
    #pragma unroll
    for (int i = 1; i < 8; i++) m = fmaxf(m, redmax[i]);

    float e0 = __expf(v.x - m), e1 = __expf(v.y - m);
    float e2 = __expf(v.z - m), e3 = __expf(v.w - m);
    float s = e0 + e1 + e2 + e3;
    #pragma unroll
    for (int o = 16; o > 0; o >>= 1) s += __shfl_xor_sync(0xffffffffu, s, o);
    if ((t & 31) == 0) redsum[t >> 5] = s;
    __syncthreads();
    s = 0.0f;
    #pragma unroll
    for (int i = 0; i < 8; i++) s += redsum[i];

    float inv = 1.0f / s;
    ((float4*)r)[t] = make_float4(e0 * inv, e1 * inv, e2 * inv, e3 * inv);
}

// ---------------------------------------------------------------------------
// launch
// ---------------------------------------------------------------------------
extern "C" void kernel_launch(void* const* d_in, const int* in_sizes, int n_in,
                              void* d_out, int out_size)
{
    const float* x     = (const float*)d_in[0];
    const float* Wf    = (const float*)d_in[1];
    const float* Wg    = (const float*)d_in[2];
    const float* Wh    = (const float*)d_in[3];
    const float* Wo    = (const float*)d_in[4];
    const float* gamma = (const float*)d_in[5];
    float* out = (float*)d_out;

    float *wcat_p, *wot_p, *gfh_p, *f_p, *h_p, *s_p, *o_p;
    cudaGetSymbolAddress((void**)&wcat_p, wcat_buf);
    cudaGetSymbolAddress((void**)&wot_p,  wot_buf);
    cudaGetSymbolAddress((void**)&gfh_p,  gfh_buf);
    cudaGetSymbolAddress((void**)&f_p,    f_buf);
    cudaGetSymbolAddress((void**)&h_p,    h_buf);
    cudaGetSymbolAddress((void**)&s_p,    s_buf);
    cudaGetSymbolAddress((void**)&o_p,    o_buf);

    const int SMEM_NT = 2 * (128 * 32 + 128 * 32) * 4;   // 65536
    const int SMEM_NN = 2 * (128 * 32 + 32 * 136) * 4;   // 67584

    cudaFuncSetAttribute(mma_gemm<0, 0>, cudaFuncAttributeMaxDynamicSharedMemorySize, SMEM_NT);
    cudaFuncSetAttribute(mma_gemm<0, 1>, cudaFuncAttributeMaxDynamicSharedMemorySize, SMEM_NT);
    cudaFuncSetAttribute(mma_gemm<1, 0>, cudaFuncAttributeMaxDynamicSharedMemorySize, SMEM_NN);

    prep_weights<<<(NCAT * CCH + 255) / 256, 256>>>(Wf, Wg, Wh, Wo, wcat_p, wot_p);

    // fused projections: gfh[32768,384] = X @ wcat^T   (K=512)
    mma_gemm<0, 0><<<dim3(3, 256, 1), 256, SMEM_NT>>>(
        x, wcat_p, gfh_p, CCH, CCH, CCH, NCAT, 0, 0, 0, nullptr, nullptr);

    pool_f<<<(BSZ * MP * CE + 255) / 256, 256>>>(gfh_p, f_p);
    pool_h<<<(BSZ * MP * CD + 255) / 256, 256>>>(gfh_p, h_p);

    // S[b] = G[b] @ F[b]^T   (M=4096, N=1024, K=64)
    mma_gemm<0, 0><<<dim3(8, 32, BSZ), 256, SMEM_NT>>>(
        gfh_p, f_p, s_p, CE, NCAT, CE, MP,
        (long long)NP * NCAT, (long long)MP * CE, (long long)NP * MP, nullptr, nullptr);

    softmax_kernel<<<BSZ * NP, 256>>>(s_p);

    // O[b] = P[b] @ H[b]   (M=4096, N=256, K=1024; B row-major [k][n])
    mma_gemm<1, 0><<<dim3(2, 32, BSZ), 256, SMEM_NN>>>(
        s_p, h_p, o_p, MP, MP, CD, CD,
        (long long)NP * MP, (long long)MP * CD, (long long)NP * CD, nullptr, nullptr);

    // out = gamma * (O @ Wo) + x   (M=32768, N=512, K=256)
    mma_gemm<0, 1><<<dim3(4, 256, 1), 256, SMEM_NT>>>(
        o_p, wot_p, out, CD, CD, CD, CCH, 0, 0, 0, gamma, x);
}

// round 10
// speedup vs baseline: 2.0878x; 1.2205x over previous
#include <cuda_runtime.h>
#include <cuda_fp16.h>
#include <cstdint>

#define BSZ 8
#define NP  4096
#define MP  1024
#define CCH 512
#define CE  64
#define CD  256
#define NCAT 384

// ---------------- scratch ----------------
__device__ __half xh_buf  [(size_t)BSZ * NP * CCH];   // x as fp16
__device__ __half wcat_buf[NCAT * CCH];               // [n][k] = [Wg|Wf|Wh]^T
__device__ __half wot_buf [CCH * CD];                 // [n][k] = Wo^T
__device__ __half gfh_buf [(size_t)BSZ * NP * NCAT];  // [B*4096][384]
__device__ __half f_buf   [BSZ * MP * CE];            // [b][key][e]
__device__ __half ht_buf  [BSZ * CD * MP];            // [b][d][key]
__device__ float  s_buf   [(size_t)BSZ * NP * MP];    // logits fp32
__device__ __half p_buf   [(size_t)BSZ * NP * MP];    // softmax weights fp16
__device__ __half o_buf   [(size_t)BSZ * NP * CD];    // [b*4096][256]

// ---------------- helpers ----------------
__device__ __forceinline__ uint32_t smem_u32(const void* p) {
    uint32_t a;
    asm("{ .reg .u64 t; cvta.to.shared.u64 t, %1; cvt.u32.u64 %0, t; }" : "=r"(a) : "l"(p));
    return a;
}
__device__ __forceinline__ void cp_async16(uint32_t dst, const void* src) {
    asm volatile("cp.async.cg.shared.global [%0], [%1], 16;" :: "r"(dst), "l"(src));
}
__device__ __forceinline__ void cp_commit() {
    asm volatile("cp.async.commit_group;" ::: "memory");
}
template <int N>
__device__ __forceinline__ void cp_wait() {
    asm volatile("cp.async.wait_group %0;" :: "n"(N) : "memory");
}
// fp16 mma, f32 accumulate
__device__ __forceinline__ void mma_f16(float c[4], const uint32_t a[4], const uint32_t b[2]) {
    asm volatile(
        "mma.sync.aligned.m16n8k16.row.col.f32.f16.f16.f32 "
        "{%0,%1,%2,%3}, {%4,%5,%6,%7}, {%8,%9}, {%0,%1,%2,%3};"
        : "+f"(c[0]), "+f"(c[1]), "+f"(c[2]), "+f"(c[3])
        : "r"(a[0]), "r"(a[1]), "r"(a[2]), "r"(a[3]), "r"(b[0]), "r"(b[1]));
}

// ---------------------------------------------------------------------------
// Pipelined NT fp16 GEMM: C[M,N] = A[M,K] * B[N,K]^T, A/B fp16 K-major.
// CTA 128x128, K-chunk 32, 2-stage cp.async. Tile rows padded to 40 halves
// (80B: 16B-aligned cp.async dst; fragment LDS bank-conflict-free).
// COUT: 0 = fp16 C, 1 = fp32 C, 2 = fp32 C = gamma*acc + resid.
// Requires M%128==0, N%128==0, K%32==0, K>=64.
// ---------------------------------------------------------------------------
#define RPAD 40
template <int COUT>
__global__ void __launch_bounds__(256, 2) mma_gemm_h(
    const __half* __restrict__ A, const __half* __restrict__ B, void* __restrict__ Cv,
    int K, int lda, int ldb, int ldc,
    long long strA, long long strB, long long strC,
    const float* __restrict__ gamma, const float* __restrict__ resid)
{
    __shared__ __align__(16) __half smh[2][2][128 * RPAD];
    const uint32_t sbase = smem_u32(&smh[0][0][0]);

    const int tid  = threadIdx.x;
    const int wid  = tid >> 5;
    const int lane = tid & 31;
    const int grp  = lane >> 2;
    const int quad = lane & 3;
    const int bz   = blockIdx.z;
    A += (size_t)bz * strA;
    B += (size_t)bz * strB;
    const int rowBase = blockIdx.y * 128;
    const int colBase = blockIdx.x * 128;
    const int wm = (wid >> 1) * 32;
    const int wn = (wid & 1) * 64;

    const int KB = K >> 5;

    auto prefetch = [&](int kb, int buf) {
        const uint32_t abase = sbase + (uint32_t)buf * (2 * 128 * RPAD * 2);
        const uint32_t bbase = abase + 128 * RPAD * 2;
        const __half* Ag = A + (size_t)rowBase * lda + kb * 32;
        const __half* Bg = B + (size_t)colBase * ldb + kb * 32;
        #pragma unroll
        for (int i = 0; i < 2; i++) {
            int idx = tid + 256 * i;
            int r = idx >> 2, seg = idx & 3;
            cp_async16(abase + (uint32_t)(r * 80 + seg * 16), Ag + (size_t)r * lda + seg * 8);
        }
        #pragma unroll
        for (int i = 0; i < 2; i++) {
            int idx = tid + 256 * i;
            int r = idx >> 2, seg = idx & 3;
            cp_async16(bbase + (uint32_t)(r * 80 + seg * 16), Bg + (size_t)r * ldb + seg * 8);
        }
        cp_commit();
    };

    float acc[2][8][4] = {};

    prefetch(0, 0);
    for (int kb = 0; kb < KB; kb++) {
        const int buf = kb & 1;
        if (kb + 1 < KB) {
            prefetch(kb + 1, buf ^ 1);
            cp_wait<1>();
        } else {
            cp_wait<0>();
        }
        __syncthreads();

        const __half* Asb = smh[buf][0];
        const __half* Bsb = smh[buf][1];

        #pragma unroll
        for (int step = 0; step < 2; step++) {
            const int kk = step * 16;
            uint32_t af[2][4];
            #pragma unroll
            for (int mi = 0; mi < 2; mi++) {
                const int m0 = wm + mi * 16 + grp, m1 = m0 + 8;
                af[mi][0] = *(const uint32_t*)(Asb + m0 * RPAD + kk + quad * 2);
                af[mi][1] = *(const uint32_t*)(Asb + m1 * RPAD + kk + quad * 2);
                af[mi][2] = *(const uint32_t*)(Asb + m0 * RPAD + kk + 8 + quad * 2);
                af[mi][3] = *(const uint32_t*)(Asb + m1 * RPAD + kk + 8 + quad * 2);
            }
            #pragma unroll
            for (int ni = 0; ni < 8; ni++) {
                const int n = wn + ni * 8 + grp;
                uint32_t bf[2];
                bf[0] = *(const uint32_t*)(Bsb + n * RPAD + kk + quad * 2);
                bf[1] = *(const uint32_t*)(Bsb + n * RPAD + kk + 8 + quad * 2);
                mma_f16(acc[0][ni], af[0], bf);
                mma_f16(acc[1][ni], af[1], bf);
            }
        }
        __syncthreads();
    }

    // epilogue
    const float gval = (COUT == 2) ? gamma[0] : 0.0f;
    #pragma unroll
    for (int mi = 0; mi < 2; mi++) {
        #pragma unroll
        for (int half_ = 0; half_ < 2; half_++) {
            const int row = rowBase + wm + mi * 16 + half_ * 8 + grp;
            const int col0 = colBase + wn + quad * 2;
            if (COUT == 0) {
                __half* C = (__half*)Cv + (size_t)bz * strC + (size_t)row * ldc + col0;
                #pragma unroll
                for (int ni = 0; ni < 8; ni++) {
                    __half2 hv = __floats2half2_rn(acc[mi][ni][half_ * 2 + 0],
                                                   acc[mi][ni][half_ * 2 + 1]);
                    *(__half2*)(C + ni * 8) = hv;
                }
            } else {
                float* C = (float*)Cv + (size_t)bz * strC + (size_t)row * ldc + col0;
                #pragma unroll
                for (int ni = 0; ni < 8; ni++) {
                    float v0 = acc[mi][ni][half_ * 2 + 0];
                    float v1 = acc[mi][ni][half_ * 2 + 1];
                    if (COUT == 2) {
                        const float* rp = resid + (size_t)row * ldc + col0 + ni * 8;
                        float2 rv = *(const float2*)rp;
                        v0 = fmaf(gval, v0, rv.x);
                        v1 = fmaf(gval, v1, rv.y);
                    }
                    *(float2*)(C + ni * 8) = make_float2(v0, v1);
                }
            }
        }
    }
}

// ---------------------------------------------------------------------------
// x -> fp16 (8 floats per thread)
// ---------------------------------------------------------------------------
__global__ void xcvt(const float* __restrict__ x, __half* __restrict__ xh)
{
    size_t i = ((size_t)blockIdx.x * 256 + threadIdx.x) * 8;
    float4 v0 = *(const float4*)(x + i);
    float4 v1 = *(const float4*)(x + i + 4);
    __half2 h0 = __floats2half2_rn(v0.x, v0.y);
    __half2 h1 = __floats2half2_rn(v0.z, v0.w);
    __half2 h2 = __floats2half2_rn(v1.x, v1.y);
    __half2 h3 = __floats2half2_rn(v1.z, v1.w);
    uint4 u;
    u.x = *(uint32_t*)&h0; u.y = *(uint32_t*)&h1;
    u.z = *(uint32_t*)&h2; u.w = *(uint32_t*)&h3;
    *(uint4*)(xh + i) = u;
}

// ---------------------------------------------------------------------------
// weight prep (fp16): wcat[n][k], wot[n][k]
// ---------------------------------------------------------------------------
__global__ void prep_weights(const float* __restrict__ Wf, const float* __restrict__ Wg,
                             const float* __restrict__ Wh, const float* __restrict__ Wo,
                             __half* __restrict__ wcat, __half* __restrict__ wot)
{
    int idx = blockIdx.x * 256 + threadIdx.x;
    if (idx < NCAT * CCH) {
        int n = idx / CCH, k = idx % CCH;
        float v;
        if (n < 64)       v = Wg[(size_t)k * 64 + n];
        else if (n < 128) v = Wf[(size_t)k * 64 + (n - 64)];
        else              v = Wh[(size_t)k * 256 + (n - 128)];
        wcat[idx] = __float2half_rn(v);
    }
    if (idx < CCH * CD) {
        int n = idx / CD, k = idx % CD;
        wot[idx] = __float2half_rn(Wo[(size_t)k * CCH + n]);
    }
}

// ---------------------------------------------------------------------------
// pool_f: gfh cols [64,128) -> f[b][key][e], fp16, half2 per thread
// ---------------------------------------------------------------------------
__global__ void pool_f(const __half* __restrict__ gfh, __half* __restrict__ f)
{
    int idx = blockIdx.x * 256 + threadIdx.x;      // over BSZ*MP*32 half2 units
    if (idx >= BSZ * MP * 32) return;
    int e2 = idx & 31;
    int m  = (idx >> 5) & 1023;
    int b  = idx >> 15;
    int p = m >> 5, q = m & 31;
    const __half* base = gfh + ((size_t)b * NP + 2 * p * 64 + 2 * q) * NCAT + 64 + e2 * 2;
    __half2 v0 = *(const __half2*)base;
    __half2 v1 = *(const __half2*)(base + NCAT);
    __half2 v2 = *(const __half2*)(base + 64 * NCAT);
    __half2 v3 = *(const __half2*)(base + 64 * NCAT + NCAT);
    ((__half2*)f)[idx] = __hmax2(__hmax2(v0, v1), __hmax2(v2, v3));
}

// ---------------------------------------------------------------------------
// pool_ht: gfh cols [128,384) -> ht[b][d][key] (transposed via smem).
// Block tile: 64 keys (m) x 64 d.  grid (16, 4, BSZ), 256 threads.
// ---------------------------------------------------------------------------
__global__ void pool_ht(const __half* __restrict__ gfh, __half* __restrict__ ht)
{
    __shared__ __half ts[64 * 70];                 // [m][d] pad 70 halves
    const int tid  = threadIdx.x;
    const int mblk = blockIdx.x * 64;
    const int dblk = blockIdx.y * 64;
    const int b    = blockIdx.z;

    #pragma unroll
    for (int j = 0; j < 8; j++) {
        int pr = tid + 256 * j;                    // 2048 (m, d2) pairs
        int m  = pr >> 5, d2 = pr & 31;
        int mg = mblk + m;
        int p = mg >> 5, q = mg & 31;
        const __half* base = gfh + ((size_t)b * NP + 2 * p * 64 + 2 * q) * NCAT
                             + 128 + dblk + d2 * 2;
        __half2 v0 = *(const __half2*)base;
        __half2 v1 = *(const __half2*)(base + NCAT);
        __half2 v2 = *(const __half2*)(base + 64 * NCAT);
        __half2 v3 = *(const __half2*)(base + 64 * NCAT + NCAT);
        *(__half2*)(ts + m * 70 + d2 * 2) = __hmax2(__hmax2(v0, v1), __hmax2(v2, v3));
    }
    __syncthreads();

    const int d  = tid >> 2;
    const int mo = (tid & 3) * 16;
    __half* orow = ht + ((size_t)b * CD + dblk + d) * MP + mblk + mo;
    #pragma unroll
    for (int i = 0; i < 16; i++)
        orow[i] = ts[(mo + i) * 70 + d];
}

// ---------------------------------------------------------------------------
// softmax: fp32 logits in, fp16 weights out. 1 block / row.
// ---------------------------------------------------------------------------
__global__ void softmax_kernel(const float* __restrict__ S, __half* __restrict__ P)
{
    __shared__ float redmax[8];
    __shared__ float redsum[8];
    const float* r = S + (size_t)blockIdx.x * MP;
    __half* pr = P + (size_t)blockIdx.x * MP;
    int t = threadIdx.x;

    float4 v = ((const float4*)r)[t];
    float m = fmaxf(fmaxf(v.x, v.y), fmaxf(v.z, v.w));
    #pragma unroll
    for (int o = 16; o > 0; o >>= 1) m = fmaxf(m, __shfl_xor_sync(0xffffffffu, m, o));
    if ((t & 31) == 0) redmax[t >> 5] = m;
    __syncthreads();
    m = redmax[0];
    #pragma unroll
    for (int i = 1; i < 8; i++) m = fmaxf(m, redmax[i]);

    float e0 = __expf(v.x - m), e1 = __expf(v.y - m);
    float e2 = __expf(v.z - m), e3 = __expf(v.w - m);
    float s = e0 + e1 + e2 + e3;
    #pragma unroll
    for (int o = 16; o > 0; o >>= 1) s += __shfl_xor_sync(0xffffffffu, s, o);
    if ((t & 31) == 0) redsum[t >> 5] = s;
    __syncthreads();
    s = 0.0f;
    #pragma unroll
    for (int i = 0; i < 8; i++) s += redsum[i];

    float inv = 1.0f / s;
    __half2 h01 = __floats2half2_rn(e0 * inv, e1 * inv);
    __half2 h23 = __floats2half2_rn(e2 * inv, e3 * inv);
    uint2 u;
    u.x = *(uint32_t*)&h01;
    u.y = *(uint32_t*)&h23;
    ((uint2*)pr)[t] = u;
}

// ---------------------------------------------------------------------------
// launch
// ---------------------------------------------------------------------------
extern "C" void kernel_launch(void* const* d_in, const int* in_sizes, int n_in,
                              void* d_out, int out_size)
{
    const float* x     = (const float*)d_in[0];
    const float* Wf    = (const float*)d_in[1];
    const float* Wg    = (const float*)d_in[2];
    const float* Wh    = (const float*)d_in[3];
    const float* Wo    = (const float*)d_in[4];
    const float* gamma = (const float*)d_in[5];
    float* out = (float*)d_out;

    __half *xh_p, *wcat_p, *wot_p, *gfh_p, *f_p, *ht_p, *p_p, *o_p;
    float *s_p;
    cudaGetSymbolAddress((void**)&xh_p,   xh_buf);
    cudaGetSymbolAddress((void**)&wcat_p, wcat_buf);
    cudaGetSymbolAddress((void**)&wot_p,  wot_buf);
    cudaGetSymbolAddress((void**)&gfh_p,  gfh_buf);
    cudaGetSymbolAddress((void**)&f_p,    f_buf);
    cudaGetSymbolAddress((void**)&ht_p,   ht_buf);
    cudaGetSymbolAddress((void**)&s_p,    s_buf);
    cudaGetSymbolAddress((void**)&p_p,    p_buf);
    cudaGetSymbolAddress((void**)&o_p,    o_buf);

    // x -> fp16 ; weights -> fp16
    xcvt<<<(BSZ * NP * CCH) / (256 * 8), 256>>>(x, xh_p);
    prep_weights<<<(NCAT * CCH + 255) / 256, 256>>>(Wf, Wg, Wh, Wo, wcat_p, wot_p);

    // fused projections: gfh[32768,384] = X @ wcat^T   (K=512)
    mma_gemm_h<0><<<dim3(3, 256, 1), 256>>>(
        xh_p, wcat_p, gfh_p, CCH, CCH, CCH, NCAT, 0, 0, 0, nullptr, nullptr);

    // pools
    pool_f <<<(BSZ * MP * 32) / 256, 256>>>(gfh_p, f_p);
    pool_ht<<<dim3(16, 4, BSZ), 256>>>(gfh_p, ht_p);

    // S[b] = G[b] @ F[b]^T  (M=4096, N=1024, K=64) -> fp32 logits
    mma_gemm_h<1><<<dim3(8, 32, BSZ), 256>>>(
        gfh_p, f_p, s_p, CE, NCAT, CE, MP,
        (long long)NP * NCAT, (long long)MP * CE, (long long)NP * MP, nullptr, nullptr);

    // softmax -> fp16 P
    softmax_kernel<<<BSZ * NP, 256>>>(s_p, p_p);

    // O[b] = P[b] @ Ht[b]^T  (M=4096, N=256, K=1024)
    mma_gemm_h<0><<<dim3(2, 32, BSZ), 256>>>(
        p_p, ht_p, o_p, MP, MP, MP, CD,
        (long long)NP * MP, (long long)CD * MP, (long long)NP * CD, nullptr, nullptr);

    // out = gamma * (O @ Wo) + x   (M=32768, N=512, K=256)
    mma_gemm_h<2><<<dim3(4, 256, 1), 256>>>(
        o_p, wot_p, out, CD, CD, CD, CCH, 0, 0, 0, gamma, x);
}

// round 11
// speedup vs baseline: 2.1843x; 1.0462x over previous
#include <cuda_runtime.h>
#include <cuda_fp16.h>
#include <cstdint>

#define BSZ 8
#define NP  4096
#define MP  1024
#define CCH 512
#define CE  64
#define CD  256
#define NCAT 384

// ---------------- scratch ----------------
__device__ __half xh_buf  [(size_t)BSZ * NP * CCH];   // x as fp16
__device__ __half wcat_buf[NCAT * CCH];               // [n][k] = [Wg|Wf|Wh]^T
__device__ __half wot_buf [CCH * CD];                 // [n][k] = Wo^T
__device__ __half gfh_buf [(size_t)BSZ * NP * NCAT];  // [B*4096][384]
__device__ __half f_buf   [BSZ * MP * CE];            // [b][key][e]
__device__ __half ht_buf  [BSZ * CD * MP];            // [b][d][key]
__device__ __half s_buf   [(size_t)BSZ * NP * MP];    // fp16 logits, then P in place
__device__ __half o_buf   [(size_t)BSZ * NP * CD];    // [b*4096][256]

// ---------------- helpers ----------------
__device__ __forceinline__ uint32_t smem_u32(const void* p) {
    uint32_t a;
    asm("{ .reg .u64 t; cvta.to.shared.u64 t, %1; cvt.u32.u64 %0, t; }" : "=r"(a) : "l"(p));
    return a;
}
__device__ __forceinline__ void cp_async16(uint32_t dst, const void* src) {
    asm volatile("cp.async.cg.shared.global [%0], [%1], 16;" :: "r"(dst), "l"(src));
}
__device__ __forceinline__ void cp_commit() {
    asm volatile("cp.async.commit_group;" ::: "memory");
}
template <int N>
__device__ __forceinline__ void cp_wait() {
    asm volatile("cp.async.wait_group %0;" :: "n"(N) : "memory");
}
// fp16 mma, f32 accumulate
__device__ __forceinline__ void mma_f16(float c[4], const uint32_t a[4], const uint32_t b[2]) {
    asm volatile(
        "mma.sync.aligned.m16n8k16.row.col.f32.f16.f16.f32 "
        "{%0,%1,%2,%3}, {%4,%5,%6,%7}, {%8,%9}, {%0,%1,%2,%3};"
        : "+f"(c[0]), "+f"(c[1]), "+f"(c[2]), "+f"(c[3])
        : "r"(a[0]), "r"(a[1]), "r"(a[2]), "r"(a[3]), "r"(b[0]), "r"(b[1]));
}

// ---------------------------------------------------------------------------
// 3-stage pipelined NT fp16 GEMM: C[M,N] = A[M,K] * B[N,K]^T, A/B fp16 K-major.
// CTA 128x128, K-chunk 32, cp.async triple buffer (dynamic smem 61.4 KB).
// Tile rows padded to 40 halves (80B; 16B-aligned cp.async, conflict-free LDS).
// COUT: 0 = fp16 C, 1 = fp32 C, 2 = fp32 C = gamma*acc + resid.
// Requires M%128==0, N%128==0, K%32==0, KB>=2.
// ---------------------------------------------------------------------------
#define RPAD    40
#define STAGE_H (2 * 128 * RPAD)            // halves per stage (A tile + B tile)
#define GEMM_SMEM (3 * STAGE_H * 2)         // bytes

template <int COUT>
__global__ void __launch_bounds__(256, 2) mma_gemm_h(
    const __half* __restrict__ A, const __half* __restrict__ B, void* __restrict__ Cv,
    int K, int lda, int ldb, int ldc,
    long long strA, long long strB, long long strC,
    const float* __restrict__ gamma, const float* __restrict__ resid)
{
    extern __shared__ __align__(16) __half smh[];
    const uint32_t sbase = smem_u32(smh);

    const int tid  = threadIdx.x;
    const int wid  = tid >> 5;
    const int lane = tid & 31;
    const int grp  = lane >> 2;
    const int quad = lane & 3;
    const int bz   = blockIdx.z;
    A += (size_t)bz * strA;
    B += (size_t)bz * strB;
    const int rowBase = blockIdx.y * 128;
    const int colBase = blockIdx.x * 128;
    const int wm = (wid >> 1) * 32;
    const int wn = (wid & 1) * 64;

    const int KB = K >> 5;

    auto prefetch = [&](int kb, int stage) {
        const uint32_t abase = sbase + (uint32_t)stage * (STAGE_H * 2);
        const uint32_t bbase = abase + 128 * RPAD * 2;
        const __half* Ag = A + (size_t)rowBase * lda + kb * 32;
        const __half* Bg = B + (size_t)colBase * ldb + kb * 32;
        #pragma unroll
        for (int i = 0; i < 2; i++) {
            int idx = tid + 256 * i;
            int r = idx >> 2, seg = idx & 3;
            cp_async16(abase + (uint32_t)(r * 80 + seg * 16), Ag + (size_t)r * lda + seg * 8);
        }
        #pragma unroll
        for (int i = 0; i < 2; i++) {
            int idx = tid + 256 * i;
            int r = idx >> 2, seg = idx & 3;
            cp_async16(bbase + (uint32_t)(r * 80 + seg * 16), Bg + (size_t)r * ldb + seg * 8);
        }
        cp_commit();
    };

    float acc[2][8][4] = {};

    prefetch(0, 0);
    if (KB > 1) prefetch(1, 1);

    int buf = 0;
    for (int kb = 0; kb < KB; kb++) {
        if (kb + 2 < KB) {
            int nb = buf + 2; if (nb >= 3) nb -= 3;
            prefetch(kb + 2, nb);
            cp_wait<2>();
        } else if (kb + 1 < KB) {
            cp_wait<1>();
        } else {
            cp_wait<0>();
        }
        __syncthreads();

        const __half* Asb = smh + buf * STAGE_H;
        const __half* Bsb = Asb + 128 * RPAD;

        #pragma unroll
        for (int step = 0; step < 2; step++) {
            const int kk = step * 16;
            uint32_t af[2][4];
            #pragma unroll
            for (int mi = 0; mi < 2; mi++) {
                const int m0 = wm + mi * 16 + grp, m1 = m0 + 8;
                af[mi][0] = *(const uint32_t*)(Asb + m0 * RPAD + kk + quad * 2);
                af[mi][1] = *(const uint32_t*)(Asb + m1 * RPAD + kk + quad * 2);
                af[mi][2] = *(const uint32_t*)(Asb + m0 * RPAD + kk + 8 + quad * 2);
                af[mi][3] = *(const uint32_t*)(Asb + m1 * RPAD + kk + 8 + quad * 2);
            }
            #pragma unroll
            for (int ni = 0; ni < 8; ni++) {
                const int n = wn + ni * 8 + grp;
                uint32_t bf[2];
                bf[0] = *(const uint32_t*)(Bsb + n * RPAD + kk + quad * 2);
                bf[1] = *(const uint32_t*)(Bsb + n * RPAD + kk + 8 + quad * 2);
                mma_f16(acc[0][ni], af[0], bf);
                mma_f16(acc[1][ni], af[1], bf);
            }
        }
        __syncthreads();
        if (++buf == 3) buf = 0;
    }

    // epilogue
    const float gval = (COUT == 2) ? gamma[0] : 0.0f;
    #pragma unroll
    for (int mi = 0; mi < 2; mi++) {
        #pragma unroll
        for (int half_ = 0; half_ < 2; half_++) {
            const int row = rowBase + wm + mi * 16 + half_ * 8 + grp;
            const int col0 = colBase + wn + quad * 2;
            if (COUT == 0) {
                __half* C = (__half*)Cv + (size_t)bz * strC + (size_t)row * ldc + col0;
                #pragma unroll
                for (int ni = 0; ni < 8; ni++) {
                    __half2 hv = __floats2half2_rn(acc[mi][ni][half_ * 2 + 0],
                                                   acc[mi][ni][half_ * 2 + 1]);
                    *(__half2*)(C + ni * 8) = hv;
                }
            } else {
                float* C = (float*)Cv + (size_t)bz * strC + (size_t)row * ldc + col0;
                #pragma unroll
                for (int ni = 0; ni < 8; ni++) {
                    float v0 = acc[mi][ni][half_ * 2 + 0];
                    float v1 = acc[mi][ni][half_ * 2 + 1];
                    if (COUT == 2) {
                        const float* rp = resid + (size_t)row * ldc + col0 + ni * 8;
                        float2 rv = *(const float2*)rp;
                        v0 = fmaf(gval, v0, rv.x);
                        v1 = fmaf(gval, v1, rv.y);
                    }
                    *(float2*)(C + ni * 8) = make_float2(v0, v1);
                }
            }
        }
    }
}

// ---------------------------------------------------------------------------
// x -> fp16 (8 floats per thread)
// ---------------------------------------------------------------------------
__global__ void xcvt(const float* __restrict__ x, __half* __restrict__ xh)
{
    size_t i = ((size_t)blockIdx.x * 256 + threadIdx.x) * 8;
    float4 v0 = *(const float4*)(x + i);
    float4 v1 = *(const float4*)(x + i + 4);
    __half2 h0 = __floats2half2_rn(v0.x, v0.y);
    __half2 h1 = __floats2half2_rn(v0.z, v0.w);
    __half2 h2 = __floats2half2_rn(v1.x, v1.y);
    __half2 h3 = __floats2half2_rn(v1.z, v1.w);
    uint4 u;
    u.x = *(uint32_t*)&h0; u.y = *(uint32_t*)&h1;
    u.z = *(uint32_t*)&h2; u.w = *(uint32_t*)&h3;
    *(uint4*)(xh + i) = u;
}

// ---------------------------------------------------------------------------
// weight prep (fp16): wcat[n][k], wot[n][k]
// ---------------------------------------------------------------------------
__global__ void prep_weights(const float* __restrict__ Wf, const float* __restrict__ Wg,
                             const float* __restrict__ Wh, const float* __restrict__ Wo,
                             __half* __restrict__ wcat, __half* __restrict__ wot)
{
    int idx = blockIdx.x * 256 + threadIdx.x;
    if (idx < NCAT * CCH) {
        int n = idx / CCH, k = idx % CCH;
        float v;
        if (n < 64)       v = Wg[(size_t)k * 64 + n];
        else if (n < 128) v = Wf[(size_t)k * 64 + (n - 64)];
        else              v = Wh[(size_t)k * 256 + (n - 128)];
        wcat[idx] = __float2half_rn(v);
    }
    if (idx < CCH * CD) {
        int n = idx / CD, k = idx % CD;
        wot[idx] = __float2half_rn(Wo[(size_t)k * CCH + n]);
    }
}

// ---------------------------------------------------------------------------
// pool_f: gfh cols [64,128) -> f[b][key][e], fp16, half2 per thread
// ---------------------------------------------------------------------------
__global__ void pool_f(const __half* __restrict__ gfh, __half* __restrict__ f)
{
    int idx = blockIdx.x * 256 + threadIdx.x;      // over BSZ*MP*32 half2 units
    if (idx >= BSZ * MP * 32) return;
    int e2 = idx & 31;
    int m  = (idx >> 5) & 1023;
    int b  = idx >> 15;
    int p = m >> 5, q = m & 31;
    const __half* base = gfh + ((size_t)b * NP + 2 * p * 64 + 2 * q) * NCAT + 64 + e2 * 2;
    __half2 v0 = *(const __half2*)base;
    __half2 v1 = *(const __half2*)(base + NCAT);
    __half2 v2 = *(const __half2*)(base + 64 * NCAT);
    __half2 v3 = *(const __half2*)(base + 64 * NCAT + NCAT);
    ((__half2*)f)[idx] = __hmax2(__hmax2(v0, v1), __hmax2(v2, v3));
}

// ---------------------------------------------------------------------------
// pool_ht: gfh cols [128,384) -> ht[b][d][key] (transposed via smem).
// ---------------------------------------------------------------------------
__global__ void pool_ht(const __half* __restrict__ gfh, __half* __restrict__ ht)
{
    __shared__ __half ts[64 * 70];
    const int tid  = threadIdx.x;
    const int mblk = blockIdx.x * 64;
    const int dblk = blockIdx.y * 64;
    const int b    = blockIdx.z;

    #pragma unroll
    for (int j = 0; j < 8; j++) {
        int pr = tid + 256 * j;
        int m  = pr >> 5, d2 = pr & 31;
        int mg = mblk + m;
        int p = mg >> 5, q = mg & 31;
        const __half* base = gfh + ((size_t)b * NP + 2 * p * 64 + 2 * q) * NCAT
                             + 128 + dblk + d2 * 2;
        __half2 v0 = *(const __half2*)base;
        __half2 v1 = *(const __half2*)(base + NCAT);
        __half2 v2 = *(const __half2*)(base + 64 * NCAT);
        __half2 v3 = *(const __half2*)(base + 64 * NCAT + NCAT);
        *(__half2*)(ts + m * 70 + d2 * 2) = __hmax2(__hmax2(v0, v1), __hmax2(v2, v3));
    }
    __syncthreads();

    const int d  = tid >> 2;
    const int mo = (tid & 3) * 16;
    __half* orow = ht + ((size_t)b * CD + dblk + d) * MP + mblk + mo;
    #pragma unroll
    for (int i = 0; i < 16; i++)
        orow[i] = ts[(mo + i) * 70 + d];
}

// ---------------------------------------------------------------------------
// softmax: fp16 logits in, fp16 weights out, IN PLACE. 1 block / row.
// ---------------------------------------------------------------------------
__global__ void softmax_kernel(__half* __restrict__ S)
{
    __shared__ float redmax[8];
    __shared__ float redsum[8];
    __half* r = S + (size_t)blockIdx.x * MP;
    int t = threadIdx.x;

    uint2 u = ((const uint2*)r)[t];
    __half2 a01 = *(__half2*)&u.x;
    __half2 a23 = *(__half2*)&u.y;
    float v0 = __low2float(a01), v1 = __high2float(a01);
    float v2 = __low2float(a23), v3 = __high2float(a23);

    float m = fmaxf(fmaxf(v0, v1), fmaxf(v2, v3));
    #pragma unroll
    for (int o = 16; o > 0; o >>= 1) m = fmaxf(m, __shfl_xor_sync(0xffffffffu, m, o));
    if ((t & 31) == 0) redmax[t >> 5] = m;
    __syncthreads();
    m = redmax[0];
    #pragma unroll
    for (int i = 1; i < 8; i++) m = fmaxf(m, redmax[i]);

    float e0 = __expf(v0 - m), e1 = __expf(v1 - m);
    float e2 = __expf(v2 - m), e3 = __expf(v3 - m);
    float s = e0 + e1 + e2 + e3;
    #pragma unroll
    for (int o = 16; o > 0; o >>= 1) s += __shfl_xor_sync(0xffffffffu, s, o);
    if ((t & 31) == 0) redsum[t >> 5] = s;
    __syncthreads();
    s = 0.0f;
    #pragma unroll
    for (int i = 0; i < 8; i++) s += redsum[i];

    float inv = 1.0f / s;
    __half2 h01 = __floats2half2_rn(e0 * inv, e1 * inv);
    __half2 h23 = __floats2half2_rn(e2 * inv, e3 * inv);
    uint2 o2;
    o2.x = *(uint32_t*)&h01;
    o2.y = *(uint32_t*)&h23;
    ((uint2*)r)[t] = o2;
}

// ---------------------------------------------------------------------------
// launch
// ---------------------------------------------------------------------------
extern "C" void kernel_launch(void* const* d_in, const int* in_sizes, int n_in,
                              void* d_out, int out_size)
{
    const float* x     = (const float*)d_in[0];
    const float* Wf    = (const float*)d_in[1];
    const float* Wg    = (const float*)d_in[2];
    const float* Wh    = (const float*)d_in[3];
    const float* Wo    = (const float*)d_in[4];
    const float* gamma = (const float*)d_in[5];
    float* out = (float*)d_out;

    __half *xh_p, *wcat_p, *wot_p, *gfh_p, *f_p, *ht_p, *s_p, *o_p;
    cudaGetSymbolAddress((void**)&xh_p,   xh_buf);
    cudaGetSymbolAddress((void**)&wcat_p, wcat_buf);
    cudaGetSymbolAddress((void**)&wot_p,  wot_buf);
    cudaGetSymbolAddress((void**)&gfh_p,  gfh_buf);
    cudaGetSymbolAddress((void**)&f_p,    f_buf);
    cudaGetSymbolAddress((void**)&ht_p,   ht_buf);
    cudaGetSymbolAddress((void**)&s_p,    s_buf);
    cudaGetSymbolAddress((void**)&o_p,    o_buf);

    cudaFuncSetAttribute(mma_gemm_h<0>, cudaFuncAttributeMaxDynamicSharedMemorySize, GEMM_SMEM);
    cudaFuncSetAttribute(mma_gemm_h<1>, cudaFuncAttributeMaxDynamicSharedMemorySize, GEMM_SMEM);
    cudaFuncSetAttribute(mma_gemm_h<2>, cudaFuncAttributeMaxDynamicSharedMemorySize, GEMM_SMEM);

    // x -> fp16 ; weights -> fp16
    xcvt<<<(BSZ * NP * CCH) / (256 * 8), 256>>>(x, xh_p);
    prep_weights<<<(NCAT * CCH + 255) / 256, 256>>>(Wf, Wg, Wh, Wo, wcat_p, wot_p);

    // fused projections: gfh[32768,384] = X @ wcat^T   (K=512)
    mma_gemm_h<0><<<dim3(3, 256, 1), 256, GEMM_SMEM>>>(
        xh_p, wcat_p, gfh_p, CCH, CCH, CCH, NCAT, 0, 0, 0, nullptr, nullptr);

    // pools
    pool_f <<<(BSZ * MP * 32) / 256, 256>>>(gfh_p, f_p);
    pool_ht<<<dim3(16, 4, BSZ), 256>>>(gfh_p, ht_p);

    // S[b] = G[b] @ F[b]^T  (M=4096, N=1024, K=64) -> fp16 logits
    mma_gemm_h<0><<<dim3(8, 32, BSZ), 256, GEMM_SMEM>>>(
        gfh_p, f_p, s_p, CE, NCAT, CE, MP,
        (long long)NP * NCAT, (long long)MP * CE, (long long)NP * MP, nullptr, nullptr);

    // softmax in place: S -> P (fp16)
    softmax_kernel<<<BSZ * NP, 256>>>(s_p);

    // O[b] = P[b] @ Ht[b]^T  (M=4096, N=256, K=1024)
    mma_gemm_h<0><<<dim3(2, 32, BSZ), 256, GEMM_SMEM>>>(
        s_p, ht_p, o_p, MP, MP, MP, CD,
        (long long)NP * MP, (long long)CD * MP, (long long)NP * CD, nullptr, nullptr);

    // out = gamma * (O @ Wo) + x   (M=32768, N=512, K=256)
    mma_gemm_h<2><<<dim3(4, 256, 1), 256, GEMM_SMEM>>>(
        o_p, wot_p, out, CD, CD, CD, CCH, 0, 0, 0, gamma, x);
}

// round 12
// speedup vs baseline: 2.5514x; 1.1681x over previous
#include <cuda_runtime.h>
#include <cuda_fp16.h>
#include <cstdint>

#define BSZ 8
#define NP  4096
#define MP  1024
#define CCH 512
#define CE  64
#define CD  256
#define NCAT 384

// ---------------- scratch ----------------
__device__ __half xh_buf  [(size_t)BSZ * NP * CCH];   // x as fp16
__device__ __half wcat_buf[NCAT * CCH];               // [n][k] = [Wg|Wf|Wh]^T
__device__ __half wot_buf [CCH * CD];                 // [n][k] = Wo^T
__device__ __half g_buf   [(size_t)BSZ * NP * CE];    // queries [B*4096][64]
__device__ __half f_buf   [BSZ * MP * CE];            // [b][key][e]
__device__ __half ht_buf  [BSZ * CD * MP];            // [b][d][key]
__device__ __half s_buf   [(size_t)BSZ * NP * MP];    // fp16 logits, then P in place
__device__ __half o_buf   [(size_t)BSZ * NP * CD];    // [b*4096][256]

// ---------------- helpers ----------------
__device__ __forceinline__ uint32_t smem_u32(const void* p) {
    uint32_t a;
    asm("{ .reg .u64 t; cvta.to.shared.u64 t, %1; cvt.u32.u64 %0, t; }" : "=r"(a) : "l"(p));
    return a;
}
__device__ __forceinline__ void cp_async16(uint32_t dst, const void* src) {
    asm volatile("cp.async.cg.shared.global [%0], [%1], 16;" :: "r"(dst), "l"(src));
}
__device__ __forceinline__ void cp_commit() {
    asm volatile("cp.async.commit_group;" ::: "memory");
}
template <int N>
__device__ __forceinline__ void cp_wait() {
    asm volatile("cp.async.wait_group %0;" :: "n"(N) : "memory");
}
__device__ __forceinline__ void ldm_x4(uint32_t r[4], uint32_t addr) {
    asm volatile("ldmatrix.sync.aligned.m8n8.x4.shared.b16 {%0,%1,%2,%3}, [%4];"
                 : "=r"(r[0]), "=r"(r[1]), "=r"(r[2]), "=r"(r[3]) : "r"(addr));
}
// fp16 mma, f32 accumulate
__device__ __forceinline__ void mma_f16(float c[4], const uint32_t a[4],
                                        uint32_t b0, uint32_t b1) {
    asm volatile(
        "mma.sync.aligned.m16n8k16.row.col.f32.f16.f16.f32 "
        "{%0,%1,%2,%3}, {%4,%5,%6,%7}, {%8,%9}, {%0,%1,%2,%3};"
        : "+f"(c[0]), "+f"(c[1]), "+f"(c[2]), "+f"(c[3])
        : "r"(a[0]), "r"(a[1]), "r"(a[2]), "r"(a[3]), "r"(b0), "r"(b1));
}

// ---------------------------------------------------------------------------
// 3-stage pipelined NT fp16 GEMM: C[M,N] = A[M,K] * B[N,K]^T, A/B fp16 K-major.
// CTA 128x128, K-chunk 32, cp.async triple buffer, ldmatrix fragment loads.
// COUT: 0 = fp16 C; 1 = fp32 C; 2 = fp32 C = gamma*acc + resid;
//       3 = projection epilogue: nx==0 -> write g cols[0:64) + pooled f,
//           nx 1,2 -> pooled+transposed ht.  (grid must be (3, 256, 1))
// Requires M%128==0, N%128==0, K%32==0, KB>=2.
// ---------------------------------------------------------------------------
#define RPAD    40
#define STAGE_H (2 * 128 * RPAD)            // halves per stage (A tile + B tile)
#define GEMM_SMEM (3 * STAGE_H * 2)         // 61440 bytes
#define TS_LD 136

template <int COUT>
__global__ void __launch_bounds__(256, 2) mma_gemm_h(
    const __half* __restrict__ A, const __half* __restrict__ B, void* __restrict__ Cv,
    int K, int lda, int ldb, int ldc,
    long long strA, long long strB, long long strC,
    const float* __restrict__ gamma, const float* __restrict__ resid,
    __half* __restrict__ f_out, __half* __restrict__ ht_out)
{
    extern __shared__ __align__(16) __half smh[];
    const uint32_t sbase = smem_u32(smh);

    const int tid  = threadIdx.x;
    const int wid  = tid >> 5;
    const int lane = tid & 31;
    const int grp  = lane >> 2;
    const int quad = lane & 3;
    const int bz   = blockIdx.z;
    A += (size_t)bz * strA;
    B += (size_t)bz * strB;
    const int rowBase = blockIdx.y * 128;
    const int colBase = blockIdx.x * 128;
    const int wm = (wid >> 1) * 32;
    const int wn = (wid & 1) * 64;

    const int KB = K >> 5;

    auto prefetch = [&](int kb, int stage) {
        const uint32_t abase = sbase + (uint32_t)stage * (STAGE_H * 2);
        const uint32_t bbase = abase + 128 * RPAD * 2;
        const __half* Ag = A + (size_t)rowBase * lda + kb * 32;
        const __half* Bg = B + (size_t)colBase * ldb + kb * 32;
        #pragma unroll
        for (int i = 0; i < 2; i++) {
            int idx = tid + 256 * i;
            int r = idx >> 2, seg = idx & 3;
            cp_async16(abase + (uint32_t)(r * 80 + seg * 16), Ag + (size_t)r * lda + seg * 8);
        }
        #pragma unroll
        for (int i = 0; i < 2; i++) {
            int idx = tid + 256 * i;
            int r = idx >> 2, seg = idx & 3;
            cp_async16(bbase + (uint32_t)(r * 80 + seg * 16), Bg + (size_t)r * ldb + seg * 8);
        }
        cp_commit();
    };

    float acc[2][8][4] = {};

    prefetch(0, 0);
    if (KB > 1) prefetch(1, 1);

    // lane-mapped ldmatrix address components (halves)
    const int a_row_off = lane & 15;          // row within 16-row block
    const int a_k_off   = (lane >> 4) << 3;   // 0 or 8
    const int b_n_off   = (lane & 7) + ((lane & 16) ? 8 : 0);
    const int b_k_off   = (lane & 8);         // 0 or 8

    int buf = 0;
    for (int kb = 0; kb < KB; kb++) {
        if (kb + 1 < KB) { cp_wait<1>(); } else { cp_wait<0>(); }
        __syncthreads();
        if (kb + 2 < KB) {
            int nb = buf + 2; if (nb >= 3) nb -= 3;
            prefetch(kb + 2, nb);
        }

        const uint32_t aaddr0 = sbase + (uint32_t)buf * (STAGE_H * 2);
        const uint32_t baddr0 = aaddr0 + 128 * RPAD * 2;

        #pragma unroll
        for (int step = 0; step < 2; step++) {
            const int kk = step * 16;
            uint32_t af[2][4];
            #pragma unroll
            for (int mi = 0; mi < 2; mi++) {
                int row = wm + mi * 16 + a_row_off;
                ldm_x4(af[mi], aaddr0 + (uint32_t)(row * RPAD + kk + a_k_off) * 2u);
            }
            uint32_t bfr[4][4];
            #pragma unroll
            for (int pr = 0; pr < 4; pr++) {
                int n = wn + pr * 16 + b_n_off;
                ldm_x4(bfr[pr], baddr0 + (uint32_t)(n * RPAD + kk + b_k_off) * 2u);
            }
            #pragma unroll
            for (int pr = 0; pr < 4; pr++) {
                mma_f16(acc[0][pr * 2 + 0], af[0], bfr[pr][0], bfr[pr][1]);
                mma_f16(acc[1][pr * 2 + 0], af[1], bfr[pr][0], bfr[pr][1]);
                mma_f16(acc[0][pr * 2 + 1], af[0], bfr[pr][2], bfr[pr][3]);
                mma_f16(acc[1][pr * 2 + 1], af[1], bfr[pr][2], bfr[pr][3]);
            }
        }
        if (++buf == 3) buf = 0;
    }

    if (COUT == 3) {
        // ---------- projection epilogue: stage tile, write g / pooled f / ht ----------
        __syncthreads();   // all warps done with pipeline smem
        __half* Ts = smh;  // [128][TS_LD]
        #pragma unroll
        for (int mi = 0; mi < 2; mi++)
            #pragma unroll
            for (int half_ = 0; half_ < 2; half_++) {
                const int row = wm + mi * 16 + half_ * 8 + grp;
                #pragma unroll
                for (int ni = 0; ni < 8; ni++) {
                    __half2 hv = __floats2half2_rn(acc[mi][ni][half_ * 2 + 0],
                                                   acc[mi][ni][half_ * 2 + 1]);
                    *(__half2*)(Ts + row * TS_LD + wn + ni * 8 + quad * 2) = hv;
                }
            }
        __syncthreads();

        const int b = blockIdx.y >> 5;
        const int p = blockIdx.y & 31;
        const int nx = blockIdx.x;

        if (nx == 0) {
            // g: cols [0,64) of all 128 rows
            {
                int lr = tid >> 1, c0 = (tid & 1) * 32;
                const uint4* src = (const uint4*)(Ts + lr * TS_LD + c0);
                uint4* dst = (uint4*)((__half*)Cv + (size_t)(rowBase + lr) * CE + c0);
                #pragma unroll
                for (int i = 0; i < 4; i++) dst[i] = src[i];
            }
            // f: pooled cols [64,128) -> f_out[b][p*32+q][e]
            {
                int q = tid >> 3, eg = tid & 7;
                const __half* r0 = Ts + (2 * q) * TS_LD + 64 + eg * 8;
                const __half* r1 = r0 + TS_LD;
                const __half* r2 = Ts + (64 + 2 * q) * TS_LD + 64 + eg * 8;
                const __half* r3 = r2 + TS_LD;
                __half2 o[4];
                #pragma unroll
                for (int i = 0; i < 4; i++) {
                    __half2 v0 = *(const __half2*)(r0 + i * 2);
                    __half2 v1 = *(const __half2*)(r1 + i * 2);
                    __half2 v2 = *(const __half2*)(r2 + i * 2);
                    __half2 v3 = *(const __half2*)(r3 + i * 2);
                    o[i] = __hmax2(__hmax2(v0, v1), __hmax2(v2, v3));
                }
                __half* dst = f_out + ((size_t)b * MP + p * 32 + q) * CE + eg * 8;
                *(uint2*)dst       = *(uint2*)&o[0];
                *(uint2*)(dst + 4) = *(uint2*)&o[2];
            }
        } else {
            // ht: pooled cols -> ht_out[b][d][key], d = (nx-1)*128 + local
            const int dg = (nx - 1) * 128;
            const int d  = tid >> 1;
            const int q0 = (tid & 1) * 16;
            __half vals[16];
            #pragma unroll
            for (int i = 0; i < 16; i++) {
                int q = q0 + i;
                __half v0 = Ts[(2 * q) * TS_LD + d];
                __half v1 = Ts[(2 * q + 1) * TS_LD + d];
                __half v2 = Ts[(64 + 2 * q) * TS_LD + d];
                __half v3 = Ts[(65 + 2 * q) * TS_LD + d];
                vals[i] = __hmax(__hmax(v0, v1), __hmax(v2, v3));
            }
            __half* dst = ht_out + ((size_t)b * CD + dg + d) * MP + p * 32 + q0;
            *(uint4*)dst       = *(uint4*)&vals[0];
            *(uint4*)(dst + 8) = *(uint4*)&vals[8];
        }
        return;
    }

    // ---------- standard epilogues ----------
    const float gval = (COUT == 2) ? gamma[0] : 0.0f;
    #pragma unroll
    for (int mi = 0; mi < 2; mi++) {
        #pragma unroll
        for (int half_ = 0; half_ < 2; half_++) {
            const int row = rowBase + wm + mi * 16 + half_ * 8 + grp;
            const int col0 = colBase + wn + quad * 2;
            if (COUT == 0) {
                __half* C = (__half*)Cv + (size_t)bz * strC + (size_t)row * ldc + col0;
                #pragma unroll
                for (int ni = 0; ni < 8; ni++) {
                    __half2 hv = __floats2half2_rn(acc[mi][ni][half_ * 2 + 0],
                                                   acc[mi][ni][half_ * 2 + 1]);
                    *(__half2*)(C + ni * 8) = hv;
                }
            } else {
                float* C = (float*)Cv + (size_t)bz * strC + (size_t)row * ldc + col0;
                #pragma unroll
                for (int ni = 0; ni < 8; ni++) {
                    float v0 = acc[mi][ni][half_ * 2 + 0];
                    float v1 = acc[mi][ni][half_ * 2 + 1];
                    if (COUT == 2) {
                        const float* rp = resid + (size_t)row * ldc + col0 + ni * 8;
                        float2 rv = *(const float2*)rp;
                        v0 = fmaf(gval, v0, rv.x);
                        v1 = fmaf(gval, v1, rv.y);
                    }
                    *(float2*)(C + ni * 8) = make_float2(v0, v1);
                }
            }
        }
    }
}

// ---------------------------------------------------------------------------
// x -> fp16 (8 floats per thread)
// ---------------------------------------------------------------------------
__global__ void xcvt(const float* __restrict__ x, __half* __restrict__ xh)
{
    size_t i = ((size_t)blockIdx.x * 256 + threadIdx.x) * 8;
    float4 v0 = *(const float4*)(x + i);
    float4 v1 = *(const float4*)(x + i + 4);
    __half2 h0 = __floats2half2_rn(v0.x, v0.y);
    __half2 h1 = __floats2half2_rn(v0.z, v0.w);
    __half2 h2 = __floats2half2_rn(v1.x, v1.y);
    __half2 h3 = __floats2half2_rn(v1.z, v1.w);
    uint4 u;
    u.x = *(uint32_t*)&h0; u.y = *(uint32_t*)&h1;
    u.z = *(uint32_t*)&h2; u.w = *(uint32_t*)&h3;
    *(uint4*)(xh + i) = u;
}

// ---------------------------------------------------------------------------
// weight prep (fp16): wcat[n][k], wot[n][k]
// ---------------------------------------------------------------------------
__global__ void prep_weights(const float* __restrict__ Wf, const float* __restrict__ Wg,
                             const float* __restrict__ Wh, const float* __restrict__ Wo,
                             __half* __restrict__ wcat, __half* __restrict__ wot)
{
    int idx = blockIdx.x * 256 + threadIdx.x;
    if (idx < NCAT * CCH) {
        int n = idx / CCH, k = idx % CCH;
        float v;
        if (n < 64)       v = Wg[(size_t)k * 64 + n];
        else if (n < 128) v = Wf[(size_t)k * 64 + (n - 64)];
        else              v = Wh[(size_t)k * 256 + (n - 128)];
        wcat[idx] = __float2half_rn(v);
    }
    if (idx < CCH * CD) {
        int n = idx / CD, k = idx % CD;
        wot[idx] = __float2half_rn(Wo[(size_t)k * CCH + n]);
    }
}

// ---------------------------------------------------------------------------
// softmax: fp16 logits in, fp16 weights out, IN PLACE. 1 block / row.
// ---------------------------------------------------------------------------
__global__ void softmax_kernel(__half* __restrict__ S)
{
    __shared__ float redmax[8];
    __shared__ float redsum[8];
    __half* r = S + (size_t)blockIdx.x * MP;
    int t = threadIdx.x;

    uint2 u = ((const uint2*)r)[t];
    __half2 a01 = *(__half2*)&u.x;
    __half2 a23 = *(__half2*)&u.y;
    float v0 = __low2float(a01), v1 = __high2float(a01);
    float v2 = __low2float(a23), v3 = __high2float(a23);

    float m = fmaxf(fmaxf(v0, v1), fmaxf(v2, v3));
    #pragma unroll
    for (int o = 16; o > 0; o >>= 1) m = fmaxf(m, __shfl_xor_sync(0xffffffffu, m, o));
    if ((t & 31) == 0) redmax[t >> 5] = m;
    __syncthreads();
    m = redmax[0];
    #pragma unroll
    for (int i = 1; i < 8; i++) m = fmaxf(m, redmax[i]);

    float e0 = __expf(v0 - m), e1 = __expf(v1 - m);
    float e2 = __expf(v2 - m), e3 = __expf(v3 - m);
    float s = e0 + e1 + e2 + e3;
    #pragma unroll
    for (int o = 16; o > 0; o >>= 1) s += __shfl_xor_sync(0xffffffffu, s, o);
    if ((t & 31) == 0) redsum[t >> 5] = s;
    __syncthreads();
    s = 0.0f;
    #pragma unroll
    for (int i = 0; i < 8; i++) s += redsum[i];

    float inv = 1.0f / s;
    __half2 h01 = __floats2half2_rn(e0 * inv, e1 * inv);
    __half2 h23 = __floats2half2_rn(e2 * inv, e3 * inv);
    uint2 o2;
    o2.x = *(uint32_t*)&h01;
    o2.y = *(uint32_t*)&h23;
    ((uint2*)r)[t] = o2;
}

// ---------------------------------------------------------------------------
// launch
// ---------------------------------------------------------------------------
extern "C" void kernel_launch(void* const* d_in, const int* in_sizes, int n_in,
                              void* d_out, int out_size)
{
    const float* x     = (const float*)d_in[0];
    const float* Wf    = (const float*)d_in[1];
    const float* Wg    = (const float*)d_in[2];
    const float* Wh    = (const float*)d_in[3];
    const float* Wo    = (const float*)d_in[4];
    const float* gamma = (const float*)d_in[5];
    float* out = (float*)d_out;

    __half *xh_p, *wcat_p, *wot_p, *g_p, *f_p, *ht_p, *s_p, *o_p;
    cudaGetSymbolAddress((void**)&xh_p,   xh_buf);
    cudaGetSymbolAddress((void**)&wcat_p, wcat_buf);
    cudaGetSymbolAddress((void**)&wot_p,  wot_buf);
    cudaGetSymbolAddress((void**)&g_p,    g_buf);
    cudaGetSymbolAddress((void**)&f_p,    f_buf);
    cudaGetSymbolAddress((void**)&ht_p,   ht_buf);
    cudaGetSymbolAddress((void**)&s_p,    s_buf);
    cudaGetSymbolAddress((void**)&o_p,    o_buf);

    cudaFuncSetAttribute(mma_gemm_h<0>, cudaFuncAttributeMaxDynamicSharedMemorySize, GEMM_SMEM);
    cudaFuncSetAttribute(mma_gemm_h<2>, cudaFuncAttributeMaxDynamicSharedMemorySize, GEMM_SMEM);
    cudaFuncSetAttribute(mma_gemm_h<3>, cudaFuncAttributeMaxDynamicSharedMemorySize, GEMM_SMEM);

    // x -> fp16 ; weights -> fp16
    xcvt<<<(BSZ * NP * CCH) / (256 * 8), 256>>>(x, xh_p);
    prep_weights<<<(NCAT * CCH + 255) / 256, 256>>>(Wf, Wg, Wh, Wo, wcat_p, wot_p);

    // fused projections + pools: g, f, ht directly (no gfh materialization)
    mma_gemm_h<3><<<dim3(3, 256, 1), 256, GEMM_SMEM>>>(
        xh_p, wcat_p, g_p, CCH, CCH, CCH, CE, 0, 0, 0, nullptr, nullptr, f_p, ht_p);

    // S[b] = G[b] @ F[b]^T  (M=4096, N=1024, K=64) -> fp16 logits
    mma_gemm_h<0><<<dim3(8, 32, BSZ), 256, GEMM_SMEM>>>(
        g_p, f_p, s_p, CE, CE, CE, MP,
        (long long)NP * CE, (long long)MP * CE, (long long)NP * MP,
        nullptr, nullptr, nullptr, nullptr);

    // softmax in place: S -> P (fp16)
    softmax_kernel<<<BSZ * NP, 256>>>(s_p);

    // O[b] = P[b] @ Ht[b]^T  (M=4096, N=256, K=1024)
    mma_gemm_h<0><<<dim3(2, 32, BSZ), 256, GEMM_SMEM>>>(
        s_p, ht_p, o_p, MP, MP, MP, CD,
        (long long)NP * MP, (long long)CD * MP, (long long)NP * CD,
        nullptr, nullptr, nullptr, nullptr);

    // out = gamma * (O @ Wo) + x   (M=32768, N=512, K=256)
    mma_gemm_h<2><<<dim3(4, 256, 1), 256, GEMM_SMEM>>>(
        o_p, wot_p, out, CD, CD, CD, CCH, 0, 0, 0, gamma, x, nullptr, nullptr);
}

// round 13
// speedup vs baseline: 2.7336x; 1.0714x over previous
#include <cuda_runtime.h>
#include <cuda_fp16.h>
#include <cstdint>

#define BSZ 8
#define NP  4096
#define MP  1024
#define CCH 512
#define CE  64
#define CD  256
#define NCAT 384

// ---------------- scratch ----------------
__device__ __half xh_buf  [(size_t)BSZ * NP * CCH];   // x as fp16
__device__ __half wcat_buf[NCAT * CCH];               // [n][k] = [Wg|Wf|Wh]^T
__device__ __half wot_buf [CCH * CD];                 // [n][k] = Wo^T
__device__ __half g_buf   [(size_t)BSZ * NP * CE];    // queries [B*4096][64]
__device__ __half f_buf   [BSZ * MP * CE];            // [b][key][e]
__device__ __half ht_buf  [BSZ * CD * MP];            // [b][d][key]
__device__ __half s_buf   [(size_t)BSZ * NP * MP];    // fp16 logits, then P in place
__device__ __half o_buf   [(size_t)BSZ * NP * CD];    // [b*4096][256]

// ---------------- helpers ----------------
__device__ __forceinline__ uint32_t smem_u32(const void* p) {
    uint32_t a;
    asm("{ .reg .u64 t; cvta.to.shared.u64 t, %1; cvt.u32.u64 %0, t; }" : "=r"(a) : "l"(p));
    return a;
}
__device__ __forceinline__ void cp_async16(uint32_t dst, const void* src) {
    asm volatile("cp.async.cg.shared.global [%0], [%1], 16;" :: "r"(dst), "l"(src));
}
__device__ __forceinline__ void cp_commit() {
    asm volatile("cp.async.commit_group;" ::: "memory");
}
template <int N>
__device__ __forceinline__ void cp_wait() {
    asm volatile("cp.async.wait_group %0;" :: "n"(N) : "memory");
}
__device__ __forceinline__ void ldm_x4(uint32_t r[4], uint32_t addr) {
    asm volatile("ldmatrix.sync.aligned.m8n8.x4.shared.b16 {%0,%1,%2,%3}, [%4];"
                 : "=r"(r[0]), "=r"(r[1]), "=r"(r[2]), "=r"(r[3]) : "r"(addr));
}
// fp16 mma, f32 accumulate
__device__ __forceinline__ void mma_f16(float c[4], const uint32_t a[4],
                                        uint32_t b0, uint32_t b1) {
    asm volatile(
        "mma.sync.aligned.m16n8k16.row.col.f32.f16.f16.f32 "
        "{%0,%1,%2,%3}, {%4,%5,%6,%7}, {%8,%9}, {%0,%1,%2,%3};"
        : "+f"(c[0]), "+f"(c[1]), "+f"(c[2]), "+f"(c[3])
        : "r"(a[0]), "r"(a[1]), "r"(a[2]), "r"(a[3]), "r"(b0), "r"(b1));
}

// ---------------------------------------------------------------------------
// 3-stage pipelined NT fp16 GEMM: C[M,N] = A[M,K] * B[N,K]^T, A/B fp16 K-major.
// CTA 128x128, K-chunk 32, cp.async triple buffer, ldmatrix fragment loads.
// COUT: 0 = fp16 C; 2 = fp32 C = gamma*acc + resid;
//       3 = projection epilogue: nx==0 -> write g cols[0:64) + pooled f,
//           nx 1,2 -> pooled+transposed ht.  (grid must be (3, 256, 1))
// Requires M%128==0, N%128==0, K%32==0, KB>=2.
// ---------------------------------------------------------------------------
#define RPAD    40
#define STAGE_H (2 * 128 * RPAD)            // halves per stage (A tile + B tile)
#define STAGE_B (STAGE_H * 2)               // bytes per stage
#define GEMM_SMEM (3 * STAGE_B)             // 61440 bytes
#define TS_LD 136

template <int COUT>
__global__ void __launch_bounds__(256, 2) mma_gemm_h(
    const __half* __restrict__ A, const __half* __restrict__ B, void* __restrict__ Cv,
    int K, int lda, int ldb, int ldc,
    long long strA, long long strB, long long strC,
    const float* __restrict__ gamma, const float* __restrict__ resid,
    __half* __restrict__ f_out, __half* __restrict__ ht_out)
{
    extern __shared__ __align__(16) __half smh[];
    const uint32_t sbase = smem_u32(smh);

    const int tid  = threadIdx.x;
    const int wid  = tid >> 5;
    const int lane = tid & 31;
    const int grp  = lane >> 2;
    const int quad = lane & 3;
    const int bz   = blockIdx.z;
    A += (size_t)bz * strA;
    B += (size_t)bz * strB;
    const int rowBase = blockIdx.y * 128;
    const int colBase = blockIdx.x * 128;
    const int wm = (wid >> 1) * 32;
    const int wn = (wid & 1) * 64;

    const int KB = K >> 5;

    auto prefetch = [&](int kb, int stage) {
        const uint32_t abase = sbase + (uint32_t)stage * STAGE_B;
        const uint32_t bbase = abase + 128 * RPAD * 2;
        const __half* Ag = A + (size_t)rowBase * lda + kb * 32;
        const __half* Bg = B + (size_t)colBase * ldb + kb * 32;
        #pragma unroll
        for (int i = 0; i < 2; i++) {
            int idx = tid + 256 * i;
            int r = idx >> 2, seg = idx & 3;
            cp_async16(abase + (uint32_t)(r * 80 + seg * 16), Ag + (size_t)r * lda + seg * 8);
        }
        #pragma unroll
        for (int i = 0; i < 2; i++) {
            int idx = tid + 256 * i;
            int r = idx >> 2, seg = idx & 3;
            cp_async16(bbase + (uint32_t)(r * 80 + seg * 16), Bg + (size_t)r * ldb + seg * 8);
        }
        cp_commit();
    };

    float acc[2][8][4] = {};

    prefetch(0, 0);
    if (KB > 1) prefetch(1, 1);

    // per-lane ldmatrix base offsets (in bytes, within a stage)
    const uint32_t a_base = (uint32_t)((wm + (lane & 15)) * RPAD + ((lane >> 4) << 3)) * 2u;
    const uint32_t b_base = (uint32_t)(128 * RPAD +
                            (wn + (lane & 7) + ((lane & 16) ? 8 : 0)) * RPAD + (lane & 8)) * 2u;

    int buf = 0;
    for (int kb = 0; kb < KB; kb++) {
        if (kb + 1 < KB) { cp_wait<1>(); } else { cp_wait<0>(); }
        __syncthreads();
        if (kb + 2 < KB) {
            int nb = buf + 2; if (nb >= 3) nb -= 3;
            prefetch(kb + 2, nb);
        }

        const uint32_t stage0 = sbase + (uint32_t)buf * STAGE_B;

        #pragma unroll
        for (int step = 0; step < 2; step++) {
            const uint32_t kko = (uint32_t)(step * 32);   // bytes
            uint32_t af[2][4];
            ldm_x4(af[0], stage0 + a_base + kko);
            ldm_x4(af[1], stage0 + a_base + kko + (uint32_t)(16 * RPAD * 2));
            #pragma unroll
            for (int pr = 0; pr < 4; pr++) {
                uint32_t bf[4];
                ldm_x4(bf, stage0 + b_base + kko + (uint32_t)(pr * 16 * RPAD * 2));
                mma_f16(acc[0][pr * 2 + 0], af[0], bf[0], bf[1]);
                mma_f16(acc[1][pr * 2 + 0], af[1], bf[0], bf[1]);
                mma_f16(acc[0][pr * 2 + 1], af[0], bf[2], bf[3]);
                mma_f16(acc[1][pr * 2 + 1], af[1], bf[2], bf[3]);
            }
        }
        if (++buf == 3) buf = 0;
    }

    if (COUT == 3) {
        // ---------- projection epilogue: stage tile, write g / pooled f / ht ----------
        __syncthreads();
        __half* Ts = smh;  // [128][TS_LD]
        #pragma unroll
        for (int mi = 0; mi < 2; mi++)
            #pragma unroll
            for (int half_ = 0; half_ < 2; half_++) {
                const int row = wm + mi * 16 + half_ * 8 + grp;
                #pragma unroll
                for (int ni = 0; ni < 8; ni++) {
                    __half2 hv = __floats2half2_rn(acc[mi][ni][half_ * 2 + 0],
                                                   acc[mi][ni][half_ * 2 + 1]);
                    *(__half2*)(Ts + row * TS_LD + wn + ni * 8 + quad * 2) = hv;
                }
            }
        __syncthreads();

        const int b = blockIdx.y >> 5;
        const int p = blockIdx.y & 31;
        const int nx = blockIdx.x;

        if (nx == 0) {
            {
                int lr = tid >> 1, c0 = (tid & 1) * 32;
                const uint4* src = (const uint4*)(Ts + lr * TS_LD + c0);
                uint4* dst = (uint4*)((__half*)Cv + (size_t)(rowBase + lr) * CE + c0);
                #pragma unroll
                for (int i = 0; i < 4; i++) dst[i] = src[i];
            }
            {
                int q = tid >> 3, eg = tid & 7;
                const __half* r0 = Ts + (2 * q) * TS_LD + 64 + eg * 8;
                const __half* r1 = r0 + TS_LD;
                const __half* r2 = Ts + (64 + 2 * q) * TS_LD + 64 + eg * 8;
                const __half* r3 = r2 + TS_LD;
                __half2 o[4];
                #pragma unroll
                for (int i = 0; i < 4; i++) {
                    __half2 v0 = *(const __half2*)(r0 + i * 2);
                    __half2 v1 = *(const __half2*)(r1 + i * 2);
                    __half2 v2 = *(const __half2*)(r2 + i * 2);
                    __half2 v3 = *(const __half2*)(r3 + i * 2);
                    o[i] = __hmax2(__hmax2(v0, v1), __hmax2(v2, v3));
                }
                __half* dst = f_out + ((size_t)b * MP + p * 32 + q) * CE + eg * 8;
                *(uint2*)dst       = *(uint2*)&o[0];
                *(uint2*)(dst + 4) = *(uint2*)&o[2];
            }
        } else {
            const int dg = (nx - 1) * 128;
            const int d  = tid >> 1;
            const int q0 = (tid & 1) * 16;
            __half vals[16];
            #pragma unroll
            for (int i = 0; i < 16; i++) {
                int q = q0 + i;
                __half v0 = Ts[(2 * q) * TS_LD + d];
                __half v1 = Ts[(2 * q + 1) * TS_LD + d];
                __half v2 = Ts[(64 + 2 * q) * TS_LD + d];
                __half v3 = Ts[(65 + 2 * q) * TS_LD + d];
                vals[i] = __hmax(__hmax(v0, v1), __hmax(v2, v3));
            }
            __half* dst = ht_out + ((size_t)b * CD + dg + d) * MP + p * 32 + q0;
            *(uint4*)dst       = *(uint4*)&vals[0];
            *(uint4*)(dst + 8) = *(uint4*)&vals[8];
        }
        return;
    }

    // ---------- standard epilogues ----------
    const float gval = (COUT == 2) ? gamma[0] : 0.0f;
    #pragma unroll
    for (int mi = 0; mi < 2; mi++) {
        #pragma unroll
        for (int half_ = 0; half_ < 2; half_++) {
            const int row = rowBase + wm + mi * 16 + half_ * 8 + grp;
            const int col0 = colBase + wn + quad * 2;
            if (COUT == 0) {
                __half* C = (__half*)Cv + (size_t)bz * strC + (size_t)row * ldc + col0;
                #pragma unroll
                for (int ni = 0; ni < 8; ni++) {
                    __half2 hv = __floats2half2_rn(acc[mi][ni][half_ * 2 + 0],
                                                   acc[mi][ni][half_ * 2 + 1]);
                    *(__half2*)(C + ni * 8) = hv;
                }
            } else {
                float* C = (float*)Cv + (size_t)bz * strC + (size_t)row * ldc + col0;
                #pragma unroll
                for (int ni = 0; ni < 8; ni++) {
                    float v0 = acc[mi][ni][half_ * 2 + 0];
                    float v1 = acc[mi][ni][half_ * 2 + 1];
                    const float* rp = resid + (size_t)row * ldc + col0 + ni * 8;
                    float2 rv = *(const float2*)rp;
                    v0 = fmaf(gval, v0, rv.x);
                    v1 = fmaf(gval, v1, rv.y);
                    *(float2*)(C + ni * 8) = make_float2(v0, v1);
                }
            }
        }
    }
}

// ---------------------------------------------------------------------------
// combined prep: x -> fp16 (8 floats/thread) + fp16 weight transpose/concat
// grid: BSZ*NP*CCH/(256*8) = 8192 blocks
// ---------------------------------------------------------------------------
__global__ void prep_all(const float* __restrict__ x,
                         const float* __restrict__ Wf, const float* __restrict__ Wg,
                         const float* __restrict__ Wh, const float* __restrict__ Wo,
                         __half* __restrict__ xh,
                         __half* __restrict__ wcat, __half* __restrict__ wot)
{
    const int t = blockIdx.x * 256 + threadIdx.x;
    {
        size_t i = (size_t)t * 8;
        float4 v0 = *(const float4*)(x + i);
        float4 v1 = *(const float4*)(x + i + 4);
        __half2 h0 = __floats2half2_rn(v0.x, v0.y);
        __half2 h1 = __floats2half2_rn(v0.z, v0.w);
        __half2 h2 = __floats2half2_rn(v1.x, v1.y);
        __half2 h3 = __floats2half2_rn(v1.z, v1.w);
        uint4 u;
        u.x = *(uint32_t*)&h0; u.y = *(uint32_t*)&h1;
        u.z = *(uint32_t*)&h2; u.w = *(uint32_t*)&h3;
        *(uint4*)(xh + i) = u;
    }
    if (t < NCAT * CCH) {
        int n = t / CCH, k = t % CCH;
        float v;
        if (n < 64)       v = Wg[(size_t)k * 64 + n];
        else if (n < 128) v = Wf[(size_t)k * 64 + (n - 64)];
        else              v = Wh[(size_t)k * 256 + (n - 128)];
        wcat[t] = __float2half_rn(v);
    }
    if (t < CCH * CD) {
        int n = t / CD, k = t % CD;
        wot[t] = __float2half_rn(Wo[(size_t)k * CCH + n]);
    }
}

// ---------------------------------------------------------------------------
// softmax: warp-per-row, in place, fp16. No block barriers.
// grid: BSZ*NP/8 blocks of 256 threads (8 warps = 8 rows).
// ---------------------------------------------------------------------------
__global__ void softmax_kernel(__half* __restrict__ S)
{
    const int lane = threadIdx.x & 31;
    const size_t row = (size_t)blockIdx.x * 8 + (threadIdx.x >> 5);
    uint4* r = (uint4*)(S + row * MP);

    uint4 u[4];
    #pragma unroll
    for (int j = 0; j < 4; j++) u[j] = r[lane + 32 * j];

    float v[32];
    #pragma unroll
    for (int j = 0; j < 4; j++) {
        const __half2* h = (const __half2*)&u[j];
        #pragma unroll
        for (int i = 0; i < 4; i++) {
            float2 f = __half22float2(h[i]);
            v[j * 8 + i * 2 + 0] = f.x;
            v[j * 8 + i * 2 + 1] = f.y;
        }
    }

    float m = v[0];
    #pragma unroll
    for (int i = 1; i < 32; i++) m = fmaxf(m, v[i]);
    #pragma unroll
    for (int o = 16; o > 0; o >>= 1) m = fmaxf(m, __shfl_xor_sync(0xffffffffu, m, o));

    float s = 0.0f;
    #pragma unroll
    for (int i = 0; i < 32; i++) { v[i] = __expf(v[i] - m); s += v[i]; }
    #pragma unroll
    for (int o = 16; o > 0; o >>= 1) s += __shfl_xor_sync(0xffffffffu, s, o);

    const float inv = 1.0f / s;
    #pragma unroll
    for (int j = 0; j < 4; j++) {
        __half2* h = (__half2*)&u[j];
        #pragma unroll
        for (int i = 0; i < 4; i++)
            h[i] = __floats2half2_rn(v[j * 8 + i * 2] * inv, v[j * 8 + i * 2 + 1] * inv);
        r[lane + 32 * j] = u[j];
    }
}

// ---------------------------------------------------------------------------
// launch
// ---------------------------------------------------------------------------
extern "C" void kernel_launch(void* const* d_in, const int* in_sizes, int n_in,
                              void* d_out, int out_size)
{
    const float* x     = (const float*)d_in[0];
    const float* Wf    = (const float*)d_in[1];
    const float* Wg    = (const float*)d_in[2];
    const float* Wh    = (const float*)d_in[3];
    const float* Wo    = (const float*)d_in[4];
    const float* gamma = (const float*)d_in[5];
    float* out = (float*)d_out;

    __half *xh_p, *wcat_p, *wot_p, *g_p, *f_p, *ht_p, *s_p, *o_p;
    cudaGetSymbolAddress((void**)&xh_p,   xh_buf);
    cudaGetSymbolAddress((void**)&wcat_p, wcat_buf);
    cudaGetSymbolAddress((void**)&wot_p,  wot_buf);
    cudaGetSymbolAddress((void**)&g_p,    g_buf);
    cudaGetSymbolAddress((void**)&f_p,    f_buf);
    cudaGetSymbolAddress((void**)&ht_p,   ht_buf);
    cudaGetSymbolAddress((void**)&s_p,    s_buf);
    cudaGetSymbolAddress((void**)&o_p,    o_buf);

    cudaFuncSetAttribute(mma_gemm_h<0>, cudaFuncAttributeMaxDynamicSharedMemorySize, GEMM_SMEM);
    cudaFuncSetAttribute(mma_gemm_h<2>, cudaFuncAttributeMaxDynamicSharedMemorySize, GEMM_SMEM);
    cudaFuncSetAttribute(mma_gemm_h<3>, cudaFuncAttributeMaxDynamicSharedMemorySize, GEMM_SMEM);

    // x -> fp16 ; weights -> fp16 (single kernel)
    prep_all<<<(BSZ * NP * CCH) / (256 * 8), 256>>>(x, Wf, Wg, Wh, Wo, xh_p, wcat_p, wot_p);

    // fused projections + pools: g, f, ht directly
    mma_gemm_h<3><<<dim3(3, 256, 1), 256, GEMM_SMEM>>>(
        xh_p, wcat_p, g_p, CCH, CCH, CCH, CE, 0, 0, 0, nullptr, nullptr, f_p, ht_p);

    // S[b] = G[b] @ F[b]^T  (M=4096, N=1024, K=64) -> fp16 logits
    mma_gemm_h<0><<<dim3(8, 32, BSZ), 256, GEMM_SMEM>>>(
        g_p, f_p, s_p, CE, CE, CE, MP,
        (long long)NP * CE, (long long)MP * CE, (long long)NP * MP,
        nullptr, nullptr, nullptr, nullptr);

    // softmax in place: S -> P (fp16), warp per row
    softmax_kernel<<<(BSZ * NP) / 8, 256>>>(s_p);

    // O[b] = P[b] @ Ht[b]^T  (M=4096, N=256, K=1024)
    mma_gemm_h<0><<<dim3(2, 32, BSZ), 256, GEMM_SMEM>>>(
        s_p, ht_p, o_p, MP, MP, MP, CD,
        (long long)NP * MP, (long long)CD * MP, (long long)NP * CD,
        nullptr, nullptr, nullptr, nullptr);

    // out = gamma * (O @ Wo) + x   (M=32768, N=512, K=256)
    mma_gemm_h<2><<<dim3(4, 256, 1), 256, GEMM_SMEM>>>(
        o_p, wot_p, out, CD, CD, CD, CCH, 0, 0, 0, gamma, x, nullptr, nullptr);
}

// round 14
// speedup vs baseline: 2.7680x; 1.0126x over previous
#include <cuda_runtime.h>
#include <cuda_fp16.h>
#include <cstdint>

#define BSZ 8
#define NP  4096
#define MP  1024
#define CCH 512
#define CE  64
#define CD  256
#define NCAT 384

// ---------------- scratch ----------------
__device__ __half xh_buf  [(size_t)BSZ * NP * CCH];   // x as fp16
__device__ __half wcat_buf[NCAT * CCH];               // [n][k] = [Wg|Wf|Wh]^T
__device__ __half wot_buf [CCH * CD];                 // [n][k] = Wo^T
__device__ __half g_buf   [(size_t)BSZ * NP * CE];    // queries [B*4096][64]
__device__ __half f_buf   [BSZ * MP * CE];            // [b][key][e]
__device__ __half ht_buf  [BSZ * CD * MP];            // [b][d][key]
__device__ __half s_buf   [(size_t)BSZ * NP * MP];    // fp16 logits, then P in place
__device__ __half o_buf   [(size_t)BSZ * NP * CD];    // [b*4096][256]

// ---------------- helpers ----------------
__device__ __forceinline__ uint32_t smem_u32(const void* p) {
    uint32_t a;
    asm("{ .reg .u64 t; cvta.to.shared.u64 t, %1; cvt.u32.u64 %0, t; }" : "=r"(a) : "l"(p));
    return a;
}
__device__ __forceinline__ void cp_async16(uint32_t dst, const void* src) {
    asm volatile("cp.async.cg.shared.global [%0], [%1], 16;" :: "r"(dst), "l"(src));
}
__device__ __forceinline__ void cp_commit() {
    asm volatile("cp.async.commit_group;" ::: "memory");
}
template <int N>
__device__ __forceinline__ void cp_wait() {
    asm volatile("cp.async.wait_group %0;" :: "n"(N) : "memory");
}
__device__ __forceinline__ void ldm_x4(uint32_t r[4], uint32_t addr) {
    asm volatile("ldmatrix.sync.aligned.m8n8.x4.shared.b16 {%0,%1,%2,%3}, [%4];"
                 : "=r"(r[0]), "=r"(r[1]), "=r"(r[2]), "=r"(r[3]) : "r"(addr));
}
// fp16 mma, f32 accumulate
__device__ __forceinline__ void mma_f16(float c[4], const uint32_t a[4],
                                        uint32_t b0, uint32_t b1) {
    asm volatile(
        "mma.sync.aligned.m16n8k16.row.col.f32.f16.f16.f32 "
        "{%0,%1,%2,%3}, {%4,%5,%6,%7}, {%8,%9}, {%0,%1,%2,%3};"
        : "+f"(c[0]), "+f"(c[1]), "+f"(c[2]), "+f"(c[3])
        : "r"(a[0]), "r"(a[1]), "r"(a[2]), "r"(a[3]), "r"(b0), "r"(b1));
}

// ---------------------------------------------------------------------------
// 3-stage pipelined NT fp16 GEMM: C[M,N] = A[M,K] * B[N,K]^T, A/B fp16 K-major.
// CTA 128x128, K-chunk 64, cp.async triple buffer, ldmatrix fragment loads.
// Rows padded to 72 halves (144B: 16B-aligned cp.async; 144 mod 128 = 16 so
// ldmatrix 8-row phases and cp.async stores are bank-conflict-free).
// COUT: 0 = fp16 C; 2 = fp32 C = gamma*acc + resid;
//       3 = projection epilogue: nx==0 -> write g cols[0:64) + pooled f,
//           nx 1,2 -> pooled+transposed ht.  (grid must be (3, 256, 1))
// Requires M%128==0, N%128==0, K%64==0.
// ---------------------------------------------------------------------------
#define RPAD    72
#define STAGE_H (2 * 128 * RPAD)            // halves per stage (A tile + B tile)
#define STAGE_B (STAGE_H * 2)               // 36864 bytes per stage
#define GEMM_SMEM (3 * STAGE_B)             // 110592 bytes
#define TS_LD 136

template <int COUT>
__global__ void __launch_bounds__(256, 2) mma_gemm_h(
    const __half* __restrict__ A, const __half* __restrict__ B, void* __restrict__ Cv,
    int K, int lda, int ldb, int ldc,
    long long strA, long long strB, long long strC,
    const float* __restrict__ gamma, const float* __restrict__ resid,
    __half* __restrict__ f_out, __half* __restrict__ ht_out)
{
    extern __shared__ __align__(16) __half smh[];
    const uint32_t sbase = smem_u32(smh);

    const int tid  = threadIdx.x;
    const int wid  = tid >> 5;
    const int lane = tid & 31;
    const int grp  = lane >> 2;
    const int quad = lane & 3;
    const int bz   = blockIdx.z;
    A += (size_t)bz * strA;
    B += (size_t)bz * strB;
    const int rowBase = blockIdx.y * 128;
    const int colBase = blockIdx.x * 128;
    const int wm = (wid >> 1) * 32;
    const int wn = (wid & 1) * 64;

    const int KB = K >> 6;

    auto prefetch = [&](int kb, int stage) {
        const uint32_t abase = sbase + (uint32_t)stage * STAGE_B;
        const uint32_t bbase = abase + 128 * RPAD * 2;
        const __half* Ag = A + (size_t)rowBase * lda + kb * 64;
        const __half* Bg = B + (size_t)colBase * ldb + kb * 64;
        #pragma unroll
        for (int i = 0; i < 4; i++) {
            int idx = tid + 256 * i;
            int r = idx >> 3, seg = idx & 7;
            cp_async16(abase + (uint32_t)(r * 144 + seg * 16), Ag + (size_t)r * lda + seg * 8);
        }
        #pragma unroll
        for (int i = 0; i < 4; i++) {
            int idx = tid + 256 * i;
            int r = idx >> 3, seg = idx & 7;
            cp_async16(bbase + (uint32_t)(r * 144 + seg * 16), Bg + (size_t)r * ldb + seg * 8);
        }
        cp_commit();
    };

    float acc[2][8][4] = {};

    prefetch(0, 0);
    if (KB > 1) prefetch(1, 1);

    // per-lane ldmatrix base offsets (bytes within a stage)
    const uint32_t a_base = (uint32_t)((wm + (lane & 15)) * RPAD + ((lane >> 4) << 3)) * 2u;
    const uint32_t b_base = (uint32_t)(128 * RPAD +
                            (wn + (lane & 7) + ((lane & 16) ? 8 : 0)) * RPAD + (lane & 8)) * 2u;

    int buf = 0;
    for (int kb = 0; kb < KB; kb++) {
        if (kb + 1 < KB) { cp_wait<1>(); } else { cp_wait<0>(); }
        __syncthreads();
        if (kb + 2 < KB) {
            int nb = buf + 2; if (nb >= 3) nb -= 3;
            prefetch(kb + 2, nb);
        }

        const uint32_t stage0 = sbase + (uint32_t)buf * STAGE_B;

        #pragma unroll
        for (int step = 0; step < 4; step++) {
            const uint32_t kko = (uint32_t)(step * 32);   // bytes (16 halves/step)
            uint32_t af[2][4];
            ldm_x4(af[0], stage0 + a_base + kko);
            ldm_x4(af[1], stage0 + a_base + kko + (uint32_t)(16 * RPAD * 2));
            #pragma unroll
            for (int pr = 0; pr < 4; pr++) {
                uint32_t bf[4];
                ldm_x4(bf, stage0 + b_base + kko + (uint32_t)(pr * 16 * RPAD * 2));
                mma_f16(acc[0][pr * 2 + 0], af[0], bf[0], bf[1]);
                mma_f16(acc[1][pr * 2 + 0], af[1], bf[0], bf[1]);
                mma_f16(acc[0][pr * 2 + 1], af[0], bf[2], bf[3]);
                mma_f16(acc[1][pr * 2 + 1], af[1], bf[2], bf[3]);
            }
        }
        if (++buf == 3) buf = 0;
    }

    if (COUT == 3) {
        // ---------- projection epilogue: stage tile, write g / pooled f / ht ----------
        __syncthreads();
        __half* Ts = smh;  // [128][TS_LD]
        #pragma unroll
        for (int mi = 0; mi < 2; mi++)
            #pragma unroll
            for (int half_ = 0; half_ < 2; half_++) {
                const int row = wm + mi * 16 + half_ * 8 + grp;
                #pragma unroll
                for (int ni = 0; ni < 8; ni++) {
                    __half2 hv = __floats2half2_rn(acc[mi][ni][half_ * 2 + 0],
                                                   acc[mi][ni][half_ * 2 + 1]);
                    *(__half2*)(Ts + row * TS_LD + wn + ni * 8 + quad * 2) = hv;
                }
            }
        __syncthreads();

        const int b = blockIdx.y >> 5;
        const int p = blockIdx.y & 31;
        const int nx = blockIdx.x;

        if (nx == 0) {
            {
                int lr = tid >> 1, c0 = (tid & 1) * 32;
                const uint4* src = (const uint4*)(Ts + lr * TS_LD + c0);
                uint4* dst = (uint4*)((__half*)Cv + (size_t)(rowBase + lr) * CE + c0);
                #pragma unroll
                for (int i = 0; i < 4; i++) dst[i] = src[i];
            }
            {
                int q = tid >> 3, eg = tid & 7;
                const __half* r0 = Ts + (2 * q) * TS_LD + 64 + eg * 8;
                const __half* r1 = r0 + TS_LD;
                const __half* r2 = Ts + (64 + 2 * q) * TS_LD + 64 + eg * 8;
                const __half* r3 = r2 + TS_LD;
                __half2 o[4];
                #pragma unroll
                for (int i = 0; i < 4; i++) {
                    __half2 v0 = *(const __half2*)(r0 + i * 2);
                    __half2 v1 = *(const __half2*)(r1 + i * 2);
                    __half2 v2 = *(const __half2*)(r2 + i * 2);
                    __half2 v3 = *(const __half2*)(r3 + i * 2);
                    o[i] = __hmax2(__hmax2(v0, v1), __hmax2(v2, v3));
                }
                __half* dst = f_out + ((size_t)b * MP + p * 32 + q) * CE + eg * 8;
                *(uint2*)dst       = *(uint2*)&o[0];
                *(uint2*)(dst + 4) = *(uint2*)&o[2];
            }
        } else {
            const int dg = (nx - 1) * 128;
            const int d  = tid >> 1;
            const int q0 = (tid & 1) * 16;
            __half vals[16];
            #pragma unroll
            for (int i = 0; i < 16; i++) {
                int q = q0 + i;
                __half v0 = Ts[(2 * q) * TS_LD + d];
                __half v1 = Ts[(2 * q + 1) * TS_LD + d];
                __half v2 = Ts[(64 + 2 * q) * TS_LD + d];
                __half v3 = Ts[(65 + 2 * q) * TS_LD + d];
                vals[i] = __hmax(__hmax(v0, v1), __hmax(v2, v3));
            }
            __half* dst = ht_out + ((size_t)b * CD + dg + d) * MP + p * 32 + q0;
            *(uint4*)dst       = *(uint4*)&vals[0];
            *(uint4*)(dst + 8) = *(uint4*)&vals[8];
        }
        return;
    }

    // ---------- standard epilogues ----------
    const float gval = (COUT == 2) ? gamma[0] : 0.0f;
    #pragma unroll
    for (int mi = 0; mi < 2; mi++) {
        #pragma unroll
        for (int half_ = 0; half_ < 2; half_++) {
            const int row = rowBase + wm + mi * 16 + half_ * 8 + grp;
            const int col0 = colBase + wn + quad * 2;
            if (COUT == 0) {
                __half* C = (__half*)Cv + (size_t)bz * strC + (size_t)row * ldc + col0;
                #pragma unroll
                for (int ni = 0; ni < 8; ni++) {
                    __half2 hv = __floats2half2_rn(acc[mi][ni][half_ * 2 + 0],
                                                   acc[mi][ni][half_ * 2 + 1]);
                    *(__half2*)(C + ni * 8) = hv;
                }
            } else {
                float* C = (float*)Cv + (size_t)bz * strC + (size_t)row * ldc + col0;
                #pragma unroll
                for (int ni = 0; ni < 8; ni++) {
                    float v0 = acc[mi][ni][half_ * 2 + 0];
                    float v1 = acc[mi][ni][half_ * 2 + 1];
                    const float* rp = resid + (size_t)row * ldc + col0 + ni * 8;
                    float2 rv = *(const float2*)rp;
                    v0 = fmaf(gval, v0, rv.x);
                    v1 = fmaf(gval, v1, rv.y);
                    *(float2*)(C + ni * 8) = make_float2(v0, v1);
                }
            }
        }
    }
}

// ---------------------------------------------------------------------------
// combined prep: x -> fp16 (8 floats/thread) + fp16 weight transpose/concat
// ---------------------------------------------------------------------------
__global__ void prep_all(const float* __restrict__ x,
                         const float* __restrict__ Wf, const float* __restrict__ Wg,
                         const float* __restrict__ Wh, const float* __restrict__ Wo,
                         __half* __restrict__ xh,
                         __half* __restrict__ wcat, __half* __restrict__ wot)
{
    const int t = blockIdx.x * 256 + threadIdx.x;
    {
        size_t i = (size_t)t * 8;
        float4 v0 = *(const float4*)(x + i);
        float4 v1 = *(const float4*)(x + i + 4);
        __half2 h0 = __floats2half2_rn(v0.x, v0.y);
        __half2 h1 = __floats2half2_rn(v0.z, v0.w);
        __half2 h2 = __floats2half2_rn(v1.x, v1.y);
        __half2 h3 = __floats2half2_rn(v1.z, v1.w);
        uint4 u;
        u.x = *(uint32_t*)&h0; u.y = *(uint32_t*)&h1;
        u.z = *(uint32_t*)&h2; u.w = *(uint32_t*)&h3;
        *(uint4*)(xh + i) = u;
    }
    if (t < NCAT * CCH) {
        int n = t / CCH, k = t % CCH;
        float v;
        if (n < 64)       v = Wg[(size_t)k * 64 + n];
        else if (n < 128) v = Wf[(size_t)k * 64 + (n - 64)];
        else              v = Wh[(size_t)k * 256 + (n - 128)];
        wcat[t] = __float2half_rn(v);
    }
    if (t < CCH * CD) {
        int n = t / CD, k = t % CD;
        wot[t] = __float2half_rn(Wo[(size_t)k * CCH + n]);
    }
}

// ---------------------------------------------------------------------------
// softmax: warp-per-row, in place, fp16. No block barriers.
// ---------------------------------------------------------------------------
__global__ void softmax_kernel(__half* __restrict__ S)
{
    const int lane = threadIdx.x & 31;
    const size_t row = (size_t)blockIdx.x * 8 + (threadIdx.x >> 5);
    uint4* r = (uint4*)(S + row * MP);

    uint4 u[4];
    #pragma unroll
    for (int j = 0; j < 4; j++) u[j] = r[lane + 32 * j];

    float v[32];
    #pragma unroll
    for (int j = 0; j < 4; j++) {
        const __half2* h = (const __half2*)&u[j];
        #pragma unroll
        for (int i = 0; i < 4; i++) {
            float2 f = __half22float2(h[i]);
            v[j * 8 + i * 2 + 0] = f.x;
            v[j * 8 + i * 2 + 1] = f.y;
        }
    }

    float m = v[0];
    #pragma unroll
    for (int i = 1; i < 32; i++) m = fmaxf(m, v[i]);
    #pragma unroll
    for (int o = 16; o > 0; o >>= 1) m = fmaxf(m, __shfl_xor_sync(0xffffffffu, m, o));

    float s = 0.0f;
    #pragma unroll
    for (int i = 0; i < 32; i++) { v[i] = __expf(v[i] - m); s += v[i]; }
    #pragma unroll
    for (int o = 16; o > 0; o >>= 1) s += __shfl_xor_sync(0xffffffffu, s, o);

    const float inv = 1.0f / s;
    #pragma unroll
    for (int j = 0; j < 4; j++) {
        __half2* h = (__half2*)&u[j];
        #pragma unroll
        for (int i = 0; i < 4; i++)
            h[i] = __floats2half2_rn(v[j * 8 + i * 2] * inv, v[j * 8 + i * 2 + 1] * inv);
        r[lane + 32 * j] = u[j];
    }
}

// ---------------------------------------------------------------------------
// launch
// ---------------------------------------------------------------------------
extern "C" void kernel_launch(void* const* d_in, const int* in_sizes, int n_in,
                              void* d_out, int out_size)
{
    const float* x     = (const float*)d_in[0];
    const float* Wf    = (const float*)d_in[1];
    const float* Wg    = (const float*)d_in[2];
    const float* Wh    = (const float*)d_in[3];
    const float* Wo    = (const float*)d_in[4];
    const float* gamma = (const float*)d_in[5];
    float* out = (float*)d_out;

    __half *xh_p, *wcat_p, *wot_p, *g_p, *f_p, *ht_p, *s_p, *o_p;
    cudaGetSymbolAddress((void**)&xh_p,   xh_buf);
    cudaGetSymbolAddress((void**)&wcat_p, wcat_buf);
    cudaGetSymbolAddress((void**)&wot_p,  wot_buf);
    cudaGetSymbolAddress((void**)&g_p,    g_buf);
    cudaGetSymbolAddress((void**)&f_p,    f_buf);
    cudaGetSymbolAddress((void**)&ht_p,   ht_buf);
    cudaGetSymbolAddress((void**)&s_p,    s_buf);
    cudaGetSymbolAddress((void**)&o_p,    o_buf);

    cudaFuncSetAttribute(mma_gemm_h<0>, cudaFuncAttributeMaxDynamicSharedMemorySize, GEMM_SMEM);
    cudaFuncSetAttribute(mma_gemm_h<2>, cudaFuncAttributeMaxDynamicSharedMemorySize, GEMM_SMEM);
    cudaFuncSetAttribute(mma_gemm_h<3>, cudaFuncAttributeMaxDynamicSharedMemorySize, GEMM_SMEM);

    // x -> fp16 ; weights -> fp16 (single kernel)
    prep_all<<<(BSZ * NP * CCH) / (256 * 8), 256>>>(x, Wf, Wg, Wh, Wo, xh_p, wcat_p, wot_p);

    // fused projections + pools: g, f, ht directly
    mma_gemm_h<3><<<dim3(3, 256, 1), 256, GEMM_SMEM>>>(
        xh_p, wcat_p, g_p, CCH, CCH, CCH, CE, 0, 0, 0, nullptr, nullptr, f_p, ht_p);

    // S[b] = G[b] @ F[b]^T  (M=4096, N=1024, K=64) -> fp16 logits
    mma_gemm_h<0><<<dim3(8, 32, BSZ), 256, GEMM_SMEM>>>(
        g_p, f_p, s_p, CE, CE, CE, MP,
        (long long)NP * CE, (long long)MP * CE, (long long)NP * MP,
        nullptr, nullptr, nullptr, nullptr);

    // softmax in place: S -> P (fp16), warp per row
    softmax_kernel<<<(BSZ * NP) / 8, 256>>>(s_p);

    // O[b] = P[b] @ Ht[b]^T  (M=4096, N=256, K=1024)
    mma_gemm_h<0><<<dim3(2, 32, BSZ), 256, GEMM_SMEM>>>(
        s_p, ht_p, o_p, MP, MP, MP, CD,
        (long long)NP * MP, (long long)CD * MP, (long long)NP * CD,
        nullptr, nullptr, nullptr, nullptr);

    // out = gamma * (O @ Wo) + x   (M=32768, N=512, K=256)
    mma_gemm_h<2><<<dim3(4, 256, 1), 256, GEMM_SMEM>>>(
        o_p, wot_p, out, CD, CD, CD, CCH, 0, 0, 0, gamma, x, nullptr, nullptr);
}

// round 15
// speedup vs baseline: 3.0601x; 1.1055x over previous
#include <cuda_runtime.h>
#include <cuda_fp16.h>
#include <cstdint>

#define BSZ 8
#define NP  4096
#define MP  1024
#define CCH 512
#define CE  64
#define CD  256
#define NCAT 384

// ---------------- scratch ----------------
__device__ __half xh_buf  [(size_t)BSZ * NP * CCH];   // x as fp16
__device__ __half wcat_buf[NCAT * CCH];               // [n][k] = [Wg|Wf|Wh]^T
__device__ __half wot_buf [CCH * CD];                 // [n][k] = Wo^T
__device__ __half g_buf   [(size_t)BSZ * NP * CE];    // queries [B*4096][64]
__device__ __half f_buf   [BSZ * MP * CE];            // [b][key][e]
__device__ __half ht_buf  [BSZ * CD * MP];            // [b][d][key]
__device__ __half o_buf   [(size_t)BSZ * NP * CD];    // [b*4096][256]

// ---------------- helpers ----------------
__device__ __forceinline__ uint32_t smem_u32(const void* p) {
    uint32_t a;
    asm("{ .reg .u64 t; cvta.to.shared.u64 t, %1; cvt.u32.u64 %0, t; }" : "=r"(a) : "l"(p));
    return a;
}
__device__ __forceinline__ void cp_async16(uint32_t dst, const void* src) {
    asm volatile("cp.async.cg.shared.global [%0], [%1], 16;" :: "r"(dst), "l"(src));
}
__device__ __forceinline__ void cp_commit() {
    asm volatile("cp.async.commit_group;" ::: "memory");
}
template <int N>
__device__ __forceinline__ void cp_wait() {
    asm volatile("cp.async.wait_group %0;" :: "n"(N) : "memory");
}
__device__ __forceinline__ void ldm_x4(uint32_t r[4], uint32_t addr) {
    asm volatile("ldmatrix.sync.aligned.m8n8.x4.shared.b16 {%0,%1,%2,%3}, [%4];"
                 : "=r"(r[0]), "=r"(r[1]), "=r"(r[2]), "=r"(r[3]) : "r"(addr));
}
// fp16 mma, f32 accumulate
__device__ __forceinline__ void mma_f16(float c[4], const uint32_t a[4],
                                        uint32_t b0, uint32_t b1) {
    asm volatile(
        "mma.sync.aligned.m16n8k16.row.col.f32.f16.f16.f32 "
        "{%0,%1,%2,%3}, {%4,%5,%6,%7}, {%8,%9}, {%0,%1,%2,%3};"
        : "+f"(c[0]), "+f"(c[1]), "+f"(c[2]), "+f"(c[3])
        : "r"(a[0]), "r"(a[1]), "r"(a[2]), "r"(a[3]), "r"(b0), "r"(b1));
}

// ---------------------------------------------------------------------------
// 3-stage pipelined NT fp16 GEMM (unchanged from R14).
// COUT: 2 = fp32 C = gamma*acc + resid;
//       3 = projection epilogue (g / pooled f / pooled+transposed ht).
// ---------------------------------------------------------------------------
#define RPAD    72
#define STAGE_H (2 * 128 * RPAD)
#define STAGE_B (STAGE_H * 2)
#define GEMM_SMEM (3 * STAGE_B)
#define TS_LD 136

template <int COUT>
__global__ void __launch_bounds__(256, 2) mma_gemm_h(
    const __half* __restrict__ A, const __half* __restrict__ B, void* __restrict__ Cv,
    int K, int lda, int ldb, int ldc,
    long long strA, long long strB, long long strC,
    const float* __restrict__ gamma, const float* __restrict__ resid,
    __half* __restrict__ f_out, __half* __restrict__ ht_out)
{
    extern __shared__ __align__(16) __half smh[];
    const uint32_t sbase = smem_u32(smh);

    const int tid  = threadIdx.x;
    const int wid  = tid >> 5;
    const int lane = tid & 31;
    const int grp  = lane >> 2;
    const int quad = lane & 3;
    const int bz   = blockIdx.z;
    A += (size_t)bz * strA;
    B += (size_t)bz * strB;
    const int rowBase = blockIdx.y * 128;
    const int colBase = blockIdx.x * 128;
    const int wm = (wid >> 1) * 32;
    const int wn = (wid & 1) * 64;

    const int KB = K >> 6;

    auto prefetch = [&](int kb, int stage) {
        const uint32_t abase = sbase + (uint32_t)stage * STAGE_B;
        const uint32_t bbase = abase + 128 * RPAD * 2;
        const __half* Ag = A + (size_t)rowBase * lda + kb * 64;
        const __half* Bg = B + (size_t)colBase * ldb + kb * 64;
        #pragma unroll
        for (int i = 0; i < 4; i++) {
            int idx = tid + 256 * i;
            int r = idx >> 3, seg = idx & 7;
            cp_async16(abase + (uint32_t)(r * 144 + seg * 16), Ag + (size_t)r * lda + seg * 8);
        }
        #pragma unroll
        for (int i = 0; i < 4; i++) {
            int idx = tid + 256 * i;
            int r = idx >> 3, seg = idx & 7;
            cp_async16(bbase + (uint32_t)(r * 144 + seg * 16), Bg + (size_t)r * ldb + seg * 8);
        }
        cp_commit();
    };

    float acc[2][8][4] = {};

    prefetch(0, 0);
    if (KB > 1) prefetch(1, 1);

    const uint32_t a_base = (uint32_t)((wm + (lane & 15)) * RPAD + ((lane >> 4) << 3)) * 2u;
    const uint32_t b_base = (uint32_t)(128 * RPAD +
                            (wn + (lane & 7) + ((lane & 16) ? 8 : 0)) * RPAD + (lane & 8)) * 2u;

    int buf = 0;
    for (int kb = 0; kb < KB; kb++) {
        if (kb + 1 < KB) { cp_wait<1>(); } else { cp_wait<0>(); }
        __syncthreads();
        if (kb + 2 < KB) {
            int nb = buf + 2; if (nb >= 3) nb -= 3;
            prefetch(kb + 2, nb);
        }

        const uint32_t stage0 = sbase + (uint32_t)buf * STAGE_B;

        #pragma unroll
        for (int step = 0; step < 4; step++) {
            const uint32_t kko = (uint32_t)(step * 32);
            uint32_t af[2][4];
            ldm_x4(af[0], stage0 + a_base + kko);
            ldm_x4(af[1], stage0 + a_base + kko + (uint32_t)(16 * RPAD * 2));
            #pragma unroll
            for (int pr = 0; pr < 4; pr++) {
                uint32_t bf[4];
                ldm_x4(bf, stage0 + b_base + kko + (uint32_t)(pr * 16 * RPAD * 2));
                mma_f16(acc[0][pr * 2 + 0], af[0], bf[0], bf[1]);
                mma_f16(acc[1][pr * 2 + 0], af[1], bf[0], bf[1]);
                mma_f16(acc[0][pr * 2 + 1], af[0], bf[2], bf[3]);
                mma_f16(acc[1][pr * 2 + 1], af[1], bf[2], bf[3]);
            }
        }
        if (++buf == 3) buf = 0;
    }

    if (COUT == 3) {
        __syncthreads();
        __half* Ts = smh;  // [128][TS_LD]
        #pragma unroll
        for (int mi = 0; mi < 2; mi++)
            #pragma unroll
            for (int half_ = 0; half_ < 2; half_++) {
                const int row = wm + mi * 16 + half_ * 8 + grp;
                #pragma unroll
                for (int ni = 0; ni < 8; ni++) {
                    __half2 hv = __floats2half2_rn(acc[mi][ni][half_ * 2 + 0],
                                                   acc[mi][ni][half_ * 2 + 1]);
                    *(__half2*)(Ts + row * TS_LD + wn + ni * 8 + quad * 2) = hv;
                }
            }
        __syncthreads();

        const int b = blockIdx.y >> 5;
        const int p = blockIdx.y & 31;
        const int nx = blockIdx.x;

        if (nx == 0) {
            {
                int lr = tid >> 1, c0 = (tid & 1) * 32;
                const uint4* src = (const uint4*)(Ts + lr * TS_LD + c0);
                uint4* dst = (uint4*)((__half*)Cv + (size_t)(rowBase + lr) * CE + c0);
                #pragma unroll
                for (int i = 0; i < 4; i++) dst[i] = src[i];
            }
            {
                int q = tid >> 3, eg = tid & 7;
                const __half* r0 = Ts + (2 * q) * TS_LD + 64 + eg * 8;
                const __half* r1 = r0 + TS_LD;
                const __half* r2 = Ts + (64 + 2 * q) * TS_LD + 64 + eg * 8;
                const __half* r3 = r2 + TS_LD;
                __half2 o[4];
                #pragma unroll
                for (int i = 0; i < 4; i++) {
                    __half2 v0 = *(const __half2*)(r0 + i * 2);
                    __half2 v1 = *(const __half2*)(r1 + i * 2);
                    __half2 v2 = *(const __half2*)(r2 + i * 2);
                    __half2 v3 = *(const __half2*)(r3 + i * 2);
                    o[i] = __hmax2(__hmax2(v0, v1), __hmax2(v2, v3));
                }
                __half* dst = f_out + ((size_t)b * MP + p * 32 + q) * CE + eg * 8;
                *(uint2*)dst       = *(uint2*)&o[0];
                *(uint2*)(dst + 4) = *(uint2*)&o[2];
            }
        } else {
            const int dg = (nx - 1) * 128;
            const int d  = tid >> 1;
            const int q0 = (tid & 1) * 16;
            __half vals[16];
            #pragma unroll
            for (int i = 0; i < 16; i++) {
                int q = q0 + i;
                __half v0 = Ts[(2 * q) * TS_LD + d];
                __half v1 = Ts[(2 * q + 1) * TS_LD + d];
                __half v2 = Ts[(64 + 2 * q) * TS_LD + d];
                __half v3 = Ts[(65 + 2 * q) * TS_LD + d];
                vals[i] = __hmax(__hmax(v0, v1), __hmax(v2, v3));
            }
            __half* dst = ht_out + ((size_t)b * CD + dg + d) * MP + p * 32 + q0;
            *(uint4*)dst       = *(uint4*)&vals[0];
            *(uint4*)(dst + 8) = *(uint4*)&vals[8];
        }
        return;
    }

    // COUT == 2: fp32 C = gamma*acc + resid
    const float gval = gamma[0];
    #pragma unroll
    for (int mi = 0; mi < 2; mi++) {
        #pragma unroll
        for (int half_ = 0; half_ < 2; half_++) {
            const int row = rowBase + wm + mi * 16 + half_ * 8 + grp;
            const int col0 = colBase + wn + quad * 2;
            float* C = (float*)Cv + (size_t)row * ldc + col0;
            const float* rp = resid + (size_t)row * ldc + col0;
            #pragma unroll
            for (int ni = 0; ni < 8; ni++) {
                float2 rv = *(const float2*)(rp + ni * 8);
                *(float2*)(C + ni * 8) = make_float2(
                    fmaf(gval, acc[mi][ni][half_ * 2 + 0], rv.x),
                    fmaf(gval, acc[mi][ni][half_ * 2 + 1], rv.y));
            }
        }
    }
}

// ---------------------------------------------------------------------------
// Flash attention: S = G@F^T, online softmax, O = P@Ht, fully fused.
// 512 threads (16 warps), CTA = 128 queries, 16 key-chunks of 64.
// Warps 0-7: S + softmax (each owns 16 complete rows -> warp-local stats).
// All 16 warps: PV (warp tile 32m x 64d). 2 syncthreads per chunk.
// smem: G[128x72] | P[128x72] | 3 stages of (F[64x72] + Ht[256x72]) | alpha,l
// ---------------------------------------------------------------------------
#define FRP 72
#define F_GS_OFF  0
#define F_P_OFF   (128 * FRP)                      // 9216 halves
#define F_ST_OFF  (F_P_OFF + 128 * FRP)            // 18432
#define F_STAGE_H ((64 + 256) * FRP)               // 23040 halves
#define F_HT_OFF  (64 * FRP)                       // Ht offset within stage
#define F_FLT_OFF (F_ST_OFF + 3 * F_STAGE_H)       // 87552 halves
#define FLASH_SMEM (F_FLT_OFF * 2 + 256 * 4)       // 176128 bytes

__global__ void __launch_bounds__(512) flash_attn(
    const __half* __restrict__ g, const __half* __restrict__ f,
    const __half* __restrict__ ht, __half* __restrict__ o)
{
    extern __shared__ __align__(16) __half smh[];
    const uint32_t sbase = smem_u32(smh);
    float* alpha_s = (float*)(smh + F_FLT_OFF);
    float* lrow_s  = alpha_s + 128;

    const int tid  = threadIdx.x;
    const int wid  = tid >> 5;
    const int lane = tid & 31;
    const int grp  = lane >> 2;
    const int quad = lane & 3;
    const int b    = blockIdx.y;
    const int mblk = blockIdx.x * 128;

    const __half* gq = g + ((size_t)b * NP + mblk) * CE;
    const __half* fb = f + (size_t)b * MP * CE;
    const __half* hb = ht + (size_t)b * CD * MP;

    // G prologue load: 128 rows x 8 segs (16B) -> 2 per thread, own group
    #pragma unroll
    for (int i = 0; i < 2; i++) {
        int idx = tid + 512 * i;
        int r = idx >> 3, seg = idx & 7;
        cp_async16(sbase + (uint32_t)(F_GS_OFF + r * FRP + seg * 8) * 2u,
                   gq + (size_t)r * CE + seg * 8);
    }
    cp_commit();

    auto prefetch = [&](int c, int stage) {
        const uint32_t st = sbase + (uint32_t)(F_ST_OFF + stage * F_STAGE_H) * 2u;
        {   // F chunk: 64 rows x 8 segs = 512 -> 1/thread
            int r = tid >> 3, seg = tid & 7;
            cp_async16(st + (uint32_t)(r * FRP + seg * 8) * 2u,
                       fb + (size_t)(c * 64 + r) * CE + seg * 8);
        }
        // Ht chunk: 256 d-rows x 8 segs = 2048 -> 4/thread
        #pragma unroll
        for (int i = 0; i < 4; i++) {
            int idx = tid + 512 * i;
            int d = idx >> 3, seg = idx & 7;
            cp_async16(st + (uint32_t)(F_HT_OFF + d * FRP + seg * 8) * 2u,
                       hb + (size_t)d * MP + c * 64 + seg * 8);
        }
        cp_commit();
    };

    prefetch(0, 0);
    prefetch(1, 1);

    float accO[2][8][4] = {};
    float mstA = -1e30f, mstB = -1e30f, lstA = 0.0f, lstB = 0.0f;

    const int a15 = lane & 15;
    const int ahi = (lane >> 4) << 3;
    const int bn  = (lane & 7) + ((lane & 16) ? 8 : 0);
    const int bk  = lane & 8;
    const int pwm = (wid >> 2) * 32;   // PV warp row base (4 groups)
    const int pwn = (wid & 3) * 64;    // PV warp col base (4 groups)
    const int swm = wid * 16;          // S warp row base (wid < 8)

    int buf = 0;
    for (int c = 0; c < 16; c++) {
        if (c + 1 < 16) { cp_wait<1>(); } else { cp_wait<0>(); }
        __syncthreads();                          // stage c ready; P free
        if (c + 2 < 16) {
            int nb = buf + 2; if (nb >= 3) nb -= 3;
            prefetch(c + 2, nb);
        }
        const uint32_t st = sbase + (uint32_t)(F_ST_OFF + buf * F_STAGE_H) * 2u;

        if (wid < 8) {
            // ---- S = G @ F^T (rows [swm, swm+16) x 64 keys) ----
            float accS[8][4] = {};
            const uint32_t ga = sbase + (uint32_t)(F_GS_OFF + (swm + a15) * FRP + ahi) * 2u;
            const uint32_t fa = st + (uint32_t)(bn * FRP + bk) * 2u;
            #pragma unroll
            for (int ks = 0; ks < 4; ks++) {
                uint32_t af[4];
                ldm_x4(af, ga + ks * 32);
                #pragma unroll
                for (int nt = 0; nt < 4; nt++) {
                    uint32_t bf[4];
                    ldm_x4(bf, fa + ks * 32 + (uint32_t)(nt * 16 * FRP * 2));
                    mma_f16(accS[nt * 2 + 0], af, bf[0], bf[1]);
                    mma_f16(accS[nt * 2 + 1], af, bf[2], bf[3]);
                }
            }
            // ---- warp-local row stats (rows grp, grp+8) ----
            float mA = -1e30f, mB = -1e30f;
            #pragma unroll
            for (int t = 0; t < 8; t++) {
                mA = fmaxf(mA, fmaxf(accS[t][0], accS[t][1]));
                mB = fmaxf(mB, fmaxf(accS[t][2], accS[t][3]));
            }
            mA = fmaxf(mA, __shfl_xor_sync(0xffffffffu, mA, 1));
            mA = fmaxf(mA, __shfl_xor_sync(0xffffffffu, mA, 2));
            mB = fmaxf(mB, __shfl_xor_sync(0xffffffffu, mB, 1));
            mB = fmaxf(mB, __shfl_xor_sync(0xffffffffu, mB, 2));
            float mnA = fmaxf(mstA, mA), mnB = fmaxf(mstB, mB);
            float aA = __expf(mstA - mnA), aB = __expf(mstB - mnB);
            mstA = mnA; mstB = mnB;
            float sA = 0.0f, sB = 0.0f;
            #pragma unroll
            for (int t = 0; t < 8; t++) {
                float p0 = __expf(accS[t][0] - mnA);
                float p1 = __expf(accS[t][1] - mnA);
                float p2 = __expf(accS[t][2] - mnB);
                float p3 = __expf(accS[t][3] - mnB);
                sA += p0 + p1; sB += p2 + p3;
                *(__half2*)(smh + F_P_OFF + (swm + grp) * FRP + t * 8 + quad * 2)
                    = __floats2half2_rn(p0, p1);
                *(__half2*)(smh + F_P_OFF + (swm + 8 + grp) * FRP + t * 8 + quad * 2)
                    = __floats2half2_rn(p2, p3);
            }
            sA += __shfl_xor_sync(0xffffffffu, sA, 1);
            sA += __shfl_xor_sync(0xffffffffu, sA, 2);
            sB += __shfl_xor_sync(0xffffffffu, sB, 1);
            sB += __shfl_xor_sync(0xffffffffu, sB, 2);
            lstA = lstA * aA + sA;
            lstB = lstB * aB + sB;
            if (quad == 0) {
                alpha_s[swm + grp]     = aA;
                alpha_s[swm + 8 + grp] = aB;
            }
        }
        __syncthreads();                          // P + alpha ready

        // ---- rescale accO by alpha ----
        {
            float a0 = alpha_s[pwm + grp],      a1 = alpha_s[pwm + 8 + grp];
            float a2 = alpha_s[pwm + 16 + grp], a3 = alpha_s[pwm + 24 + grp];
            #pragma unroll
            for (int nt = 0; nt < 8; nt++) {
                accO[0][nt][0] *= a0; accO[0][nt][1] *= a0;
                accO[0][nt][2] *= a1; accO[0][nt][3] *= a1;
                accO[1][nt][0] *= a2; accO[1][nt][1] *= a2;
                accO[1][nt][2] *= a3; accO[1][nt][3] *= a3;
            }
        }
        // ---- O += P @ Ht (warp tile 32m x 64d) ----
        {
            const uint32_t pa = sbase + (uint32_t)(F_P_OFF + (pwm + a15) * FRP + ahi) * 2u;
            const uint32_t ha = st + (uint32_t)(F_HT_OFF + (pwn + bn) * FRP + bk) * 2u;
            #pragma unroll
            for (int ks = 0; ks < 4; ks++) {
                uint32_t af0[4], af1[4];
                ldm_x4(af0, pa + ks * 32);
                ldm_x4(af1, pa + ks * 32 + (uint32_t)(16 * FRP * 2));
                #pragma unroll
                for (int nt = 0; nt < 4; nt++) {
                    uint32_t bf[4];
                    ldm_x4(bf, ha + ks * 32 + (uint32_t)(nt * 16 * FRP * 2));
                    mma_f16(accO[0][nt * 2 + 0], af0, bf[0], bf[1]);
                    mma_f16(accO[1][nt * 2 + 0], af1, bf[0], bf[1]);
                    mma_f16(accO[0][nt * 2 + 1], af0, bf[2], bf[3]);
                    mma_f16(accO[1][nt * 2 + 1], af1, bf[2], bf[3]);
                }
            }
        }
        if (++buf == 3) buf = 0;
    }

    // publish row sums
    if (wid < 8 && quad == 0) {
        lrow_s[swm + grp]     = lstA;
        lrow_s[swm + 8 + grp] = lstB;
    }
    __syncthreads();

    // epilogue: O /= l, fp16 out
    __half* ob = o + ((size_t)b * NP + mblk) * CD;
    #pragma unroll
    for (int mi = 0; mi < 2; mi++) {
        #pragma unroll
        for (int hf = 0; hf < 2; hf++) {
            const int row = pwm + mi * 16 + hf * 8 + grp;
            const float inv = 1.0f / lrow_s[row];
            __half* cp = ob + (size_t)row * CD + pwn + quad * 2;
            #pragma unroll
            for (int nt = 0; nt < 8; nt++)
                *(__half2*)(cp + nt * 8) = __floats2half2_rn(
                    accO[mi][nt][hf * 2 + 0] * inv, accO[mi][nt][hf * 2 + 1] * inv);
        }
    }
}

// ---------------------------------------------------------------------------
// combined prep: x -> fp16 + fp16 weight transpose/concat
// ---------------------------------------------------------------------------
__global__ void prep_all(const float* __restrict__ x,
                         const float* __restrict__ Wf, const float* __restrict__ Wg,
                         const float* __restrict__ Wh, const float* __restrict__ Wo,
                         __half* __restrict__ xh,
                         __half* __restrict__ wcat, __half* __restrict__ wot)
{
    const int t = blockIdx.x * 256 + threadIdx.x;
    {
        size_t i = (size_t)t * 8;
        float4 v0 = *(const float4*)(x + i);
        float4 v1 = *(const float4*)(x + i + 4);
        __half2 h0 = __floats2half2_rn(v0.x, v0.y);
        __half2 h1 = __floats2half2_rn(v0.z, v0.w);
        __half2 h2 = __floats2half2_rn(v1.x, v1.y);
        __half2 h3 = __floats2half2_rn(v1.z, v1.w);
        uint4 u;
        u.x = *(uint32_t*)&h0; u.y = *(uint32_t*)&h1;
        u.z = *(uint32_t*)&h2; u.w = *(uint32_t*)&h3;
        *(uint4*)(xh + i) = u;
    }
    if (t < NCAT * CCH) {
        int n = t / CCH, k = t % CCH;
        float v;
        if (n < 64)       v = Wg[(size_t)k * 64 + n];
        else if (n < 128) v = Wf[(size_t)k * 64 + (n - 64)];
        else              v = Wh[(size_t)k * 256 + (n - 128)];
        wcat[t] = __float2half_rn(v);
    }
    if (t < CCH * CD) {
        int n = t / CD, k = t % CD;
        wot[t] = __float2half_rn(Wo[(size_t)k * CCH + n]);
    }
}

// ---------------------------------------------------------------------------
// launch
// ---------------------------------------------------------------------------
extern "C" void kernel_launch(void* const* d_in, const int* in_sizes, int n_in,
                              void* d_out, int out_size)
{
    const float* x     = (const float*)d_in[0];
    const float* Wf    = (const float*)d_in[1];
    const float* Wg    = (const float*)d_in[2];
    const float* Wh    = (const float*)d_in[3];
    const float* Wo    = (const float*)d_in[4];
    const float* gamma = (const float*)d_in[5];
    float* out = (float*)d_out;

    __half *xh_p, *wcat_p, *wot_p, *g_p, *f_p, *ht_p, *o_p;
    cudaGetSymbolAddress((void**)&xh_p,   xh_buf);
    cudaGetSymbolAddress((void**)&wcat_p, wcat_buf);
    cudaGetSymbolAddress((void**)&wot_p,  wot_buf);
    cudaGetSymbolAddress((void**)&g_p,    g_buf);
    cudaGetSymbolAddress((void**)&f_p,    f_buf);
    cudaGetSymbolAddress((void**)&ht_p,   ht_buf);
    cudaGetSymbolAddress((void**)&o_p,    o_buf);

    cudaFuncSetAttribute(mma_gemm_h<2>, cudaFuncAttributeMaxDynamicSharedMemorySize, GEMM_SMEM);
    cudaFuncSetAttribute(mma_gemm_h<3>, cudaFuncAttributeMaxDynamicSharedMemorySize, GEMM_SMEM);
    cudaFuncSetAttribute(flash_attn,    cudaFuncAttributeMaxDynamicSharedMemorySize, FLASH_SMEM);

    // x -> fp16 ; weights -> fp16
    prep_all<<<(BSZ * NP * CCH) / (256 * 8), 256>>>(x, Wf, Wg, Wh, Wo, xh_p, wcat_p, wot_p);

    // fused projections + pools: g, f, ht directly
    mma_gemm_h<3><<<dim3(3, 256, 1), 256, GEMM_SMEM>>>(
        xh_p, wcat_p, g_p, CCH, CCH, CCH, CE, 0, 0, 0, nullptr, nullptr, f_p, ht_p);

    // fused S + softmax + PV (S never touches DRAM)
    flash_attn<<<dim3(32, BSZ), 512, FLASH_SMEM>>>(g_p, f_p, ht_p, o_p);

    // out = gamma * (O @ Wo) + x   (M=32768, N=512, K=256)
    mma_gemm_h<2><<<dim3(4, 256, 1), 256, GEMM_SMEM>>>(
        o_p, wot_p, out, CD, CD, CD, CCH, 0, 0, 0, gamma, x, nullptr, nullptr);
}

// round 16
// speedup vs baseline: 3.0959x; 1.0117x over previous
#include <cuda_runtime.h>
#include <cuda_fp16.h>
#include <cstdint>

#define BSZ 8
#define NP  4096
#define MP  1024
#define CCH 512
#define CE  64
#define CD  256
#define NCAT 384

// ---------------- scratch ----------------
__device__ __half xh_buf  [(size_t)BSZ * NP * CCH];   // x as fp16
__device__ __half wcat_buf[NCAT * CCH];               // [n][k] = [Wg|Wf|Wh]^T
__device__ __half wot_buf [CCH * CD];                 // [n][k] = Wo^T
__device__ __half g_buf   [(size_t)BSZ * NP * CE];    // queries [B*4096][64]
__device__ __half f_buf   [BSZ * MP * CE];            // [b][key][e]
__device__ __half ht_buf  [BSZ * CD * MP];            // [b][d][key]
__device__ __half o_buf   [(size_t)BSZ * NP * CD];    // [b*4096][256]

// ---------------- helpers ----------------
__device__ __forceinline__ uint32_t smem_u32(const void* p) {
    uint32_t a;
    asm("{ .reg .u64 t; cvta.to.shared.u64 t, %1; cvt.u32.u64 %0, t; }" : "=r"(a) : "l"(p));
    return a;
}
__device__ __forceinline__ void cp_async16(uint32_t dst, const void* src) {
    asm volatile("cp.async.cg.shared.global [%0], [%1], 16;" :: "r"(dst), "l"(src));
}
__device__ __forceinline__ void cp_commit() {
    asm volatile("cp.async.commit_group;" ::: "memory");
}
template <int N>
__device__ __forceinline__ void cp_wait() {
    asm volatile("cp.async.wait_group %0;" :: "n"(N) : "memory");
}
__device__ __forceinline__ void l2_prefetch(const void* p) {
    asm volatile("prefetch.global.L2 [%0];" :: "l"(p));
}
__device__ __forceinline__ void ldm_x4(uint32_t r[4], uint32_t addr) {
    asm volatile("ldmatrix.sync.aligned.m8n8.x4.shared.b16 {%0,%1,%2,%3}, [%4];"
                 : "=r"(r[0]), "=r"(r[1]), "=r"(r[2]), "=r"(r[3]) : "r"(addr));
}
// fp16 mma, f32 accumulate
__device__ __forceinline__ void mma_f16(float c[4], const uint32_t a[4],
                                        uint32_t b0, uint32_t b1) {
    asm volatile(
        "mma.sync.aligned.m16n8k16.row.col.f32.f16.f16.f32 "
        "{%0,%1,%2,%3}, {%4,%5,%6,%7}, {%8,%9}, {%0,%1,%2,%3};"
        : "+f"(c[0]), "+f"(c[1]), "+f"(c[2]), "+f"(c[3])
        : "r"(a[0]), "r"(a[1]), "r"(a[2]), "r"(a[3]), "r"(b0), "r"(b1));
}

// ---------------------------------------------------------------------------
// 3-stage pipelined NT fp16 GEMM.
// COUT: 2 = fp32 C = gamma*acc + resid (smem-staged float4 epilogue);
//       3 = projection epilogue (g / pooled f / pooled+transposed ht).
// ---------------------------------------------------------------------------
#define RPAD    72
#define STAGE_H (2 * 128 * RPAD)
#define STAGE_B (STAGE_H * 2)
#define GEMM_SMEM (3 * STAGE_B)      // 110592 B (>= 128*132*4 = 67584 for epilogue)
#define TS_LD 136
#define TF_LD 132

template <int COUT>
__global__ void __launch_bounds__(256, 2) mma_gemm_h(
    const __half* __restrict__ A, const __half* __restrict__ B, void* __restrict__ Cv,
    int K, int lda, int ldb, int ldc,
    long long strA, long long strB, long long strC,
    const float* __restrict__ gamma, const float* __restrict__ resid,
    __half* __restrict__ f_out, __half* __restrict__ ht_out)
{
    extern __shared__ __align__(16) __half smh[];
    const uint32_t sbase = smem_u32(smh);

    const int tid  = threadIdx.x;
    const int wid  = tid >> 5;
    const int lane = tid & 31;
    const int grp  = lane >> 2;
    const int quad = lane & 3;
    const int bz   = blockIdx.z;
    A += (size_t)bz * strA;
    B += (size_t)bz * strB;
    const int rowBase = blockIdx.y * 128;
    const int colBase = blockIdx.x * 128;
    const int wm = (wid >> 1) * 32;
    const int wn = (wid & 1) * 64;

    const int KB = K >> 6;

    auto prefetch = [&](int kb, int stage) {
        const uint32_t abase = sbase + (uint32_t)stage * STAGE_B;
        const uint32_t bbase = abase + 128 * RPAD * 2;
        const __half* Ag = A + (size_t)rowBase * lda + kb * 64;
        const __half* Bg = B + (size_t)colBase * ldb + kb * 64;
        #pragma unroll
        for (int i = 0; i < 4; i++) {
            int idx = tid + 256 * i;
            int r = idx >> 3, seg = idx & 7;
            cp_async16(abase + (uint32_t)(r * 144 + seg * 16), Ag + (size_t)r * lda + seg * 8);
        }
        #pragma unroll
        for (int i = 0; i < 4; i++) {
            int idx = tid + 256 * i;
            int r = idx >> 3, seg = idx & 7;
            cp_async16(bbase + (uint32_t)(r * 144 + seg * 16), Bg + (size_t)r * ldb + seg * 8);
        }
        cp_commit();
    };

    float acc[2][8][4] = {};

    prefetch(0, 0);
    if (KB > 1) prefetch(1, 1);

    if (COUT == 2) {
        // warm L2 with the resid tile (512 lines of 128B, 2 per thread)
        #pragma unroll
        for (int i = 0; i < 2; i++) {
            int idx = tid + 256 * i;
            int r = idx >> 2, seg = (idx & 3) * 32;
            l2_prefetch(resid + (size_t)(rowBase + r) * ldc + colBase + seg);
        }
    }

    const uint32_t a_base = (uint32_t)((wm + (lane & 15)) * RPAD + ((lane >> 4) << 3)) * 2u;
    const uint32_t b_base = (uint32_t)(128 * RPAD +
                            (wn + (lane & 7) + ((lane & 16) ? 8 : 0)) * RPAD + (lane & 8)) * 2u;

    int buf = 0;
    for (int kb = 0; kb < KB; kb++) {
        if (kb + 1 < KB) { cp_wait<1>(); } else { cp_wait<0>(); }
        __syncthreads();
        if (kb + 2 < KB) {
            int nb = buf + 2; if (nb >= 3) nb -= 3;
            prefetch(kb + 2, nb);
        }

        const uint32_t stage0 = sbase + (uint32_t)buf * STAGE_B;

        #pragma unroll
        for (int step = 0; step < 4; step++) {
            const uint32_t kko = (uint32_t)(step * 32);
            uint32_t af[2][4];
            ldm_x4(af[0], stage0 + a_base + kko);
            ldm_x4(af[1], stage0 + a_base + kko + (uint32_t)(16 * RPAD * 2));
            #pragma unroll
            for (int pr = 0; pr < 4; pr++) {
                uint32_t bf[4];
                ldm_x4(bf, stage0 + b_base + kko + (uint32_t)(pr * 16 * RPAD * 2));
                mma_f16(acc[0][pr * 2 + 0], af[0], bf[0], bf[1]);
                mma_f16(acc[1][pr * 2 + 0], af[1], bf[0], bf[1]);
                mma_f16(acc[0][pr * 2 + 1], af[0], bf[2], bf[3]);
                mma_f16(acc[1][pr * 2 + 1], af[1], bf[2], bf[3]);
            }
        }
        if (++buf == 3) buf = 0;
    }

    if (COUT == 3) {
        __syncthreads();
        __half* Ts = smh;  // [128][TS_LD]
        #pragma unroll
        for (int mi = 0; mi < 2; mi++)
            #pragma unroll
            for (int half_ = 0; half_ < 2; half_++) {
                const int row = wm + mi * 16 + half_ * 8 + grp;
                #pragma unroll
                for (int ni = 0; ni < 8; ni++) {
                    __half2 hv = __floats2half2_rn(acc[mi][ni][half_ * 2 + 0],
                                                   acc[mi][ni][half_ * 2 + 1]);
                    *(__half2*)(Ts + row * TS_LD + wn + ni * 8 + quad * 2) = hv;
                }
            }
        __syncthreads();

        const int b = blockIdx.y >> 5;
        const int p = blockIdx.y & 31;
        const int nx = blockIdx.x;

        if (nx == 0) {
            {
                int lr = tid >> 1, c0 = (tid & 1) * 32;
                const uint4* src = (const uint4*)(Ts + lr * TS_LD + c0);
                uint4* dst = (uint4*)((__half*)Cv + (size_t)(rowBase + lr) * CE + c0);
                #pragma unroll
                for (int i = 0; i < 4; i++) dst[i] = src[i];
            }
            {
                int q = tid >> 3, eg = tid & 7;
                const __half* r0 = Ts + (2 * q) * TS_LD + 64 + eg * 8;
                const __half* r1 = r0 + TS_LD;
                const __half* r2 = Ts + (64 + 2 * q) * TS_LD + 64 + eg * 8;
                const __half* r3 = r2 + TS_LD;
                __half2 o[4];
                #pragma unroll
                for (int i = 0; i < 4; i++) {
                    __half2 v0 = *(const __half2*)(r0 + i * 2);
                    __half2 v1 = *(const __half2*)(r1 + i * 2);
                    __half2 v2 = *(const __half2*)(r2 + i * 2);
                    __half2 v3 = *(const __half2*)(r3 + i * 2);
                    o[i] = __hmax2(__hmax2(v0, v1), __hmax2(v2, v3));
                }
                __half* dst = f_out + ((size_t)b * MP + p * 32 + q) * CE + eg * 8;
                *(uint2*)dst       = *(uint2*)&o[0];
                *(uint2*)(dst + 4) = *(uint2*)&o[2];
            }
        } else {
            const int dg = (nx - 1) * 128;
            const int d  = tid >> 1;
            const int q0 = (tid & 1) * 16;
            __half vals[16];
            #pragma unroll
            for (int i = 0; i < 16; i++) {
                int q = q0 + i;
                __half v0 = Ts[(2 * q) * TS_LD + d];
                __half v1 = Ts[(2 * q + 1) * TS_LD + d];
                __half v2 = Ts[(64 + 2 * q) * TS_LD + d];
                __half v3 = Ts[(65 + 2 * q) * TS_LD + d];
                vals[i] = __hmax(__hmax(v0, v1), __hmax(v2, v3));
            }
            __half* dst = ht_out + ((size_t)b * CD + dg + d) * MP + p * 32 + q0;
            *(uint4*)dst       = *(uint4*)&vals[0];
            *(uint4*)(dst + 8) = *(uint4*)&vals[8];
        }
        return;
    }

    // ---------- COUT == 2: smem-staged fp32 epilogue, float4 traffic ----------
    {
        __syncthreads();                       // all warps done reading stages
        float* Tf = (float*)smh;               // [128][TF_LD]
        #pragma unroll
        for (int mi = 0; mi < 2; mi++)
            #pragma unroll
            for (int half_ = 0; half_ < 2; half_++) {
                const int row = wm + mi * 16 + half_ * 8 + grp;
                #pragma unroll
                for (int ni = 0; ni < 8; ni++) {
                    *(float2*)(Tf + row * TF_LD + wn + ni * 8 + quad * 2) =
                        make_float2(acc[mi][ni][half_ * 2 + 0],
                                    acc[mi][ni][half_ * 2 + 1]);
                }
            }
        __syncthreads();

        const float gval = gamma[0];
        float* C = (float*)Cv;
        // 128 rows x 32 float4/row = 4096 float4; 16 per thread; warp = one row
        #pragma unroll
        for (int i = 0; i < 16; i++) {
            int idx = tid + 256 * i;
            int r = idx >> 5, c4 = (idx & 31) * 4;
            const float* rp = resid + (size_t)(rowBase + r) * ldc + colBase + c4;
            float4 rv = *(const float4*)rp;
            float4 av = *(const float4*)(Tf + r * TF_LD + c4);
            float4 ov;
            ov.x = fmaf(gval, av.x, rv.x);
            ov.y = fmaf(gval, av.y, rv.y);
            ov.z = fmaf(gval, av.z, rv.z);
            ov.w = fmaf(gval, av.w, rv.w);
            *(float4*)(C + (size_t)(rowBase + r) * ldc + colBase + c4) = ov;
        }
    }
}

// ---------------------------------------------------------------------------
// Flash attention (unchanged from R15): fused S = G@F^T, online softmax, O = P@Ht.
// ---------------------------------------------------------------------------
#define FRP 72
#define F_GS_OFF  0
#define F_P_OFF   (128 * FRP)
#define F_ST_OFF  (F_P_OFF + 128 * FRP)
#define F_STAGE_H ((64 + 256) * FRP)
#define F_HT_OFF  (64 * FRP)
#define F_FLT_OFF (F_ST_OFF + 3 * F_STAGE_H)
#define FLASH_SMEM (F_FLT_OFF * 2 + 256 * 4)

__global__ void __launch_bounds__(512) flash_attn(
    const __half* __restrict__ g, const __half* __restrict__ f,
    const __half* __restrict__ ht, __half* __restrict__ o)
{
    extern __shared__ __align__(16) __half smh[];
    const uint32_t sbase = smem_u32(smh);
    float* alpha_s = (float*)(smh + F_FLT_OFF);
    float* lrow_s  = alpha_s + 128;

    const int tid  = threadIdx.x;
    const int wid  = tid >> 5;
    const int lane = tid & 31;
    const int grp  = lane >> 2;
    const int quad = lane & 3;
    const int b    = blockIdx.y;
    const int mblk = blockIdx.x * 128;

    const __half* gq = g + ((size_t)b * NP + mblk) * CE;
    const __half* fb = f + (size_t)b * MP * CE;
    const __half* hb = ht + (size_t)b * CD * MP;

    #pragma unroll
    for (int i = 0; i < 2; i++) {
        int idx = tid + 512 * i;
        int r = idx >> 3, seg = idx & 7;
        cp_async16(sbase + (uint32_t)(F_GS_OFF + r * FRP + seg * 8) * 2u,
                   gq + (size_t)r * CE + seg * 8);
    }
    cp_commit();

    auto prefetch = [&](int c, int stage) {
        const uint32_t st = sbase + (uint32_t)(F_ST_OFF + stage * F_STAGE_H) * 2u;
        {
            int r = tid >> 3, seg = tid & 7;
            cp_async16(st + (uint32_t)(r * FRP + seg * 8) * 2u,
                       fb + (size_t)(c * 64 + r) * CE + seg * 8);
        }
        #pragma unroll
        for (int i = 0; i < 4; i++) {
            int idx = tid + 512 * i;
            int d = idx >> 3, seg = idx & 7;
            cp_async16(st + (uint32_t)(F_HT_OFF + d * FRP + seg * 8) * 2u,
                       hb + (size_t)d * MP + c * 64 + seg * 8);
        }
        cp_commit();
    };

    prefetch(0, 0);
    prefetch(1, 1);

    float accO[2][8][4] = {};
    float mstA = -1e30f, mstB = -1e30f, lstA = 0.0f, lstB = 0.0f;

    const int a15 = lane & 15;
    const int ahi = (lane >> 4) << 3;
    const int bn  = (lane & 7) + ((lane & 16) ? 8 : 0);
    const int bk  = lane & 8;
    const int pwm = (wid >> 2) * 32;
    const int pwn = (wid & 3) * 64;
    const int swm = wid * 16;

    int buf = 0;
    for (int c = 0; c < 16; c++) {
        if (c + 1 < 16) { cp_wait<1>(); } else { cp_wait<0>(); }
        __syncthreads();
        if (c + 2 < 16) {
            int nb = buf + 2; if (nb >= 3) nb -= 3;
            prefetch(c + 2, nb);
        }
        const uint32_t st = sbase + (uint32_t)(F_ST_OFF + buf * F_STAGE_H) * 2u;

        if (wid < 8) {
            float accS[8][4] = {};
            const uint32_t ga = sbase + (uint32_t)(F_GS_OFF + (swm + a15) * FRP + ahi) * 2u;
            const uint32_t fa = st + (uint32_t)(bn * FRP + bk) * 2u;
            #pragma unroll
            for (int ks = 0; ks < 4; ks++) {
                uint32_t af[4];
                ldm_x4(af, ga + ks * 32);
                #pragma unroll
                for (int nt = 0; nt < 4; nt++) {
                    uint32_t bf[4];
                    ldm_x4(bf, fa + ks * 32 + (uint32_t)(nt * 16 * FRP * 2));
                    mma_f16(accS[nt * 2 + 0], af, bf[0], bf[1]);
                    mma_f16(accS[nt * 2 + 1], af, bf[2], bf[3]);
                }
            }
            float mA = -1e30f, mB = -1e30f;
            #pragma unroll
            for (int t = 0; t < 8; t++) {
                mA = fmaxf(mA, fmaxf(accS[t][0], accS[t][1]));
                mB = fmaxf(mB, fmaxf(accS[t][2], accS[t][3]));
            }
            mA = fmaxf(mA, __shfl_xor_sync(0xffffffffu, mA, 1));
            mA = fmaxf(mA, __shfl_xor_sync(0xffffffffu, mA, 2));
            mB = fmaxf(mB, __shfl_xor_sync(0xffffffffu, mB, 1));
            mB = fmaxf(mB, __shfl_xor_sync(0xffffffffu, mB, 2));
            float mnA = fmaxf(mstA, mA), mnB = fmaxf(mstB, mB);
            float aA = __expf(mstA - mnA), aB = __expf(mstB - mnB);
            mstA = mnA; mstB = mnB;
            float sA = 0.0f, sB = 0.0f;
            #pragma unroll
            for (int t = 0; t < 8; t++) {
                float p0 = __expf(accS[t][0] - mnA);
                float p1 = __expf(accS[t][1] - mnA);
                float p2 = __expf(accS[t][2] - mnB);
                float p3 = __expf(accS[t][3] - mnB);
                sA += p0 + p1; sB += p2 + p3;
                *(__half2*)(smh + F_P_OFF + (swm + grp) * FRP + t * 8 + quad * 2)
                    = __floats2half2_rn(p0, p1);
                *(__half2*)(smh + F_P_OFF + (swm + 8 + grp) * FRP + t * 8 + quad * 2)
                    = __floats2half2_rn(p2, p3);
            }
            sA += __shfl_xor_sync(0xffffffffu, sA, 1);
            sA += __shfl_xor_sync(0xffffffffu, sA, 2);
            sB += __shfl_xor_sync(0xffffffffu, sB, 1);
            sB += __shfl_xor_sync(0xffffffffu, sB, 2);
            lstA = lstA * aA + sA;
            lstB = lstB * aB + sB;
            if (quad == 0) {
                alpha_s[swm + grp]     = aA;
                alpha_s[swm + 8 + grp] = aB;
            }
        }
        __syncthreads();

        {
            float a0 = alpha_s[pwm + grp],      a1 = alpha_s[pwm + 8 + grp];
            float a2 = alpha_s[pwm + 16 + grp], a3 = alpha_s[pwm + 24 + grp];
            #pragma unroll
            for (int nt = 0; nt < 8; nt++) {
                accO[0][nt][0] *= a0; accO[0][nt][1] *= a0;
                accO[0][nt][2] *= a1; accO[0][nt][3] *= a1;
                accO[1][nt][0] *= a2; accO[1][nt][1] *= a2;
                accO[1][nt][2] *= a3; accO[1][nt][3] *= a3;
            }
        }
        {
            const uint32_t pa = sbase + (uint32_t)(F_P_OFF + (pwm + a15) * FRP + ahi) * 2u;
            const uint32_t ha = st + (uint32_t)(F_HT_OFF + (pwn + bn) * FRP + bk) * 2u;
            #pragma unroll
            for (int ks = 0; ks < 4; ks++) {
                uint32_t af0[4], af1[4];
                ldm_x4(af0, pa + ks * 32);
                ldm_x4(af1, pa + ks * 32 + (uint32_t)(16 * FRP * 2));
                #pragma unroll
                for (int nt = 0; nt < 4; nt++) {
                    uint32_t bf[4];
                    ldm_x4(bf, ha + ks * 32 + (uint32_t)(nt * 16 * FRP * 2));
                    mma_f16(accO[0][nt * 2 + 0], af0, bf[0], bf[1]);
                    mma_f16(accO[1][nt * 2 + 0], af1, bf[0], bf[1]);
                    mma_f16(accO[0][nt * 2 + 1], af0, bf[2], bf[3]);
                    mma_f16(accO[1][nt * 2 + 1], af1, bf[2], bf[3]);
                }
            }
        }
        if (++buf == 3) buf = 0;
    }

    if (wid < 8 && quad == 0) {
        lrow_s[swm + grp]     = lstA;
        lrow_s[swm + 8 + grp] = lstB;
    }
    __syncthreads();

    __half* ob = o + ((size_t)b * NP + mblk) * CD;
    #pragma unroll
    for (int mi = 0; mi < 2; mi++) {
        #pragma unroll
        for (int hf = 0; hf < 2; hf++) {
            const int row = pwm + mi * 16 + hf * 8 + grp;
            const float inv = 1.0f / lrow_s[row];
            __half* cp = ob + (size_t)row * CD + pwn + quad * 2;
            #pragma unroll
            for (int nt = 0; nt < 8; nt++)
                *(__half2*)(cp + nt * 8) = __floats2half2_rn(
                    accO[mi][nt][hf * 2 + 0] * inv, accO[mi][nt][hf * 2 + 1] * inv);
        }
    }
}

// ---------------------------------------------------------------------------
// combined prep: x -> fp16 + fp16 weight transpose/concat
// ---------------------------------------------------------------------------
__global__ void prep_all(const float* __restrict__ x,
                         const float* __restrict__ Wf, const float* __restrict__ Wg,
                         const float* __restrict__ Wh, const float* __restrict__ Wo,
                         __half* __restrict__ xh,
                         __half* __restrict__ wcat, __half* __restrict__ wot)
{
    const int t = blockIdx.x * 256 + threadIdx.x;
    {
        size_t i = (size_t)t * 8;
        float4 v0 = *(const float4*)(x + i);
        float4 v1 = *(const float4*)(x + i + 4);
        __half2 h0 = __floats2half2_rn(v0.x, v0.y);
        __half2 h1 = __floats2half2_rn(v0.z, v0.w);
        __half2 h2 = __floats2half2_rn(v1.x, v1.y);
        __half2 h3 = __floats2half2_rn(v1.z, v1.w);
        uint4 u;
        u.x = *(uint32_t*)&h0; u.y = *(uint32_t*)&h1;
        u.z = *(uint32_t*)&h2; u.w = *(uint32_t*)&h3;
        *(uint4*)(xh + i) = u;
    }
    if (t < NCAT * CCH) {
        int n = t / CCH, k = t % CCH;
        float v;
        if (n < 64)       v = Wg[(size_t)k * 64 + n];
        else if (n < 128) v = Wf[(size_t)k * 64 + (n - 64)];
        else              v = Wh[(size_t)k * 256 + (n - 128)];
        wcat[t] = __float2half_rn(v);
    }
    if (t < CCH * CD) {
        int n = t / CD, k = t % CD;
        wot[t] = __float2half_rn(Wo[(size_t)k * CCH + n]);
    }
}

// ---------------------------------------------------------------------------
// launch
// ---------------------------------------------------------------------------
extern "C" void kernel_launch(void* const* d_in, const int* in_sizes, int n_in,
                              void* d_out, int out_size)
{
    const float* x     = (const float*)d_in[0];
    const float* Wf    = (const float*)d_in[1];
    const float* Wg    = (const float*)d_in[2];
    const float* Wh    = (const float*)d_in[3];
    const float* Wo    = (const float*)d_in[4];
    const float* gamma = (const float*)d_in[5];
    float* out = (float*)d_out;

    __half *xh_p, *wcat_p, *wot_p, *g_p, *f_p, *ht_p, *o_p;
    cudaGetSymbolAddress((void**)&xh_p,   xh_buf);
    cudaGetSymbolAddress((void**)&wcat_p, wcat_buf);
    cudaGetSymbolAddress((void**)&wot_p,  wot_buf);
    cudaGetSymbolAddress((void**)&g_p,    g_buf);
    cudaGetSymbolAddress((void**)&f_p,    f_buf);
    cudaGetSymbolAddress((void**)&ht_p,   ht_buf);
    cudaGetSymbolAddress((void**)&o_p,    o_buf);

    cudaFuncSetAttribute(mma_gemm_h<2>, cudaFuncAttributeMaxDynamicSharedMemorySize, GEMM_SMEM);
    cudaFuncSetAttribute(mma_gemm_h<3>, cudaFuncAttributeMaxDynamicSharedMemorySize, GEMM_SMEM);
    cudaFuncSetAttribute(flash_attn,    cudaFuncAttributeMaxDynamicSharedMemorySize, FLASH_SMEM);

    // x -> fp16 ; weights -> fp16
    prep_all<<<(BSZ * NP * CCH) / (256 * 8), 256>>>(x, Wf, Wg, Wh, Wo, xh_p, wcat_p, wot_p);

    // fused projections + pools: g, f, ht directly
    mma_gemm_h<3><<<dim3(3, 256, 1), 256, GEMM_SMEM>>>(
        xh_p, wcat_p, g_p, CCH, CCH, CCH, CE, 0, 0, 0, nullptr, nullptr, f_p, ht_p);

    // fused S + softmax + PV (S never touches DRAM)
    flash_attn<<<dim3(32, BSZ), 512, FLASH_SMEM>>>(g_p, f_p, ht_p, o_p);

    // out = gamma * (O @ Wo) + x   (M=32768, N=512, K=256)
    mma_gemm_h<2><<<dim3(4, 256, 1), 256, GEMM_SMEM>>>(
        o_p, wot_p, out, CD, CD, CD, CCH, 0, 0, 0, gamma, x, nullptr, nullptr);
}

// round 17
// speedup vs baseline: 3.2105x; 1.0370x over previous
#include <cuda_runtime.h>
#include <cuda_fp16.h>
#include <cstdint>

#define BSZ 8
#define NP  4096
#define MP  1024
#define CCH 512
#define CE  64
#define CD  256
#define NCAT 384

// ---------------- scratch ----------------
__device__ __half xh_buf  [(size_t)BSZ * NP * CCH];   // x as fp16 (also residual)
__device__ __half wcat_buf[NCAT * CCH];               // [n][k] = [Wg|Wf|Wh]^T
__device__ __half wot_buf [CCH * CD];                 // [n][k] = Wo^T
__device__ __half g_buf   [(size_t)BSZ * NP * CE];    // queries [B*4096][64]
__device__ __half f_buf   [BSZ * MP * CE];            // [b][key][e]
__device__ __half ht_buf  [BSZ * CD * MP];            // [b][d][key]
__device__ __half o_buf   [(size_t)BSZ * NP * CD];    // [b*4096][256]

// ---------------- helpers ----------------
__device__ __forceinline__ uint32_t smem_u32(const void* p) {
    uint32_t a;
    asm("{ .reg .u64 t; cvta.to.shared.u64 t, %1; cvt.u32.u64 %0, t; }" : "=r"(a) : "l"(p));
    return a;
}
__device__ __forceinline__ void cp_async16(uint32_t dst, const void* src) {
    asm volatile("cp.async.cg.shared.global [%0], [%1], 16;" :: "r"(dst), "l"(src));
}
__device__ __forceinline__ void cp_commit() {
    asm volatile("cp.async.commit_group;" ::: "memory");
}
template <int N>
__device__ __forceinline__ void cp_wait() {
    asm volatile("cp.async.wait_group %0;" :: "n"(N) : "memory");
}
__device__ __forceinline__ void ldm_x4(uint32_t r[4], uint32_t addr) {
    asm volatile("ldmatrix.sync.aligned.m8n8.x4.shared.b16 {%0,%1,%2,%3}, [%4];"
                 : "=r"(r[0]), "=r"(r[1]), "=r"(r[2]), "=r"(r[3]) : "r"(addr));
}
// fp16 mma, f32 accumulate
__device__ __forceinline__ void mma_f16(float c[4], const uint32_t a[4],
                                        uint32_t b0, uint32_t b1) {
    asm volatile(
        "mma.sync.aligned.m16n8k16.row.col.f32.f16.f16.f32 "
        "{%0,%1,%2,%3}, {%4,%5,%6,%7}, {%8,%9}, {%0,%1,%2,%3};"
        : "+f"(c[0]), "+f"(c[1]), "+f"(c[2]), "+f"(c[3])
        : "r"(a[0]), "r"(a[1]), "r"(a[2]), "r"(a[3]), "r"(b0), "r"(b1));
}

// ---------------------------------------------------------------------------
// 3-stage pipelined NT fp16 GEMM — used ONLY for the fused projection+pools
// (COUT=3 epilogue). Unchanged from R16.
// ---------------------------------------------------------------------------
#define RPAD    72
#define STAGE_H (2 * 128 * RPAD)
#define STAGE_B (STAGE_H * 2)
#define GEMM_SMEM (3 * STAGE_B)
#define TS_LD 136

template <int COUT>
__global__ void __launch_bounds__(256, 2) mma_gemm_h(
    const __half* __restrict__ A, const __half* __restrict__ B, void* __restrict__ Cv,
    int K, int lda, int ldb, int ldc,
    __half* __restrict__ f_out, __half* __restrict__ ht_out)
{
    extern __shared__ __align__(16) __half smh[];
    const uint32_t sbase = smem_u32(smh);

    const int tid  = threadIdx.x;
    const int wid  = tid >> 5;
    const int lane = tid & 31;
    const int grp  = lane >> 2;
    const int quad = lane & 3;
    const int rowBase = blockIdx.y * 128;
    const int wm = (wid >> 1) * 32;
    const int wn = (wid & 1) * 64;
    const int colBase = blockIdx.x * 128;

    const int KB = K >> 6;

    auto prefetch = [&](int kb, int stage) {
        const uint32_t abase = sbase + (uint32_t)stage * STAGE_B;
        const uint32_t bbase = abase + 128 * RPAD * 2;
        const __half* Ag = A + (size_t)rowBase * lda + kb * 64;
        const __half* Bg = B + (size_t)colBase * ldb + kb * 64;
        #pragma unroll
        for (int i = 0; i < 4; i++) {
            int idx = tid + 256 * i;
            int r = idx >> 3, seg = idx & 7;
            cp_async16(abase + (uint32_t)(r * 144 + seg * 16), Ag + (size_t)r * lda + seg * 8);
        }
        #pragma unroll
        for (int i = 0; i < 4; i++) {
            int idx = tid + 256 * i;
            int r = idx >> 3, seg = idx & 7;
            cp_async16(bbase + (uint32_t)(r * 144 + seg * 16), Bg + (size_t)r * ldb + seg * 8);
        }
        cp_commit();
    };

    float acc[2][8][4] = {};

    prefetch(0, 0);
    if (KB > 1) prefetch(1, 1);

    const uint32_t a_base = (uint32_t)((wm + (lane & 15)) * RPAD + ((lane >> 4) << 3)) * 2u;
    const uint32_t b_base = (uint32_t)(128 * RPAD +
                            (wn + (lane & 7) + ((lane & 16) ? 8 : 0)) * RPAD + (lane & 8)) * 2u;

    int buf = 0;
    for (int kb = 0; kb < KB; kb++) {
        if (kb + 1 < KB) { cp_wait<1>(); } else { cp_wait<0>(); }
        __syncthreads();
        if (kb + 2 < KB) {
            int nb = buf + 2; if (nb >= 3) nb -= 3;
            prefetch(kb + 2, nb);
        }

        const uint32_t stage0 = sbase + (uint32_t)buf * STAGE_B;

        #pragma unroll
        for (int step = 0; step < 4; step++) {
            const uint32_t kko = (uint32_t)(step * 32);
            uint32_t af[2][4];
            ldm_x4(af[0], stage0 + a_base + kko);
            ldm_x4(af[1], stage0 + a_base + kko + (uint32_t)(16 * RPAD * 2));
            #pragma unroll
            for (int pr = 0; pr < 4; pr++) {
                uint32_t bf[4];
                ldm_x4(bf, stage0 + b_base + kko + (uint32_t)(pr * 16 * RPAD * 2));
                mma_f16(acc[0][pr * 2 + 0], af[0], bf[0], bf[1]);
                mma_f16(acc[1][pr * 2 + 0], af[1], bf[0], bf[1]);
                mma_f16(acc[0][pr * 2 + 1], af[0], bf[2], bf[3]);
                mma_f16(acc[1][pr * 2 + 1], af[1], bf[2], bf[3]);
            }
        }
        if (++buf == 3) buf = 0;
    }

    // projection epilogue: stage tile, write g / pooled f / pooled+transposed ht
    __syncthreads();
    __half* Ts = smh;  // [128][TS_LD]
    #pragma unroll
    for (int mi = 0; mi < 2; mi++)
        #pragma unroll
        for (int half_ = 0; half_ < 2; half_++) {
            const int row = wm + mi * 16 + half_ * 8 + grp;
            #pragma unroll
            for (int ni = 0; ni < 8; ni++) {
                __half2 hv = __floats2half2_rn(acc[mi][ni][half_ * 2 + 0],
                                               acc[mi][ni][half_ * 2 + 1]);
                *(__half2*)(Ts + row * TS_LD + wn + ni * 8 + quad * 2) = hv;
            }
        }
    __syncthreads();

    const int b = blockIdx.y >> 5;
    const int p = blockIdx.y & 31;
    const int nx = blockIdx.x;

    if (nx == 0) {
        {
            int lr = tid >> 1, c0 = (tid & 1) * 32;
            const uint4* src = (const uint4*)(Ts + lr * TS_LD + c0);
            uint4* dst = (uint4*)((__half*)Cv + (size_t)(rowBase + lr) * CE + c0);
            #pragma unroll
            for (int i = 0; i < 4; i++) dst[i] = src[i];
        }
        {
            int q = tid >> 3, eg = tid & 7;
            const __half* r0 = Ts + (2 * q) * TS_LD + 64 + eg * 8;
            const __half* r1 = r0 + TS_LD;
            const __half* r2 = Ts + (64 + 2 * q) * TS_LD + 64 + eg * 8;
            const __half* r3 = r2 + TS_LD;
            __half2 o[4];
            #pragma unroll
            for (int i = 0; i < 4; i++) {
                __half2 v0 = *(const __half2*)(r0 + i * 2);
                __half2 v1 = *(const __half2*)(r1 + i * 2);
                __half2 v2 = *(const __half2*)(r2 + i * 2);
                __half2 v3 = *(const __half2*)(r3 + i * 2);
                o[i] = __hmax2(__hmax2(v0, v1), __hmax2(v2, v3));
            }
            __half* dst = f_out + ((size_t)b * MP + p * 32 + q) * CE + eg * 8;
            *(uint2*)dst       = *(uint2*)&o[0];
            *(uint2*)(dst + 4) = *(uint2*)&o[2];
        }
    } else {
        const int dg = (nx - 1) * 128;
        const int d  = tid >> 1;
        const int q0 = (tid & 1) * 16;
        __half vals[16];
        #pragma unroll
        for (int i = 0; i < 16; i++) {
            int q = q0 + i;
            __half v0 = Ts[(2 * q) * TS_LD + d];
            __half v1 = Ts[(2 * q + 1) * TS_LD + d];
            __half v2 = Ts[(64 + 2 * q) * TS_LD + d];
            __half v3 = Ts[(65 + 2 * q) * TS_LD + d];
            vals[i] = __hmax(__hmax(v0, v1), __hmax(v2, v3));
        }
        __half* dst = ht_out + ((size_t)b * CD + dg + d) * MP + p * 32 + q0;
        *(uint4*)dst       = *(uint4*)&vals[0];
        *(uint4*)(dst + 8) = *(uint4*)&vals[8];
    }
}

// ---------------------------------------------------------------------------
// out_gemm: out[32768,512] = gamma * (O[32768,256] @ Wo^T[512,256]^T) + xh
// CTA tile 128x64, 8 warps (4m x 2n, warp tile 32x32), 2-stage cp.async,
// 3 CTAs/SM (regs<=85, smem 55.3 KB). fp16 residual (xh), fp32 out.
// ---------------------------------------------------------------------------
#define ORP 72
#define O_STAGE_H ((128 + 64) * ORP)     // 13824 halves
#define O_STAGE_B (O_STAGE_H * 2)        // 27648 bytes
#define OG_SMEM (2 * O_STAGE_B)          // 55296 bytes
#define OTF_LD 68

__global__ void __launch_bounds__(256, 3) out_gemm(
    const __half* __restrict__ A, const __half* __restrict__ B,
    float* __restrict__ C, const __half* __restrict__ residh,
    const float* __restrict__ gamma)
{
    extern __shared__ __align__(16) __half smh[];
    const uint32_t sbase = smem_u32(smh);

    const int tid  = threadIdx.x;
    const int wid  = tid >> 5;
    const int lane = tid & 31;
    const int grp  = lane >> 2;
    const int quad = lane & 3;
    const int rowBase = blockIdx.y * 128;
    const int colBase = blockIdx.x * 64;
    const int wm = (wid >> 1) * 32;      // 0,32,64,96
    const int wn = (wid & 1) * 32;       // 0,32

    const int KB = 4;                    // K=256, chunk 64

    auto prefetch = [&](int kb, int stage) {
        const uint32_t abase = sbase + (uint32_t)stage * O_STAGE_B;
        const uint32_t bbase = abase + 128 * ORP * 2;
        const __half* Ag = A + (size_t)rowBase * CD + kb * 64;
        const __half* Bg = B + (size_t)colBase * CD + kb * 64;
        #pragma unroll
        for (int i = 0; i < 4; i++) {
            int idx = tid + 256 * i;
            int r = idx >> 3, seg = idx & 7;
            cp_async16(abase + (uint32_t)(r * 144 + seg * 16), Ag + (size_t)r * CD + seg * 8);
        }
        #pragma unroll
        for (int i = 0; i < 2; i++) {
            int idx = tid + 256 * i;
            int r = idx >> 3, seg = idx & 7;
            cp_async16(bbase + (uint32_t)(r * 144 + seg * 16), Bg + (size_t)r * CD + seg * 8);
        }
        cp_commit();
    };

    float acc[2][4][4] = {};

    prefetch(0, 0);
    prefetch(1, 1);

    const uint32_t a_base = (uint32_t)((wm + (lane & 15)) * ORP + ((lane >> 4) << 3)) * 2u;
    const uint32_t b_base = (uint32_t)(128 * ORP +
                            (wn + (lane & 7) + ((lane & 16) ? 8 : 0)) * ORP + (lane & 8)) * 2u;

    for (int kb = 0; kb < KB; kb++) {
        if (kb + 1 < KB) { cp_wait<1>(); } else { cp_wait<0>(); }
        __syncthreads();

        const uint32_t stage0 = sbase + (uint32_t)(kb & 1) * O_STAGE_B;

        #pragma unroll
        for (int step = 0; step < 4; step++) {
            const uint32_t kko = (uint32_t)(step * 32);
            uint32_t af[2][4];
            ldm_x4(af[0], stage0 + a_base + kko);
            ldm_x4(af[1], stage0 + a_base + kko + (uint32_t)(16 * ORP * 2));
            #pragma unroll
            for (int nt = 0; nt < 2; nt++) {
                uint32_t bf[4];
                ldm_x4(bf, stage0 + b_base + kko + (uint32_t)(nt * 16 * ORP * 2));
                mma_f16(acc[0][nt * 2 + 0], af[0], bf[0], bf[1]);
                mma_f16(acc[1][nt * 2 + 0], af[1], bf[0], bf[1]);
                mma_f16(acc[0][nt * 2 + 1], af[0], bf[2], bf[3]);
                mma_f16(acc[1][nt * 2 + 1], af[1], bf[2], bf[3]);
            }
        }
        __syncthreads();                 // all warps done with this stage
        if (kb + 2 < KB) prefetch(kb + 2, kb & 1);
    }

    // ---- epilogue: stage acc to smem fp32, then coalesced float4 pass ----
    float* Tf = (float*)smh;             // [128][OTF_LD]
    #pragma unroll
    for (int mi = 0; mi < 2; mi++)
        #pragma unroll
        for (int hf = 0; hf < 2; hf++) {
            const int row = wm + mi * 16 + hf * 8 + grp;
            #pragma unroll
            for (int ni = 0; ni < 4; ni++)
                *(float2*)(Tf + row * OTF_LD + wn + ni * 8 + quad * 2) =
                    make_float2(acc[mi][ni][hf * 2 + 0], acc[mi][ni][hf * 2 + 1]);
        }
    __syncthreads();

    const float gval = gamma[0];
    // 128 rows x 16 float4/row = 2048 slots, 8 per thread
    #pragma unroll
    for (int i = 0; i < 8; i++) {
        int idx = tid + 256 * i;
        int r = idx >> 4, c4 = (idx & 15) * 4;
        const __half* rp = residh + (size_t)(rowBase + r) * CCH + colBase + c4;
        uint2 ru = *(const uint2*)rp;
        float2 r01 = __half22float2(*(__half2*)&ru.x);
        float2 r23 = __half22float2(*(__half2*)&ru.y);
        float4 av = *(const float4*)(Tf + r * OTF_LD + c4);
        float4 ov;
        ov.x = fmaf(gval, av.x, r01.x);
        ov.y = fmaf(gval, av.y, r01.y);
        ov.z = fmaf(gval, av.z, r23.x);
        ov.w = fmaf(gval, av.w, r23.y);
        *(float4*)(C + (size_t)(rowBase + r) * CCH + colBase + c4) = ov;
    }
}

// ---------------------------------------------------------------------------
// Flash attention (unchanged from R15/16)
// ---------------------------------------------------------------------------
#define FRP 72
#define F_GS_OFF  0
#define F_P_OFF   (128 * FRP)
#define F_ST_OFF  (F_P_OFF + 128 * FRP)
#define F_STAGE_H ((64 + 256) * FRP)
#define F_HT_OFF  (64 * FRP)
#define F_FLT_OFF (F_ST_OFF + 3 * F_STAGE_H)
#define FLASH_SMEM (F_FLT_OFF * 2 + 256 * 4)

__global__ void __launch_bounds__(512) flash_attn(
    const __half* __restrict__ g, const __half* __restrict__ f,
    const __half* __restrict__ ht, __half* __restrict__ o)
{
    extern __shared__ __align__(16) __half smh[];
    const uint32_t sbase = smem_u32(smh);
    float* alpha_s = (float*)(smh + F_FLT_OFF);
    float* lrow_s  = alpha_s + 128;

    const int tid  = threadIdx.x;
    const int wid  = tid >> 5;
    const int lane = tid & 31;
    const int grp  = lane >> 2;
    const int quad = lane & 3;
    const int b    = blockIdx.y;
    const int mblk = blockIdx.x * 128;

    const __half* gq = g + ((size_t)b * NP + mblk) * CE;
    const __half* fb = f + (size_t)b * MP * CE;
    const __half* hb = ht + (size_t)b * CD * MP;

    #pragma unroll
    for (int i = 0; i < 2; i++) {
        int idx = tid + 512 * i;
        int r = idx >> 3, seg = idx & 7;
        cp_async16(sbase + (uint32_t)(F_GS_OFF + r * FRP + seg * 8) * 2u,
                   gq + (size_t)r * CE + seg * 8);
    }
    cp_commit();

    auto prefetch = [&](int c, int stage) {
        const uint32_t st = sbase + (uint32_t)(F_ST_OFF + stage * F_STAGE_H) * 2u;
        {
            int r = tid >> 3, seg = tid & 7;
            cp_async16(st + (uint32_t)(r * FRP + seg * 8) * 2u,
                       fb + (size_t)(c * 64 + r) * CE + seg * 8);
        }
        #pragma unroll
        for (int i = 0; i < 4; i++) {
            int idx = tid + 512 * i;
            int d = idx >> 3, seg = idx & 7;
            cp_async16(st + (uint32_t)(F_HT_OFF + d * FRP + seg * 8) * 2u,
                       hb + (size_t)d * MP + c * 64 + seg * 8);
        }
        cp_commit();
    };

    prefetch(0, 0);
    prefetch(1, 1);

    float accO[2][8][4] = {};
    float mstA = -1e30f, mstB = -1e30f, lstA = 0.0f, lstB = 0.0f;

    const int a15 = lane & 15;
    const int ahi = (lane >> 4) << 3;
    const int bn  = (lane & 7) + ((lane & 16) ? 8 : 0);
    const int bk  = lane & 8;
    const int pwm = (wid >> 2) * 32;
    const int pwn = (wid & 3) * 64;
    const int swm = wid * 16;

    int buf = 0;
    for (int c = 0; c < 16; c++) {
        if (c + 1 < 16) { cp_wait<1>(); } else { cp_wait<0>(); }
        __syncthreads();
        if (c + 2 < 16) {
            int nb = buf + 2; if (nb >= 3) nb -= 3;
            prefetch(c + 2, nb);
        }
        const uint32_t st = sbase + (uint32_t)(F_ST_OFF + buf * F_STAGE_H) * 2u;

        if (wid < 8) {
            float accS[8][4] = {};
            const uint32_t ga = sbase + (uint32_t)(F_GS_OFF + (swm + a15) * FRP + ahi) * 2u;
            const uint32_t fa = st + (uint32_t)(bn * FRP + bk) * 2u;
            #pragma unroll
            for (int ks = 0; ks < 4; ks++) {
                uint32_t af[4];
                ldm_x4(af, ga + ks * 32);
                #pragma unroll
                for (int nt = 0; nt < 4; nt++) {
                    uint32_t bf[4];
                    ldm_x4(bf, fa + ks * 32 + (uint32_t)(nt * 16 * FRP * 2));
                    mma_f16(accS[nt * 2 + 0], af, bf[0], bf[1]);
                    mma_f16(accS[nt * 2 + 1], af, bf[2], bf[3]);
                }
            }
            float mA = -1e30f, mB = -1e30f;
            #pragma unroll
            for (int t = 0; t < 8; t++) {
                mA = fmaxf(mA, fmaxf(accS[t][0], accS[t][1]));
                mB = fmaxf(mB, fmaxf(accS[t][2], accS[t][3]));
            }
            mA = fmaxf(mA, __shfl_xor_sync(0xffffffffu, mA, 1));
            mA = fmaxf(mA, __shfl_xor_sync(0xffffffffu, mA, 2));
            mB = fmaxf(mB, __shfl_xor_sync(0xffffffffu, mB, 1));
            mB = fmaxf(mB, __shfl_xor_sync(0xffffffffu, mB, 2));
            float mnA = fmaxf(mstA, mA), mnB = fmaxf(mstB, mB);
            float aA = __expf(mstA - mnA), aB = __expf(mstB - mnB);
            mstA = mnA; mstB = mnB;
            float sA = 0.0f, sB = 0.0f;
            #pragma unroll
            for (int t = 0; t < 8; t++) {
                float p0 = __expf(accS[t][0] - mnA);
                float p1 = __expf(accS[t][1] - mnA);
                float p2 = __expf(accS[t][2] - mnB);
                float p3 = __expf(accS[t][3] - mnB);
                sA += p0 + p1; sB += p2 + p3;
                *(__half2*)(smh + F_P_OFF + (swm + grp) * FRP + t * 8 + quad * 2)
                    = __floats2half2_rn(p0, p1);
                *(__half2*)(smh + F_P_OFF + (swm + 8 + grp) * FRP + t * 8 + quad * 2)
                    = __floats2half2_rn(p2, p3);
            }
            sA += __shfl_xor_sync(0xffffffffu, sA, 1);
            sA += __shfl_xor_sync(0xffffffffu, sA, 2);
            sB += __shfl_xor_sync(0xffffffffu, sB, 1);
            sB += __shfl_xor_sync(0xffffffffu, sB, 2);
            lstA = lstA * aA + sA;
            lstB = lstB * aB + sB;
            if (quad == 0) {
                alpha_s[swm + grp]     = aA;
                alpha_s[swm + 8 + grp] = aB;
            }
        }
        __syncthreads();

        {
            float a0 = alpha_s[pwm + grp],      a1 = alpha_s[pwm + 8 + grp];
            float a2 = alpha_s[pwm + 16 + grp], a3 = alpha_s[pwm + 24 + grp];
            #pragma unroll
            for (int nt = 0; nt < 8; nt++) {
                accO[0][nt][0] *= a0; accO[0][nt][1] *= a0;
                accO[0][nt][2] *= a1; accO[0][nt][3] *= a1;
                accO[1][nt][0] *= a2; accO[1][nt][1] *= a2;
                accO[1][nt][2] *= a3; accO[1][nt][3] *= a3;
            }
        }
        {
            const uint32_t pa = sbase + (uint32_t)(F_P_OFF + (pwm + a15) * FRP + ahi) * 2u;
            const uint32_t ha = st + (uint32_t)(F_HT_OFF + (pwn + bn) * FRP + bk) * 2u;
            #pragma unroll
            for (int ks = 0; ks < 4; ks++) {
                uint32_t af0[4], af1[4];
                ldm_x4(af0, pa + ks * 32);
                ldm_x4(af1, pa + ks * 32 + (uint32_t)(16 * FRP * 2));
                #pragma unroll
                for (int nt = 0; nt < 4; nt++) {
                    uint32_t bf[4];
                    ldm_x4(bf, ha + ks * 32 + (uint32_t)(nt * 16 * FRP * 2));
                    mma_f16(accO[0][nt * 2 + 0], af0, bf[0], bf[1]);
                    mma_f16(accO[1][nt * 2 + 0], af1, bf[0], bf[1]);
                    mma_f16(accO[0][nt * 2 + 1], af0, bf[2], bf[3]);
                    mma_f16(accO[1][nt * 2 + 1], af1, bf[2], bf[3]);
                }
            }
        }
        if (++buf == 3) buf = 0;
    }

    if (wid < 8 && quad == 0) {
        lrow_s[swm + grp]     = lstA;
        lrow_s[swm + 8 + grp] = lstB;
    }
    __syncthreads();

    __half* ob = o + ((size_t)b * NP + mblk) * CD;
    #pragma unroll
    for (int mi = 0; mi < 2; mi++) {
        #pragma unroll
        for (int hf = 0; hf < 2; hf++) {
            const int row = pwm + mi * 16 + hf * 8 + grp;
            const float inv = 1.0f / lrow_s[row];
            __half* cp = ob + (size_t)row * CD + pwn + quad * 2;
            #pragma unroll
            for (int nt = 0; nt < 8; nt++)
                *(__half2*)(cp + nt * 8) = __floats2half2_rn(
                    accO[mi][nt][hf * 2 + 0] * inv, accO[mi][nt][hf * 2 + 1] * inv);
        }
    }
}

// ---------------------------------------------------------------------------
// combined prep: x -> fp16 + fp16 weight transpose/concat
// ---------------------------------------------------------------------------
__global__ void prep_all(const float* __restrict__ x,
                         const float* __restrict__ Wf, const float* __restrict__ Wg,
                         const float* __restrict__ Wh, const float* __restrict__ Wo,
                         __half* __restrict__ xh,
                         __half* __restrict__ wcat, __half* __restrict__ wot)
{
    const int t = blockIdx.x * 256 + threadIdx.x;
    {
        size_t i = (size_t)t * 8;
        float4 v0 = *(const float4*)(x + i);
        float4 v1 = *(const float4*)(x + i + 4);
        __half2 h0 = __floats2half2_rn(v0.x, v0.y);
        __half2 h1 = __floats2half2_rn(v0.z, v0.w);
        __half2 h2 = __floats2half2_rn(v1.x, v1.y);
        __half2 h3 = __floats2half2_rn(v1.z, v1.w);
        uint4 u;
        u.x = *(uint32_t*)&h0; u.y = *(uint32_t*)&h1;
        u.z = *(uint32_t*)&h2; u.w = *(uint32_t*)&h3;
        *(uint4*)(xh + i) = u;
    }
    if (t < NCAT * CCH) {
        int n = t / CCH, k = t % CCH;
        float v;
        if (n < 64)       v = Wg[(size_t)k * 64 + n];
        else if (n < 128) v = Wf[(size_t)k * 64 + (n - 64)];
        else              v = Wh[(size_t)k * 256 + (n - 128)];
        wcat[t] = __float2half_rn(v);
    }
    if (t < CCH * CD) {
        int n = t / CD, k = t % CD;
        wot[t] = __float2half_rn(Wo[(size_t)k * CCH + n]);
    }
}

// ---------------------------------------------------------------------------
// launch
// ---------------------------------------------------------------------------
extern "C" void kernel_launch(void* const* d_in, const int* in_sizes, int n_in,
                              void* d_out, int out_size)
{
    const float* x     = (const float*)d_in[0];
    const float* Wf    = (const float*)d_in[1];
    const float* Wg    = (const float*)d_in[2];
    const float* Wh    = (const float*)d_in[3];
    const float* Wo    = (const float*)d_in[4];
    const float* gamma = (const float*)d_in[5];
    float* out = (float*)d_out;

    __half *xh_p, *wcat_p, *wot_p, *g_p, *f_p, *ht_p, *o_p;
    cudaGetSymbolAddress((void**)&xh_p,   xh_buf);
    cudaGetSymbolAddress((void**)&wcat_p, wcat_buf);
    cudaGetSymbolAddress((void**)&wot_p,  wot_buf);
    cudaGetSymbolAddress((void**)&g_p,    g_buf);
    cudaGetSymbolAddress((void**)&f_p,    f_buf);
    cudaGetSymbolAddress((void**)&ht_p,   ht_buf);
    cudaGetSymbolAddress((void**)&o_p,    o_buf);

    cudaFuncSetAttribute(mma_gemm_h<3>, cudaFuncAttributeMaxDynamicSharedMemorySize, GEMM_SMEM);
    cudaFuncSetAttribute(out_gemm,      cudaFuncAttributeMaxDynamicSharedMemorySize, OG_SMEM);
    cudaFuncSetAttribute(flash_attn,    cudaFuncAttributeMaxDynamicSharedMemorySize, FLASH_SMEM);

    // x -> fp16 ; weights -> fp16
    prep_all<<<(BSZ * NP * CCH) / (256 * 8), 256>>>(x, Wf, Wg, Wh, Wo, xh_p, wcat_p, wot_p);

    // fused projections + pools: g, f, ht directly
    mma_gemm_h<3><<<dim3(3, 256, 1), 256, GEMM_SMEM>>>(
        xh_p, wcat_p, g_p, CCH, CCH, CCH, CE, f_p, ht_p);

    // fused S + softmax + PV (S never touches DRAM)
    flash_attn<<<dim3(32, BSZ), 512, FLASH_SMEM>>>(g_p, f_p, ht_p, o_p);

    // out = gamma * (O @ Wo) + x  (residual via fp16 xh; 3 CTAs/SM)
    out_gemm<<<dim3(8, 256, 1), 256, OG_SMEM>>>(o_p, wot_p, out, xh_p, gamma);
}